// round 10
// baseline (speedup 1.0000x reference)
#include <cuda_runtime.h>
#include <cuda_bf16.h>
#include <cstdint>
#include <cstddef>

#define BATCH 4
#define DIM   128
#define DIN   256
#define HH    64
#define WW    64
#define HW    4096
#define LSEQ  4096
#define DSTATE 16
#define DTRANK 8
#define EPSV  1e-5f
#define SLOPE 0.01f

#define NCH   4
#define CHLEN (LSEQ/NCH)
#define NPAIR (BATCH*DIN)

typedef unsigned long long ull;

__device__ __forceinline__ ull pack2(float lo, float hi) {
    ull r; asm("mov.b64 %0, {%1, %2};" : "=l"(r) : "f"(lo), "f"(hi)); return r;
}
__device__ __forceinline__ void unpack2(ull p, float& lo, float& hi) {
    asm("mov.b64 {%0, %1}, %2;" : "=f"(lo), "=f"(hi) : "l"(p));
}
__device__ __forceinline__ ull ffma2(ull a, ull b, ull c) {
    ull d; asm("fma.rn.f32x2 %0, %1, %2, %3;" : "=l"(d) : "l"(a), "l"(b), "l"(c)); return d;
}
__device__ __forceinline__ float softplus_f(float x) {
    return (x > 20.f) ? x : log1pf(expf(x));
}
__device__ __forceinline__ uint32_t saddr(const void* p) {
    return (uint32_t)__cvta_generic_to_shared(p);
}
__device__ __forceinline__ void cpa4(uint32_t dst, const void* src) {
    asm volatile("cp.async.ca.shared.global [%0], [%1], 4;" :: "r"(dst), "l"(src));
}
__device__ __forceinline__ void cpa16(uint32_t dst, const void* src) {
    asm volatile("cp.async.cg.shared.global [%0], [%1], 16;" :: "r"(dst), "l"(src));
}

#define W1ELEMS (DIM * 9 * DIN)
#define W2ELEMS (DIN * 9 * DIM)

// ---------------- scratch ----------------
struct Scratch {
    float h1[2 * BATCH * DIN * HW];
    float h2[4 * BATCH * DIM * HW];
    float t [BATCH * LSEQ * DIM];
    float xrx[BATCH * LSEQ * DIN];
    float resT[NPAIR * LSEQ];
    float xs[BATCH * LSEQ * DIN];
    float xsT[NPAIR * LSEQ];
    float deltaT[NPAIR * LSEQ];
    float gatedT[NPAIR * LSEQ];
    float bc[BATCH * LSEQ * 2*DSTATE];
    float weff[DIN * DIN];
    float negA[DIN * DSTATE];
    float4 wpack[DIN];
    ull  wd1[W1ELEMS];
    ull  wd2[W2ELEMS];
    float chA[(NCH-1) * NPAIR * DSTATE];
    float chH[(NCH-1) * NPAIR * DSTATE];
    float hst[NCH * NPAIR * DSTATE];
};
__device__ Scratch g_scratch;

// ---------------- precompute kernels (3 launches; conv1 stays at slot 3) ---------
__global__ void negA_wpack_kernel(const float* __restrict__ A_log, float* __restrict__ negA,
                                  const float* __restrict__ w1d, float4* __restrict__ wp)
{
    if (blockIdx.x < 16) {
        int i = blockIdx.x * 256 + threadIdx.x;
        negA[i] = -expf(A_log[i]);
    } else {
        int d = threadIdx.x;
        wp[d] = make_float4(w1d[4*d], w1d[4*d+1], w1d[4*d+2], w1d[4*d+3]);
    }
}
__global__ __launch_bounds__(256)
void weff_kernel(const float* __restrict__ xw, const float* __restrict__ dtw,
                 float* __restrict__ weff)
{
    int k = blockIdx.x, d = threadIdx.x;
    float acc = 0.f;
#pragma unroll
    for (int r = 0; r < DTRANK; r++)
        acc = fmaf(xw[k * 40 + r], dtw[r * DIN + d], acc);
    weff[k * DIN + d] = acc;
}
__global__ __launch_bounds__(256)
void wdup_kernel(const float* __restrict__ w1, const float* __restrict__ w2,
                 ull* __restrict__ wd1, ull* __restrict__ wd2)
{
    int i = blockIdx.x * 256 + threadIdx.x;
    if (i < W1ELEMS) {
        int oc = i % DIN; int rest = i / DIN;
        int tap = rest % 9; int ci = rest / 9;
        float w = w1[((size_t)oc * DIM + ci) * 9 + tap];
        wd1[i] = pack2(w, w);
    } else if (i < W1ELEMS + W2ELEMS) {
        int j = i - W1ELEMS;
        int oc = j % DIM; int rest = j / DIM;
        int tap = rest % 9; int ci = rest / 9;
        float w = w2[((size_t)oc * DIN + ci) * 9 + tap];
        wd2[j] = pack2(w, w);
    }
}

// ---------------- conv v9: v8 pipeline, OCPB=4, 3 CTAs/SM -------------------------
// 32x64 tile, 8 px/thread (float4 row-quads), 4 oc/block, CIC=2, split-K.
// acc = 16 ull (32 regs) -> fits 85-reg budget for 3 CTAs/SM (24 warps).
template<int CIN, int COUT, int SPLIT>
__global__ __launch_bounds__(256, 3)
void conv3x3_v9_kernel(const float* __restrict__ x, const ull* __restrict__ wd,
                       float* __restrict__ out)
{
    constexpr int OCPB = 4, CIC = 2, CSPAN = CIN / SPLIT;
    constexpr int NCHUNK = CSPAN / CIC;
    __shared__ float4 sx4[2][CIC * 18 * 36];       // 41472 B
    __shared__ ulonglong2 swt[2][CIC * 9 * 2];     //  1152 B

    const int tid = threadIdx.x;
    const int tx = tid & 31, ty = tid >> 5;        // ty 0..7
    const int bx0 = blockIdx.x * 32;
    const int bz = blockIdx.z;
    constexpr int OCB = COUT / OCPB;
    const int b    = bz / (OCB * SPLIT);
    const int r    = bz % (OCB * SPLIT);
    const int oc0  = (r / SPLIT) * OCPB;
    const int part = r % SPLIT;
    const int cbase = part * CSPAN;
    const float* xb = x + (size_t)b * CIN * HW;
    float* out_part = out + (size_t)part * BATCH * COUT * HW;

    for (int i = tid; i < 2 * CIC * 18 * 36; i += 256)
        ((float4*)sx4)[i] = make_float4(0.f, 0.f, 0.f, 0.f);
    __syncthreads();

    auto load_chunk = [&](int buf, int c0) {
        for (int rr = ty; rr < CIC * 18; rr += 8) {
            int ci = (rr >= 18) ? 1 : 0;
            int p  = rr - 18 * ci;
            int gr = p - 1;
#pragma unroll
            for (int s = 0; s < 2; s++) {
                int xx = tx + 32 * s;
                if (xx < 34) {
                    int gx = bx0 + xx - 1;
                    if ((unsigned)gx < (unsigned)WW) {
                        const float* pc = xb + (size_t)(cbase + c0 + ci) * HW + gx;
                        uint32_t dst = saddr(&sx4[buf][rr * 36 + xx]);
                        if (p > 0)  cpa4(dst + 0,  pc + (size_t)gr * WW);
                        cpa4(dst + 4,  pc + (size_t)(gr + 16) * WW);
                        cpa4(dst + 8,  pc + (size_t)(gr + 32) * WW);
                        if (p < 17) cpa4(dst + 12, pc + (size_t)(gr + 48) * WW);
                    }
                }
            }
        }
        if (tid < CIC * 9 * 2) {
            int q = tid & 1;
            int rowi = tid >> 1;                   // 0..17 = ci*9+tap
            int ci = (rowi >= 9) ? 1 : 0;
            int tap = rowi - 9 * ci;
            const ull* src = wd + ((size_t)(cbase + c0 + ci) * 9 + tap) * COUT + oc0 + 2 * q;
            cpa16(saddr(&swt[buf][rowi * 2 + q]), src);
        }
    };

    ull acc[OCPB][4];
#pragma unroll
    for (int i = 0; i < OCPB; i++)
#pragma unroll
        for (int q = 0; q < 4; q++) acc[i][q] = 0ull;

    load_chunk(0, 0);
    asm volatile("cp.async.commit_group;");

    for (int ch = 0; ch < NCHUNK; ch++) {
        const int cur = ch & 1;
        if (ch + 1 < NCHUNK) {
            load_chunk(cur ^ 1, (ch + 1) * CIC);
            asm volatile("cp.async.commit_group;");
            asm volatile("cp.async.wait_group 1;");
        } else {
            asm volatile("cp.async.wait_group 0;");
        }
        __syncthreads();

        const float4* sxb = sx4[cur];
        const ulonglong2* swb = swt[cur];
#pragma unroll
        for (int ci = 0; ci < CIC; ci++) {
#pragma unroll
            for (int tap = 0; tap < 9; tap++) {
                const int ti = tap / 3, tj = tap % 3;
                ulonglong2 A = *(const ulonglong2*)&sxb[(ci * 18 + ty + ti) * 36 + tx + tj];
                ulonglong2 C = *(const ulonglong2*)&sxb[(ci * 18 + ty + 8 + ti) * 36 + tx + tj];
                ulonglong2 w01 = swb[(ci * 9 + tap) * 2 + 0];
                ulonglong2 w23 = swb[(ci * 9 + tap) * 2 + 1];
                acc[0][0] = ffma2(A.x, w01.x, acc[0][0]); acc[0][1] = ffma2(A.y, w01.x, acc[0][1]);
                acc[0][2] = ffma2(C.x, w01.x, acc[0][2]); acc[0][3] = ffma2(C.y, w01.x, acc[0][3]);
                acc[1][0] = ffma2(A.x, w01.y, acc[1][0]); acc[1][1] = ffma2(A.y, w01.y, acc[1][1]);
                acc[1][2] = ffma2(C.x, w01.y, acc[1][2]); acc[1][3] = ffma2(C.y, w01.y, acc[1][3]);
                acc[2][0] = ffma2(A.x, w23.x, acc[2][0]); acc[2][1] = ffma2(A.y, w23.x, acc[2][1]);
                acc[2][2] = ffma2(C.x, w23.x, acc[2][2]); acc[2][3] = ffma2(C.y, w23.x, acc[2][3]);
                acc[3][0] = ffma2(A.x, w23.y, acc[3][0]); acc[3][1] = ffma2(A.y, w23.y, acc[3][1]);
                acc[3][2] = ffma2(C.x, w23.y, acc[3][2]); acc[3][3] = ffma2(C.y, w23.y, acc[3][3]);
            }
        }
        __syncthreads();
    }

    float* ob = out_part + (size_t)b * COUT * HW;
#pragma unroll
    for (int oc = 0; oc < OCPB; oc++) {
        float r0, r16, r32, r48, r8, r24, r40, r56;
        unpack2(acc[oc][0], r0,  r16);
        unpack2(acc[oc][1], r32, r48);
        unpack2(acc[oc][2], r8,  r24);
        unpack2(acc[oc][3], r40, r56);
        size_t base = ((size_t)(oc0 + oc) * HH) * WW + bx0 + tx;
        ob[base + (size_t)(ty)      * WW] = r0;
        ob[base + (size_t)(ty + 8)  * WW] = r8;
        ob[base + (size_t)(ty + 16) * WW] = r16;
        ob[base + (size_t)(ty + 24) * WW] = r24;
        ob[base + (size_t)(ty + 32) * WW] = r32;
        ob[base + (size_t)(ty + 40) * WW] = r40;
        ob[base + (size_t)(ty + 48) * WW] = r48;
        ob[base + (size_t)(ty + 56) * WW] = r56;
    }
}

// ---------------- instance norm + leaky, sums NPART split-K partials + bias -------
template<int NPART>
__global__ __launch_bounds__(256)
void inorm_lrelu_kernel(const float* __restrict__ in, size_t pstride,
                        const float* __restrict__ bias, int C,
                        float* __restrict__ out, const float* __restrict__ resid)
{
    __shared__ float s1[256], s2[256];
    const size_t base = (size_t)blockIdx.x * HW;
    const int c = blockIdx.x % C;
    const float bv = bias[c];
    const float* p = in + base;
    float v[16];
    float sum = 0.f, sq = 0.f;
#pragma unroll
    for (int i = 0; i < 16; i++) {
        int off = threadIdx.x + i * 256;
        float acc = bv + p[off];
        if (NPART >= 2) acc += p[pstride + off];
        if (NPART >= 3) acc += p[2 * pstride + off];
        if (NPART >= 4) acc += p[3 * pstride + off];
        v[i] = acc;
        sum += acc; sq += acc * acc;
    }
    s1[threadIdx.x] = sum; s2[threadIdx.x] = sq;
    __syncthreads();
    for (int off = 128; off; off >>= 1) {
        if (threadIdx.x < off) {
            s1[threadIdx.x] += s1[threadIdx.x + off];
            s2[threadIdx.x] += s2[threadIdx.x + off];
        }
        __syncthreads();
    }
    float mean = s1[0] * (1.f / HW);
    float var  = s2[0] * (1.f / HW) - mean * mean;
    float rstd = rsqrtf(var + EPSV);
    float* o = out + base;
    const float* rr = resid ? resid + base : nullptr;
#pragma unroll
    for (int i = 0; i < 16; i++) {
        float xv = v[i];
        float lr = xv > 0.f ? xv : SLOPE * xv;
        float val = (xv - mean) * rstd + lr;
        if (rr) val += rr[threadIdx.x + i * 256];
        o[threadIdx.x + i * 256] = val;
    }
}

// ---------------- layernorm over channels, coalesced via smem transpose ----------
__global__ __launch_bounds__(256)
void layernorm_v2_kernel(const float* __restrict__ h, const float* __restrict__ g,
                         const float* __restrict__ beta, float* __restrict__ t)
{
    __shared__ float sv[DIM][33];
    __shared__ float ps[8][33], ps2[8][33];
    __shared__ float smean[32], srstd[32];
    const int tx = threadIdx.x & 31, ty = threadIdx.x >> 5;
    const int l0 = blockIdx.x * 32, b = blockIdx.y;
    const float* hb = h + (size_t)b * DIM * HW + l0;

    for (int c = ty; c < DIM; c += 8)
        sv[c][tx] = hb[(size_t)c * HW + tx];
    __syncthreads();

    float sum = 0.f, sq = 0.f;
#pragma unroll
    for (int i = 0; i < 16; i++) {
        float v = sv[ty * 16 + i][tx];
        sum += v; sq += v * v;
    }
    ps[ty][tx] = sum; ps2[ty][tx] = sq;
    __syncthreads();
    if (ty == 0) {
        float s = 0.f, s2 = 0.f;
#pragma unroll
        for (int w = 0; w < 8; w++) { s += ps[w][tx]; s2 += ps2[w][tx]; }
        float mean = s * (1.f / DIM);
        float var  = s2 * (1.f / DIM) - mean * mean;
        smean[tx] = mean;
        srstd[tx] = rsqrtf(var + EPSV);
    }
    __syncthreads();

#pragma unroll
    for (int cc = 0; cc < 4; cc++) {
        int c = tx + 32 * cc;
        float gv = g[c], bv = beta[c];
        for (int l = ty; l < 32; l += 8) {
            float m = smean[l], rs = srstd[l];
            t[((size_t)(b * LSEQ + l0 + l)) * DIM + c] = (sv[c][l] - m) * rs * gv + bv;
        }
    }
}

// ---------------- in_proj GEMM (software-pipelined loads) ------------------------
__global__ __launch_bounds__(256)
void gemm_inproj_kernel(const float* __restrict__ A, const float* __restrict__ Bw,
                        float* __restrict__ xrx, float* __restrict__ resT)
{
    __shared__ ull   As2[8][128];
    __shared__ float Bs[8][128];
    __shared__ float sT[32][129];
    const int tid = threadIdx.x;
    const int tm = tid >> 4, tn = tid & 15;
    const int m0 = blockIdx.x * 128, n0 = blockIdx.y * 128;
    const int K = DIM, N = 2 * DIN;
    ull acc[8][4];
#pragma unroll
    for (int i = 0; i < 8; i++)
#pragma unroll
        for (int j = 0; j < 4; j++) acc[i][j] = 0ull;
    const int ar = tid >> 1, ak = (tid & 1) * 4;
    const int bk = tid >> 5, bn = (tid & 31) * 4;
    float4 av = *(const float4*)(A + (size_t)(m0 + ar) * K + ak);
    float4 bv = *(const float4*)(Bw + (size_t)bk * N + n0 + bn);
    for (int k0 = 0; k0 < K; k0 += 8) {
        __syncthreads();
        As2[ak + 0][ar] = pack2(av.x, av.x);
        As2[ak + 1][ar] = pack2(av.y, av.y);
        As2[ak + 2][ar] = pack2(av.z, av.z);
        As2[ak + 3][ar] = pack2(av.w, av.w);
        *(float4*)&Bs[bk][bn] = bv;
        __syncthreads();
        if (k0 + 8 < K) {
            av = *(const float4*)(A + (size_t)(m0 + ar) * K + k0 + 8 + ak);
            bv = *(const float4*)(Bw + (size_t)(k0 + 8 + bk) * N + n0 + bn);
        }
#pragma unroll
        for (int k = 0; k < 8; k++) {
            ull a2[8], b2[4];
#pragma unroll
            for (int i = 0; i < 8; i++) a2[i] = As2[k][tm * 8 + i];
#pragma unroll
            for (int j = 0; j < 4; j++) b2[j] = *(const ull*)&Bs[k][tn * 2 + 32 * j];
#pragma unroll
            for (int i = 0; i < 8; i++)
#pragma unroll
                for (int j = 0; j < 4; j++)
                    acc[i][j] = ffma2(a2[i], b2[j], acc[i][j]);
        }
    }
    if (n0 < DIN) {
#pragma unroll
        for (int i = 0; i < 8; i++) {
            int row = m0 + tm * 8 + i;
#pragma unroll
            for (int j = 0; j < 4; j++) {
                float lo, hi; unpack2(acc[i][j], lo, hi);
                *(float2*)(xrx + (size_t)row * DIN + n0 + tn * 2 + 32 * j) = make_float2(lo, hi);
            }
        }
    } else {
        const int b = m0 >> 12, t0 = m0 & 4095, d0 = n0 - DIN;
#pragma unroll
        for (int j = 0; j < 4; j++) {
            __syncthreads();
#pragma unroll
            for (int i = 0; i < 8; i++) {
                int rl = tm * 8 + i;
                float lo, hi; unpack2(acc[i][j], lo, hi);
                sT[2 * tn][rl]     = lo;
                sT[2 * tn + 1][rl] = hi;
            }
            __syncthreads();
            int col = tid >> 3, r0 = (tid & 7) * 16;
            float* dst = resT + ((size_t)(b * DIN + d0 + 32 * j + col)) * LSEQ + t0 + r0;
#pragma unroll
            for (int k = 0; k < 16; k++) dst[k] = sT[col][r0 + k];
        }
    }
}

// ---------------- delta GEMM (software-pipelined loads) --------------------------
__global__ __launch_bounds__(256)
void gemm_delta_kernel(const float* __restrict__ A, const float* __restrict__ Bw,
                       const float* __restrict__ dtb, float* __restrict__ deltaT)
{
    __shared__ ull   As2[8][128];
    __shared__ float Bs[8][128];
    __shared__ float sT[32][129];
    const int tid = threadIdx.x;
    const int tm = tid >> 4, tn = tid & 15;
    const int m0 = blockIdx.x * 128, n0 = blockIdx.y * 128;
    const int K = DIN, N = DIN;
    ull acc[8][4];
#pragma unroll
    for (int i = 0; i < 8; i++)
#pragma unroll
        for (int j = 0; j < 4; j++) acc[i][j] = 0ull;
    const int ar = tid >> 1, ak = (tid & 1) * 4;
    const int bk = tid >> 5, bn = (tid & 31) * 4;
    float4 av = *(const float4*)(A + (size_t)(m0 + ar) * K + ak);
    float4 bv = *(const float4*)(Bw + (size_t)bk * N + n0 + bn);
    for (int k0 = 0; k0 < K; k0 += 8) {
        __syncthreads();
        As2[ak + 0][ar] = pack2(av.x, av.x);
        As2[ak + 1][ar] = pack2(av.y, av.y);
        As2[ak + 2][ar] = pack2(av.z, av.z);
        As2[ak + 3][ar] = pack2(av.w, av.w);
        *(float4*)&Bs[bk][bn] = bv;
        __syncthreads();
        if (k0 + 8 < K) {
            av = *(const float4*)(A + (size_t)(m0 + ar) * K + k0 + 8 + ak);
            bv = *(const float4*)(Bw + (size_t)(k0 + 8 + bk) * N + n0 + bn);
        }
#pragma unroll
        for (int k = 0; k < 8; k++) {
            ull a2[8], b2[4];
#pragma unroll
            for (int i = 0; i < 8; i++) a2[i] = As2[k][tm * 8 + i];
#pragma unroll
            for (int j = 0; j < 4; j++) b2[j] = *(const ull*)&Bs[k][tn * 2 + 32 * j];
#pragma unroll
            for (int i = 0; i < 8; i++)
#pragma unroll
                for (int j = 0; j < 4; j++)
                    acc[i][j] = ffma2(a2[i], b2[j], acc[i][j]);
        }
    }
    const int b = m0 >> 12, t0 = m0 & 4095;
#pragma unroll
    for (int j = 0; j < 4; j++) {
        __syncthreads();
        float blo = dtb[n0 + 32 * j + 2 * tn];
        float bhi = dtb[n0 + 32 * j + 2 * tn + 1];
#pragma unroll
        for (int i = 0; i < 8; i++) {
            int rl = tm * 8 + i;
            float lo, hi; unpack2(acc[i][j], lo, hi);
            sT[2 * tn][rl]     = softplus_f(lo + blo);
            sT[2 * tn + 1][rl] = softplus_f(hi + bhi);
        }
        __syncthreads();
        int col = tid >> 3, r0 = (tid & 7) * 16;
        float* dst = deltaT + ((size_t)(b * DIN + n0 + 32 * j + col)) * LSEQ + t0 + r0;
#pragma unroll
        for (int k = 0; k < 16; k++) dst[k] = sT[col][r0 + k];
    }
}

// ---------------- BC GEMM (software-pipelined loads) -----------------------------
__global__ __launch_bounds__(256)
void gemm_bc_kernel(const float* __restrict__ A, const float* __restrict__ xw,
                    float* __restrict__ bc)
{
    __shared__ ull   As2[16][128];
    __shared__ float Bs[16][32];
    const int tid = threadIdx.x;
    const int tm = tid >> 4, tn = tid & 15;
    const int m0 = blockIdx.x * 128;
    ull acc[8];
#pragma unroll
    for (int i = 0; i < 8; i++) acc[i] = 0ull;
    const int ar = tid >> 1, aq = (tid & 1) * 8;
    float4 a1 = *(const float4*)(A + (size_t)(m0 + ar) * DIN + aq);
    float4 a2v = *(const float4*)(A + (size_t)(m0 + ar) * DIN + aq + 4);
    float bvv[2];
#pragma unroll
    for (int q = 0; q < 2; q++) {
        int idx = tid + q * 256;
        bvv[q] = xw[(size_t)(idx >> 5) * 40 + 8 + (idx & 31)];
    }
    for (int k0 = 0; k0 < DIN; k0 += 16) {
        __syncthreads();
        As2[aq + 0][ar] = pack2(a1.x, a1.x);
        As2[aq + 1][ar] = pack2(a1.y, a1.y);
        As2[aq + 2][ar] = pack2(a1.z, a1.z);
        As2[aq + 3][ar] = pack2(a1.w, a1.w);
        As2[aq + 4][ar] = pack2(a2v.x, a2v.x);
        As2[aq + 5][ar] = pack2(a2v.y, a2v.y);
        As2[aq + 6][ar] = pack2(a2v.z, a2v.z);
        As2[aq + 7][ar] = pack2(a2v.w, a2v.w);
#pragma unroll
        for (int q = 0; q < 2; q++) {
            int idx = tid + q * 256;
            Bs[idx >> 5][idx & 31] = bvv[q];
        }
        __syncthreads();
        if (k0 + 16 < DIN) {
            a1  = *(const float4*)(A + (size_t)(m0 + ar) * DIN + k0 + 16 + aq);
            a2v = *(const float4*)(A + (size_t)(m0 + ar) * DIN + k0 + 16 + aq + 4);
#pragma unroll
            for (int q = 0; q < 2; q++) {
                int idx = tid + q * 256;
                bvv[q] = xw[(size_t)(k0 + 16 + (idx >> 5)) * 40 + 8 + (idx & 31)];
            }
        }
#pragma unroll
        for (int k = 0; k < 16; k++) {
            ull b2 = *(const ull*)&Bs[k][2 * tn];
#pragma unroll
            for (int i = 0; i < 8; i++)
                acc[i] = ffma2(As2[k][tm * 8 + i], b2, acc[i]);
        }
    }
#pragma unroll
    for (int i = 0; i < 8; i++) {
        int row = m0 + tm * 8 + i;
        float lo, hi; unpack2(acc[i], lo, hi);
        *(float2*)(bc + (size_t)row * 32 + 2 * tn) = make_float2(lo, hi);
    }
}

// ---------------- out_proj GEMM (software-pipelined loads) -----------------------
__global__ __launch_bounds__(256)
void gemm_out_kernel(const float* __restrict__ gatedT, const float* __restrict__ Bw,
                     float* __restrict__ out)
{
    __shared__ ull   As2[8][128];
    __shared__ float Bs[8][128];
    __shared__ float sT[32][129];
    const int tid = threadIdx.x;
    const int tm = tid >> 4, tn = tid & 15;
    const int m0 = blockIdx.x * 128;
    const int K = DIN, N = DIM;
    const int b = m0 >> 12, t0 = m0 & 4095;
    ull acc[8][4];
#pragma unroll
    for (int i = 0; i < 8; i++)
#pragma unroll
        for (int j = 0; j < 4; j++) acc[i][j] = 0ull;
    const int kk = tid >> 5, tl = tid & 31;
    const int bk = tid >> 5, bn = (tid & 31) * 4;
    float gv[4];
#pragma unroll
    for (int it = 0; it < 4; it++)
        gv[it] = gatedT[((size_t)(b * DIN + kk)) * LSEQ + t0 + tl + 32 * it];
    float4 bv = *(const float4*)(Bw + (size_t)bk * N + bn);
    for (int k0 = 0; k0 < K; k0 += 8) {
        __syncthreads();
#pragma unroll
        for (int it = 0; it < 4; it++)
            As2[kk][tl + 32 * it] = pack2(gv[it], gv[it]);
        *(float4*)&Bs[bk][bn] = bv;
        __syncthreads();
        if (k0 + 8 < K) {
            int d = k0 + 8 + kk;
#pragma unroll
            for (int it = 0; it < 4; it++)
                gv[it] = gatedT[((size_t)(b * DIN + d)) * LSEQ + t0 + tl + 32 * it];
            bv = *(const float4*)(Bw + (size_t)(k0 + 8 + bk) * N + bn);
        }
#pragma unroll
        for (int k = 0; k < 8; k++) {
            ull a2[8], b2[4];
#pragma unroll
            for (int i = 0; i < 8; i++) a2[i] = As2[k][tm * 8 + i];
#pragma unroll
            for (int j = 0; j < 4; j++) b2[j] = *(const ull*)&Bs[k][tn * 2 + 32 * j];
#pragma unroll
            for (int i = 0; i < 8; i++)
#pragma unroll
                for (int j = 0; j < 4; j++)
                    acc[i][j] = ffma2(a2[i], b2[j], acc[i][j]);
        }
    }
#pragma unroll
    for (int j = 0; j < 4; j++) {
        __syncthreads();
#pragma unroll
        for (int i = 0; i < 8; i++) {
            int rl = tm * 8 + i;
            float lo, hi; unpack2(acc[i][j], lo, hi);
            sT[2 * tn][rl]     = lo;
            sT[2 * tn + 1][rl] = hi;
        }
        __syncthreads();
        int col = tid >> 3, r0 = (tid & 7) * 16;
        float* dst = out + ((size_t)(b * DIM + 32 * j + col)) * LSEQ + t0 + r0;
#pragma unroll
        for (int k = 0; k < 16; k++) dst[k] = sT[col][r0 + k];
    }
}

// ---------------- causal depthwise conv1d (k=4) + silu, dual-layout output ------
__global__ __launch_bounds__(256)
void conv1d_silu_T_kernel(const float* __restrict__ xrx, const float4* __restrict__ wp,
                          const float* __restrict__ bias,
                          float* __restrict__ xs, float* __restrict__ xsT)
{
    __shared__ float st[32][33];
    const int tx = threadIdx.x & 31, ty = threadIdx.x >> 5;
    const int t0 = blockIdx.x * 32, d0 = blockIdx.y * 32, b = blockIdx.z;
    const int d = d0 + tx;
    float4 w = wp[d];
    float bv = bias[d];
    const float* xb = xrx + (size_t)b * LSEQ * DIN + d;
#pragma unroll
    for (int k = 0; k < 4; k++) {
        int t = t0 + ty + 8 * k;
        float acc = bv;
        if (t - 3 >= 0) acc = fmaf(w.x, xb[(size_t)(t - 3) * DIN], acc);
        if (t - 2 >= 0) acc = fmaf(w.y, xb[(size_t)(t - 2) * DIN], acc);
        if (t - 1 >= 0) acc = fmaf(w.z, xb[(size_t)(t - 1) * DIN], acc);
        acc = fmaf(w.w, xb[(size_t)t * DIN], acc);
        float s = acc / (1.f + __expf(-acc));
        xs[((size_t)b * LSEQ + t) * DIN + d] = s;
        st[tx][ty + 8 * k] = s;
    }
    __syncthreads();
#pragma unroll
    for (int k = 0; k < 4; k++) {
        int dd = d0 + ty + 8 * k;
        xsT[((size_t)(b * DIN + dd)) * LSEQ + t0 + tx] = st[ty + 8 * k][tx];
    }
}

// ---------------- scan pass 1 (R8 form) ----------------
__global__ __launch_bounds__(256)
void scan_p1_kernel(const float* __restrict__ deltaT, const float* __restrict__ xsT,
                    const float* __restrict__ bc, const float* __restrict__ negA,
                    float* __restrict__ chA, float* __restrict__ chH)
{
    int gw = (blockIdx.x * blockDim.x + threadIdx.x) >> 5;
    int lane = threadIdx.x & 31;
    int half = lane >> 4, n = lane & 15;
    int chunk = gw >> 9;
    int wp = gw & 511;
    int pair = wp * 2 + half;
    int b = pair >> 8, d = pair & 255;
    int t0 = chunk * CHLEN;

    float A = negA[d * DSTATE + n];
    const float* dl = deltaT + (size_t)(b * DIN + d) * LSEQ + t0;
    const float* ul = xsT    + (size_t)(b * DIN + d) * LSEQ + t0;
    const float* xb = bc + ((size_t)b * LSEQ + t0) * 32;

    float h = 0.f, pA = 1.f;
    for (int t = 0; t < CHLEN; t++) {
        float dt  = dl[t];
        float ut  = ul[t];
        float Bn  = xb[t * 32 + n];
        float a = __expf(dt * A);
        pA *= a;
        h = fmaf(a, h, dt * ut * Bn);
    }
    int idx = (chunk * NPAIR + pair) * DSTATE + n;
    chA[idx] = pA;
    chH[idx] = h;
}

// ---------------- scan pass 2 ----------------
__global__ __launch_bounds__(256)
void scan_p2_kernel(const float* __restrict__ chA, const float* __restrict__ chH,
                    float* __restrict__ hst)
{
    int i = blockIdx.x * 256 + threadIdx.x;
    float h = 0.f;
    hst[i] = 0.f;
#pragma unroll
    for (int c = 0; c < NCH - 1; c++) {
        h = fmaf(chA[c * NPAIR * DSTATE + i], h, chH[c * NPAIR * DSTATE + i]);
        hst[(c + 1) * NPAIR * DSTATE + i] = h;
    }
}

// ---------------- scan pass 3 (R8 form, + fused gate) ----------------
__global__ __launch_bounds__(256)
void scan_p3_kernel(const float* __restrict__ deltaT, const float* __restrict__ xsT,
                    const float* __restrict__ bc, const float* __restrict__ negA,
                    const float* __restrict__ Dp, const float* __restrict__ hst,
                    const float* __restrict__ resT, float* __restrict__ gatedT)
{
    __shared__ float sy[8][2][32];
    int gw = (blockIdx.x * blockDim.x + threadIdx.x) >> 5;
    int lane = threadIdx.x & 31;
    int wslot = threadIdx.x >> 5;
    int half = lane >> 4, n = lane & 15;
    int chunk = gw >> 9;
    int wp = gw & 511;
    int pair = wp * 2 + half;
    int b = pair >> 8, d = pair & 255;
    int t0 = chunk * CHLEN;

    float A = negA[d * DSTATE + n];
    const float* dl = deltaT + (size_t)(b * DIN + d) * LSEQ + t0;
    const float* ul = xsT    + (size_t)(b * DIN + d) * LSEQ + t0;
    const float* xb = bc + ((size_t)b * LSEQ + t0) * 32;
    float h = hst[(chunk * NPAIR + pair) * DSTATE + n];

    int dp0 = (wp * 2) & 255;
    int bb  = (wp * 2) >> 8;
    float Dv0 = Dp[dp0], Dv1 = Dp[dp0 + 1];
    const float* u0p = xsT + (size_t)(bb * DIN + dp0)     * LSEQ + t0;
    const float* u1p = xsT + (size_t)(bb * DIN + dp0 + 1) * LSEQ + t0;
    const float* r0p = resT + (size_t)(bb * DIN + dp0)     * LSEQ + t0;
    const float* r1p = resT + (size_t)(bb * DIN + dp0 + 1) * LSEQ + t0;
    float* y0p = gatedT + (size_t)(bb * DIN + dp0)     * LSEQ + t0;
    float* y1p = gatedT + (size_t)(bb * DIN + dp0 + 1) * LSEQ + t0;

    for (int t = 0; t < CHLEN; t++) {
        float dt  = dl[t];
        float ut  = ul[t];
        float Bn  = xb[t * 32 + n];
        float Cn  = xb[t * 32 + 16 + n];
        float a = __expf(dt * A);
        h = fmaf(a, h, dt * ut * Bn);
        float yv = h * Cn;
        yv += __shfl_xor_sync(0xffffffffu, yv, 8);
        yv += __shfl_xor_sync(0xffffffffu, yv, 4);
        yv += __shfl_xor_sync(0xffffffffu, yv, 2);
        yv += __shfl_xor_sync(0xffffffffu, yv, 1);
        if (n == 0) sy[wslot][half][t & 31] = yv;
        if ((t & 31) == 31) {
            __syncwarp();
            int tb = t & ~31;
            float r0 = r0p[tb + lane];
            float r1 = r1p[tb + lane];
            float s0 = r0 / (1.f + __expf(-r0));
            float s1 = r1 / (1.f + __expf(-r1));
            y0p[tb + lane] = fmaf(u0p[tb + lane], Dv0, sy[wslot][0][lane]) * s0;
            y1p[tb + lane] = fmaf(u1p[tb + lane], Dv1, sy[wslot][1][lane]) * s1;
            __syncwarp();
        }
    }
}

// ---------------- launch ----------------
extern "C" void kernel_launch(void* const* d_in, const int* in_sizes, int n_in,
                              void* d_out, int out_size)
{
    const float* x         = (const float*)d_in[0];
    const float* conv1_w   = (const float*)d_in[1];
    const float* conv1_b   = (const float*)d_in[2];
    const float* conv2_w   = (const float*)d_in[3];
    const float* conv2_b   = (const float*)d_in[4];
    const float* ln_g      = (const float*)d_in[5];
    const float* ln_b      = (const float*)d_in[6];
    const float* in_proj_w = (const float*)d_in[7];
    const float* conv1d_w  = (const float*)d_in[8];
    const float* conv1d_b  = (const float*)d_in[9];
    const float* x_proj_w  = (const float*)d_in[10];
    const float* dt_proj_w = (const float*)d_in[11];
    const float* dt_proj_b = (const float*)d_in[12];
    const float* A_log     = (const float*)d_in[13];
    const float* Dp        = (const float*)d_in[14];
    const float* out_proj_w= (const float*)d_in[15];
    float* out = (float*)d_out;

    Scratch* s = nullptr;
    cudaGetSymbolAddress((void**)&s, g_scratch);

    const size_t p1stride = (size_t)BATCH * DIN * HW;
    const size_t p2stride = (size_t)BATCH * DIM * HW;

    // 0-2) precompute (conv1 stays at profiled slot 3)
    negA_wpack_kernel<<<17, 256>>>(A_log, s->negA, conv1d_w, s->wpack);
    weff_kernel<<<DIN, DIN>>>(x_proj_w, dt_proj_w, s->weff);
    wdup_kernel<<<(W1ELEMS + W2ELEMS + 255) / 256, 256>>>(conv1_w, conv2_w, s->wd1, s->wd2);
    // 3) conv1 split-K x2, OCPB=4: grid 2 x 1 x 512 = 1024 blocks
    conv3x3_v9_kernel<DIM, DIN, 2><<<dim3(2, 1, BATCH * (DIN / 4) * 2), 256>>>(
        x, s->wd1, s->h1);
    // 4) inorm (sums 2 partials + bias) + leaky
    inorm_lrelu_kernel<2><<<BATCH * DIN, 256>>>(s->h1, p1stride, conv1_b, DIN, s->h1, nullptr);
    // 5) conv2 split-K x4, OCPB=4: grid 2 x 1 x 512 = 1024 blocks
    conv3x3_v9_kernel<DIN, DIM, 4><<<dim3(2, 1, BATCH * (DIM / 4) * 4), 256>>>(
        s->h1, s->wd2, s->h2);
    // 6) inorm (sums 4 partials + bias) + leaky + residual
    inorm_lrelu_kernel<4><<<BATCH * DIM, 256>>>(s->h2, p2stride, conv2_b, DIM, s->h2, x);
    // 7) layernorm (coalesced) + transpose to (b*l, c)
    layernorm_v2_kernel<<<dim3(HW / 32, BATCH), 256>>>(s->h2, ln_g, ln_b, s->t);
    // 8) in_proj GEMM (xs rows + res transposed)
    gemm_inproj_kernel<<<dim3(BATCH * LSEQ / 128, 4), 256>>>(
        s->t, in_proj_w, s->xrx, s->resT);
    // 9) depthwise conv1d + silu
    conv1d_silu_T_kernel<<<dim3(LSEQ / 32, DIN / 32, BATCH), 256>>>(
        s->xrx, s->wpack, conv1d_b, s->xs, s->xsT);
    // 10) delta GEMM (softplus + transpose)
    gemm_delta_kernel<<<dim3(BATCH * LSEQ / 128, 2), 256>>>(
        s->xs, s->weff, dt_proj_b, s->deltaT);
    // 11) B/C GEMM
    gemm_bc_kernel<<<BATCH * LSEQ / 128, 256>>>(s->xs, x_proj_w, s->bc);
    // 12) chunked selective scan
    scan_p1_kernel<<<(NCH - 1) * 64, 256>>>(
        s->deltaT, s->xsT, s->bc, s->negA, s->chA, s->chH);
    scan_p2_kernel<<<NPAIR * DSTATE / 256, 256>>>(s->chA, s->chH, s->hst);
    scan_p3_kernel<<<NCH * 64, 256>>>(
        s->deltaT, s->xsT, s->bc, s->negA, Dp, s->hst, s->resT, s->gatedT);
    // 13) out_proj GEMM (gated A, coalesced) + NCHW store
    gemm_out_kernel<<<BATCH * LSEQ / 128, 256>>>(s->gatedT, out_proj_w, out);
}

// round 11
// speedup vs baseline: 1.1390x; 1.1390x over previous
#include <cuda_runtime.h>
#include <cuda_bf16.h>
#include <cstdint>
#include <cstddef>

#define BATCH 4
#define DIM   128
#define DIN   256
#define HH    64
#define WW    64
#define HW    4096
#define LSEQ  4096
#define DSTATE 16
#define DTRANK 8
#define EPSV  1e-5f
#define SLOPE 0.01f

#define NCH   4
#define CHLEN (LSEQ/NCH)
#define NPAIR (BATCH*DIN)

typedef unsigned long long ull;

__device__ __forceinline__ ull pack2(float lo, float hi) {
    ull r; asm("mov.b64 %0, {%1, %2};" : "=l"(r) : "f"(lo), "f"(hi)); return r;
}
__device__ __forceinline__ void unpack2(ull p, float& lo, float& hi) {
    asm("mov.b64 {%0, %1}, %2;" : "=f"(lo), "=f"(hi) : "l"(p));
}
__device__ __forceinline__ ull ffma2(ull a, ull b, ull c) {
    ull d; asm("fma.rn.f32x2 %0, %1, %2, %3;" : "=l"(d) : "l"(a), "l"(b), "l"(c)); return d;
}
__device__ __forceinline__ float softplus_f(float x) {
    return (x > 20.f) ? x : log1pf(expf(x));
}
__device__ __forceinline__ uint32_t saddr(const void* p) {
    return (uint32_t)__cvta_generic_to_shared(p);
}
__device__ __forceinline__ void cpa4(uint32_t dst, const void* src) {
    asm volatile("cp.async.ca.shared.global [%0], [%1], 4;" :: "r"(dst), "l"(src));
}
__device__ __forceinline__ void cpa16(uint32_t dst, const void* src) {
    asm volatile("cp.async.cg.shared.global [%0], [%1], 16;" :: "r"(dst), "l"(src));
}

#define W1ELEMS (DIM * 9 * DIN)
#define W2ELEMS (DIN * 9 * DIM)

// ---------------- scratch ----------------
struct Scratch {
    float h1[2 * BATCH * DIN * HW];
    float h2[4 * BATCH * DIM * HW];
    float t [BATCH * LSEQ * DIM];
    float xrx[BATCH * LSEQ * DIN];
    float resT[NPAIR * LSEQ];
    float xs[BATCH * LSEQ * DIN];
    float xsT[NPAIR * LSEQ];
    float deltaT[NPAIR * LSEQ];
    float gatedT[NPAIR * LSEQ];
    float bc[BATCH * LSEQ * 2*DSTATE];
    float weff[DIN * DIN];
    float negA[DIN * DSTATE];
    float4 wpack[DIN];
    ull  wd1[W1ELEMS];
    ull  wd2[W2ELEMS];
    float chA[(NCH-1) * NPAIR * DSTATE];
    float chH[(NCH-1) * NPAIR * DSTATE];
    float hst[NCH * NPAIR * DSTATE];
};
__device__ Scratch g_scratch;

// ---------------- precompute kernels (3 launches; conv1 stays at slot 3) ---------
__global__ void negA_wpack_kernel(const float* __restrict__ A_log, float* __restrict__ negA,
                                  const float* __restrict__ w1d, float4* __restrict__ wp)
{
    if (blockIdx.x < 16) {
        int i = blockIdx.x * 256 + threadIdx.x;
        negA[i] = -expf(A_log[i]);
    } else {
        int d = threadIdx.x;
        wp[d] = make_float4(w1d[4*d], w1d[4*d+1], w1d[4*d+2], w1d[4*d+3]);
    }
}
__global__ __launch_bounds__(256)
void weff_kernel(const float* __restrict__ xw, const float* __restrict__ dtw,
                 float* __restrict__ weff)
{
    int k = blockIdx.x, d = threadIdx.x;
    float acc = 0.f;
#pragma unroll
    for (int r = 0; r < DTRANK; r++)
        acc = fmaf(xw[k * 40 + r], dtw[r * DIN + d], acc);
    weff[k * DIN + d] = acc;
}
__global__ __launch_bounds__(256)
void wdup_kernel(const float* __restrict__ w1, const float* __restrict__ w2,
                 ull* __restrict__ wd1, ull* __restrict__ wd2)
{
    int i = blockIdx.x * 256 + threadIdx.x;
    if (i < W1ELEMS) {
        int oc = i % DIN; int rest = i / DIN;
        int tap = rest % 9; int ci = rest / 9;
        float w = w1[((size_t)oc * DIM + ci) * 9 + tap];
        wd1[i] = pack2(w, w);
    } else if (i < W1ELEMS + W2ELEMS) {
        int j = i - W1ELEMS;
        int oc = j % DIM; int rest = j / DIM;
        int tap = rest % 9; int ci = rest / 9;
        float w = w2[((size_t)oc * DIN + ci) * 9 + tap];
        wd2[j] = pack2(w, w);
    }
}

// ---------------- conv v8 (exact R8 form) -----------------------------------------
template<int CIN, int COUT, int SPLIT>
__global__ __launch_bounds__(256, 2)
void conv3x3_v8_kernel(const float* __restrict__ x, const ull* __restrict__ wd,
                       float* __restrict__ out)
{
    constexpr int OCPB = 8, CIC = 2, CSPAN = CIN / SPLIT;
    constexpr int NCHUNK = CSPAN / CIC;
    __shared__ float4 sx4[2][CIC * 18 * 36];
    __shared__ ulonglong2 swt[2][CIC * 9 * 4];

    const int tid = threadIdx.x;
    const int tx = tid & 31, ty = tid >> 5;
    const int bx0 = blockIdx.x * 32;
    const int bz = blockIdx.z;
    constexpr int OCB = COUT / OCPB;
    const int b    = bz / (OCB * SPLIT);
    const int r    = bz % (OCB * SPLIT);
    const int oc0  = (r / SPLIT) * OCPB;
    const int part = r % SPLIT;
    const int cbase = part * CSPAN;
    const float* xb = x + (size_t)b * CIN * HW;
    float* out_part = out + (size_t)part * BATCH * COUT * HW;

    for (int i = tid; i < 2 * CIC * 18 * 36; i += 256)
        ((float4*)sx4)[i] = make_float4(0.f, 0.f, 0.f, 0.f);
    __syncthreads();

    auto load_chunk = [&](int buf, int c0) {
        for (int rr = ty; rr < CIC * 18; rr += 8) {
            int ci = (rr >= 18) ? 1 : 0;
            int p  = rr - 18 * ci;
            int gr = p - 1;
#pragma unroll
            for (int s = 0; s < 2; s++) {
                int xx = tx + 32 * s;
                if (xx < 34) {
                    int gx = bx0 + xx - 1;
                    if ((unsigned)gx < (unsigned)WW) {
                        const float* pc = xb + (size_t)(cbase + c0 + ci) * HW + gx;
                        uint32_t dst = saddr(&sx4[buf][rr * 36 + xx]);
                        if (p > 0)  cpa4(dst + 0,  pc + (size_t)gr * WW);
                        cpa4(dst + 4,  pc + (size_t)(gr + 16) * WW);
                        cpa4(dst + 8,  pc + (size_t)(gr + 32) * WW);
                        if (p < 17) cpa4(dst + 12, pc + (size_t)(gr + 48) * WW);
                    }
                }
            }
        }
        if (tid < CIC * 9 * 4) {
            int q = tid & 3;
            int rowi = tid >> 2;
            int ci = (rowi >= 9) ? 1 : 0;
            int tap = rowi - 9 * ci;
            const ull* src = wd + ((size_t)(cbase + c0 + ci) * 9 + tap) * COUT + oc0 + 2 * q;
            cpa16(saddr(&swt[buf][rowi * 4 + q]), src);
        }
    };

    ull acc[OCPB][4];
#pragma unroll
    for (int i = 0; i < OCPB; i++)
#pragma unroll
        for (int q = 0; q < 4; q++) acc[i][q] = 0ull;

    load_chunk(0, 0);
    asm volatile("cp.async.commit_group;");

    for (int ch = 0; ch < NCHUNK; ch++) {
        const int cur = ch & 1;
        if (ch + 1 < NCHUNK) {
            load_chunk(cur ^ 1, (ch + 1) * CIC);
            asm volatile("cp.async.commit_group;");
            asm volatile("cp.async.wait_group 1;");
        } else {
            asm volatile("cp.async.wait_group 0;");
        }
        __syncthreads();

        const float4* sxb = sx4[cur];
        const ulonglong2* swb = swt[cur];
#pragma unroll
        for (int ci = 0; ci < CIC; ci++) {
#pragma unroll
            for (int tap = 0; tap < 9; tap++) {
                const int ti = tap / 3, tj = tap % 3;
                ulonglong2 A = *(const ulonglong2*)&sxb[(ci * 18 + ty + ti) * 36 + tx + tj];
                ulonglong2 C = *(const ulonglong2*)&sxb[(ci * 18 + ty + 8 + ti) * 36 + tx + tj];
                ulonglong2 w01 = swb[(ci * 9 + tap) * 4 + 0];
                ulonglong2 w23 = swb[(ci * 9 + tap) * 4 + 1];
                ulonglong2 w45 = swb[(ci * 9 + tap) * 4 + 2];
                ulonglong2 w67 = swb[(ci * 9 + tap) * 4 + 3];
                acc[0][0] = ffma2(A.x, w01.x, acc[0][0]); acc[0][1] = ffma2(A.y, w01.x, acc[0][1]);
                acc[0][2] = ffma2(C.x, w01.x, acc[0][2]); acc[0][3] = ffma2(C.y, w01.x, acc[0][3]);
                acc[1][0] = ffma2(A.x, w01.y, acc[1][0]); acc[1][1] = ffma2(A.y, w01.y, acc[1][1]);
                acc[1][2] = ffma2(C.x, w01.y, acc[1][2]); acc[1][3] = ffma2(C.y, w01.y, acc[1][3]);
                acc[2][0] = ffma2(A.x, w23.x, acc[2][0]); acc[2][1] = ffma2(A.y, w23.x, acc[2][1]);
                acc[2][2] = ffma2(C.x, w23.x, acc[2][2]); acc[2][3] = ffma2(C.y, w23.x, acc[2][3]);
                acc[3][0] = ffma2(A.x, w23.y, acc[3][0]); acc[3][1] = ffma2(A.y, w23.y, acc[3][1]);
                acc[3][2] = ffma2(C.x, w23.y, acc[3][2]); acc[3][3] = ffma2(C.y, w23.y, acc[3][3]);
                acc[4][0] = ffma2(A.x, w45.x, acc[4][0]); acc[4][1] = ffma2(A.y, w45.x, acc[4][1]);
                acc[4][2] = ffma2(C.x, w45.x, acc[4][2]); acc[4][3] = ffma2(C.y, w45.x, acc[4][3]);
                acc[5][0] = ffma2(A.x, w45.y, acc[5][0]); acc[5][1] = ffma2(A.y, w45.y, acc[5][1]);
                acc[5][2] = ffma2(C.x, w45.y, acc[5][2]); acc[5][3] = ffma2(C.y, w45.y, acc[5][3]);
                acc[6][0] = ffma2(A.x, w67.x, acc[6][0]); acc[6][1] = ffma2(A.y, w67.x, acc[6][1]);
                acc[6][2] = ffma2(C.x, w67.x, acc[6][2]); acc[6][3] = ffma2(C.y, w67.x, acc[6][3]);
                acc[7][0] = ffma2(A.x, w67.y, acc[7][0]); acc[7][1] = ffma2(A.y, w67.y, acc[7][1]);
                acc[7][2] = ffma2(C.x, w67.y, acc[7][2]); acc[7][3] = ffma2(C.y, w67.y, acc[7][3]);
            }
        }
        __syncthreads();
    }

    float* ob = out_part + (size_t)b * COUT * HW;
#pragma unroll
    for (int oc = 0; oc < OCPB; oc++) {
        float r0, r16, r32, r48, r8, r24, r40, r56;
        unpack2(acc[oc][0], r0,  r16);
        unpack2(acc[oc][1], r32, r48);
        unpack2(acc[oc][2], r8,  r24);
        unpack2(acc[oc][3], r40, r56);
        size_t base = ((size_t)(oc0 + oc) * HH) * WW + bx0 + tx;
        ob[base + (size_t)(ty)      * WW] = r0;
        ob[base + (size_t)(ty + 8)  * WW] = r8;
        ob[base + (size_t)(ty + 16) * WW] = r16;
        ob[base + (size_t)(ty + 24) * WW] = r24;
        ob[base + (size_t)(ty + 32) * WW] = r32;
        ob[base + (size_t)(ty + 40) * WW] = r40;
        ob[base + (size_t)(ty + 48) * WW] = r48;
        ob[base + (size_t)(ty + 56) * WW] = r56;
    }
}

// ---------------- instance norm + leaky, sums NPART split-K partials + bias -------
template<int NPART>
__global__ __launch_bounds__(256)
void inorm_lrelu_kernel(const float* __restrict__ in, size_t pstride,
                        const float* __restrict__ bias, int C,
                        float* __restrict__ out, const float* __restrict__ resid)
{
    __shared__ float s1[256], s2[256];
    const size_t base = (size_t)blockIdx.x * HW;
    const int c = blockIdx.x % C;
    const float bv = bias[c];
    const float* p = in + base;
    float v[16];
    float sum = 0.f, sq = 0.f;
#pragma unroll
    for (int i = 0; i < 16; i++) {
        int off = threadIdx.x + i * 256;
        float acc = bv + p[off];
        if (NPART >= 2) acc += p[pstride + off];
        if (NPART >= 3) acc += p[2 * pstride + off];
        if (NPART >= 4) acc += p[3 * pstride + off];
        v[i] = acc;
        sum += acc; sq += acc * acc;
    }
    s1[threadIdx.x] = sum; s2[threadIdx.x] = sq;
    __syncthreads();
    for (int off = 128; off; off >>= 1) {
        if (threadIdx.x < off) {
            s1[threadIdx.x] += s1[threadIdx.x + off];
            s2[threadIdx.x] += s2[threadIdx.x + off];
        }
        __syncthreads();
    }
    float mean = s1[0] * (1.f / HW);
    float var  = s2[0] * (1.f / HW) - mean * mean;
    float rstd = rsqrtf(var + EPSV);
    float* o = out + base;
    const float* rr = resid ? resid + base : nullptr;
#pragma unroll
    for (int i = 0; i < 16; i++) {
        float xv = v[i];
        float lr = xv > 0.f ? xv : SLOPE * xv;
        float val = (xv - mean) * rstd + lr;
        if (rr) val += rr[threadIdx.x + i * 256];
        o[threadIdx.x + i * 256] = val;
    }
}

// ---------------- layernorm over channels, coalesced via smem transpose ----------
__global__ __launch_bounds__(256)
void layernorm_v2_kernel(const float* __restrict__ h, const float* __restrict__ g,
                         const float* __restrict__ beta, float* __restrict__ t)
{
    __shared__ float sv[DIM][33];
    __shared__ float ps[8][33], ps2[8][33];
    __shared__ float smean[32], srstd[32];
    const int tx = threadIdx.x & 31, ty = threadIdx.x >> 5;
    const int l0 = blockIdx.x * 32, b = blockIdx.y;
    const float* hb = h + (size_t)b * DIM * HW + l0;

    for (int c = ty; c < DIM; c += 8)
        sv[c][tx] = hb[(size_t)c * HW + tx];
    __syncthreads();

    float sum = 0.f, sq = 0.f;
#pragma unroll
    for (int i = 0; i < 16; i++) {
        float v = sv[ty * 16 + i][tx];
        sum += v; sq += v * v;
    }
    ps[ty][tx] = sum; ps2[ty][tx] = sq;
    __syncthreads();
    if (ty == 0) {
        float s = 0.f, s2 = 0.f;
#pragma unroll
        for (int w = 0; w < 8; w++) { s += ps[w][tx]; s2 += ps2[w][tx]; }
        float mean = s * (1.f / DIM);
        float var  = s2 * (1.f / DIM) - mean * mean;
        smean[tx] = mean;
        srstd[tx] = rsqrtf(var + EPSV);
    }
    __syncthreads();

#pragma unroll
    for (int cc = 0; cc < 4; cc++) {
        int c = tx + 32 * cc;
        float gv = g[c], bv = beta[c];
        for (int l = ty; l < 32; l += 8) {
            float m = smean[l], rs = srstd[l];
            t[((size_t)(b * LSEQ + l0 + l)) * DIM + c] = (sv[c][l] - m) * rs * gv + bv;
        }
    }
}

// ---------------- in_proj GEMM (software-pipelined loads) ------------------------
__global__ __launch_bounds__(256)
void gemm_inproj_kernel(const float* __restrict__ A, const float* __restrict__ Bw,
                        float* __restrict__ xrx, float* __restrict__ resT)
{
    __shared__ ull   As2[8][128];
    __shared__ float Bs[8][128];
    __shared__ float sT[32][129];
    const int tid = threadIdx.x;
    const int tm = tid >> 4, tn = tid & 15;
    const int m0 = blockIdx.x * 128, n0 = blockIdx.y * 128;
    const int K = DIM, N = 2 * DIN;
    ull acc[8][4];
#pragma unroll
    for (int i = 0; i < 8; i++)
#pragma unroll
        for (int j = 0; j < 4; j++) acc[i][j] = 0ull;
    const int ar = tid >> 1, ak = (tid & 1) * 4;
    const int bk = tid >> 5, bn = (tid & 31) * 4;
    float4 av = *(const float4*)(A + (size_t)(m0 + ar) * K + ak);
    float4 bv = *(const float4*)(Bw + (size_t)bk * N + n0 + bn);
    for (int k0 = 0; k0 < K; k0 += 8) {
        __syncthreads();
        As2[ak + 0][ar] = pack2(av.x, av.x);
        As2[ak + 1][ar] = pack2(av.y, av.y);
        As2[ak + 2][ar] = pack2(av.z, av.z);
        As2[ak + 3][ar] = pack2(av.w, av.w);
        *(float4*)&Bs[bk][bn] = bv;
        __syncthreads();
        if (k0 + 8 < K) {
            av = *(const float4*)(A + (size_t)(m0 + ar) * K + k0 + 8 + ak);
            bv = *(const float4*)(Bw + (size_t)(k0 + 8 + bk) * N + n0 + bn);
        }
#pragma unroll
        for (int k = 0; k < 8; k++) {
            ull a2[8], b2[4];
#pragma unroll
            for (int i = 0; i < 8; i++) a2[i] = As2[k][tm * 8 + i];
#pragma unroll
            for (int j = 0; j < 4; j++) b2[j] = *(const ull*)&Bs[k][tn * 2 + 32 * j];
#pragma unroll
            for (int i = 0; i < 8; i++)
#pragma unroll
                for (int j = 0; j < 4; j++)
                    acc[i][j] = ffma2(a2[i], b2[j], acc[i][j]);
        }
    }
    if (n0 < DIN) {
#pragma unroll
        for (int i = 0; i < 8; i++) {
            int row = m0 + tm * 8 + i;
#pragma unroll
            for (int j = 0; j < 4; j++) {
                float lo, hi; unpack2(acc[i][j], lo, hi);
                *(float2*)(xrx + (size_t)row * DIN + n0 + tn * 2 + 32 * j) = make_float2(lo, hi);
            }
        }
    } else {
        const int b = m0 >> 12, t0 = m0 & 4095, d0 = n0 - DIN;
#pragma unroll
        for (int j = 0; j < 4; j++) {
            __syncthreads();
#pragma unroll
            for (int i = 0; i < 8; i++) {
                int rl = tm * 8 + i;
                float lo, hi; unpack2(acc[i][j], lo, hi);
                sT[2 * tn][rl]     = lo;
                sT[2 * tn + 1][rl] = hi;
            }
            __syncthreads();
            int col = tid >> 3, r0 = (tid & 7) * 16;
            float* dst = resT + ((size_t)(b * DIN + d0 + 32 * j + col)) * LSEQ + t0 + r0;
#pragma unroll
            for (int k = 0; k < 16; k++) dst[k] = sT[col][r0 + k];
        }
    }
}

// ---------------- delta GEMM (software-pipelined loads) --------------------------
__global__ __launch_bounds__(256)
void gemm_delta_kernel(const float* __restrict__ A, const float* __restrict__ Bw,
                       const float* __restrict__ dtb, float* __restrict__ deltaT)
{
    __shared__ ull   As2[8][128];
    __shared__ float Bs[8][128];
    __shared__ float sT[32][129];
    const int tid = threadIdx.x;
    const int tm = tid >> 4, tn = tid & 15;
    const int m0 = blockIdx.x * 128, n0 = blockIdx.y * 128;
    const int K = DIN, N = DIN;
    ull acc[8][4];
#pragma unroll
    for (int i = 0; i < 8; i++)
#pragma unroll
        for (int j = 0; j < 4; j++) acc[i][j] = 0ull;
    const int ar = tid >> 1, ak = (tid & 1) * 4;
    const int bk = tid >> 5, bn = (tid & 31) * 4;
    float4 av = *(const float4*)(A + (size_t)(m0 + ar) * K + ak);
    float4 bv = *(const float4*)(Bw + (size_t)bk * N + n0 + bn);
    for (int k0 = 0; k0 < K; k0 += 8) {
        __syncthreads();
        As2[ak + 0][ar] = pack2(av.x, av.x);
        As2[ak + 1][ar] = pack2(av.y, av.y);
        As2[ak + 2][ar] = pack2(av.z, av.z);
        As2[ak + 3][ar] = pack2(av.w, av.w);
        *(float4*)&Bs[bk][bn] = bv;
        __syncthreads();
        if (k0 + 8 < K) {
            av = *(const float4*)(A + (size_t)(m0 + ar) * K + k0 + 8 + ak);
            bv = *(const float4*)(Bw + (size_t)(k0 + 8 + bk) * N + n0 + bn);
        }
#pragma unroll
        for (int k = 0; k < 8; k++) {
            ull a2[8], b2[4];
#pragma unroll
            for (int i = 0; i < 8; i++) a2[i] = As2[k][tm * 8 + i];
#pragma unroll
            for (int j = 0; j < 4; j++) b2[j] = *(const ull*)&Bs[k][tn * 2 + 32 * j];
#pragma unroll
            for (int i = 0; i < 8; i++)
#pragma unroll
                for (int j = 0; j < 4; j++)
                    acc[i][j] = ffma2(a2[i], b2[j], acc[i][j]);
        }
    }
    const int b = m0 >> 12, t0 = m0 & 4095;
#pragma unroll
    for (int j = 0; j < 4; j++) {
        __syncthreads();
        float blo = dtb[n0 + 32 * j + 2 * tn];
        float bhi = dtb[n0 + 32 * j + 2 * tn + 1];
#pragma unroll
        for (int i = 0; i < 8; i++) {
            int rl = tm * 8 + i;
            float lo, hi; unpack2(acc[i][j], lo, hi);
            sT[2 * tn][rl]     = softplus_f(lo + blo);
            sT[2 * tn + 1][rl] = softplus_f(hi + bhi);
        }
        __syncthreads();
        int col = tid >> 3, r0 = (tid & 7) * 16;
        float* dst = deltaT + ((size_t)(b * DIN + n0 + 32 * j + col)) * LSEQ + t0 + r0;
#pragma unroll
        for (int k = 0; k < 16; k++) dst[k] = sT[col][r0 + k];
    }
}

// ---------------- BC GEMM: M-tile 64, software-pipelined -------------------------
__global__ __launch_bounds__(256)
void gemm_bc_kernel(const float* __restrict__ A, const float* __restrict__ xw,
                    float* __restrict__ bc)
{
    __shared__ ull   As2[16][64];
    __shared__ float Bs[16][32];
    const int tid = threadIdx.x;
    const int tm = tid >> 4, tn = tid & 15;
    const int m0 = blockIdx.x * 64;
    ull acc[4];
#pragma unroll
    for (int i = 0; i < 4; i++) acc[i] = 0ull;
    const int ar = tid >> 2, aq = (tid & 3) * 4;
    float4 a1 = *(const float4*)(A + (size_t)(m0 + ar) * DIN + aq);
    float bvv[2];
#pragma unroll
    for (int q = 0; q < 2; q++) {
        int idx = tid + q * 256;
        bvv[q] = xw[(size_t)(idx >> 5) * 40 + 8 + (idx & 31)];
    }
    for (int k0 = 0; k0 < DIN; k0 += 16) {
        __syncthreads();
        As2[aq + 0][ar] = pack2(a1.x, a1.x);
        As2[aq + 1][ar] = pack2(a1.y, a1.y);
        As2[aq + 2][ar] = pack2(a1.z, a1.z);
        As2[aq + 3][ar] = pack2(a1.w, a1.w);
#pragma unroll
        for (int q = 0; q < 2; q++) {
            int idx = tid + q * 256;
            Bs[idx >> 5][idx & 31] = bvv[q];
        }
        __syncthreads();
        if (k0 + 16 < DIN) {
            a1 = *(const float4*)(A + (size_t)(m0 + ar) * DIN + k0 + 16 + aq);
#pragma unroll
            for (int q = 0; q < 2; q++) {
                int idx = tid + q * 256;
                bvv[q] = xw[(size_t)(k0 + 16 + (idx >> 5)) * 40 + 8 + (idx & 31)];
            }
        }
#pragma unroll
        for (int k = 0; k < 16; k++) {
            ull b2 = *(const ull*)&Bs[k][2 * tn];
#pragma unroll
            for (int i = 0; i < 4; i++)
                acc[i] = ffma2(As2[k][tm * 4 + i], b2, acc[i]);
        }
    }
#pragma unroll
    for (int i = 0; i < 4; i++) {
        int row = m0 + tm * 4 + i;
        float lo, hi; unpack2(acc[i], lo, hi);
        *(float2*)(bc + (size_t)row * 32 + 2 * tn) = make_float2(lo, hi);
    }
}

// ---------------- out_proj GEMM: M-tile 64, software-pipelined -------------------
__global__ __launch_bounds__(256)
void gemm_out_kernel(const float* __restrict__ gatedT, const float* __restrict__ Bw,
                     float* __restrict__ out)
{
    __shared__ ull   As2[8][64];
    __shared__ float Bs[8][128];
    __shared__ float sT[32][65];
    const int tid = threadIdx.x;
    const int tm = tid >> 4, tn = tid & 15;
    const int m0 = blockIdx.x * 64;
    const int K = DIN, N = DIM;
    const int b = m0 >> 12, t0 = m0 & 4095;
    ull acc[4][4];
#pragma unroll
    for (int i = 0; i < 4; i++)
#pragma unroll
        for (int j = 0; j < 4; j++) acc[i][j] = 0ull;
    const int kk = tid >> 5, tl = tid & 31;
    const int bk = tid >> 5, bn = (tid & 31) * 4;
    float gv[2];
#pragma unroll
    for (int it = 0; it < 2; it++)
        gv[it] = gatedT[((size_t)(b * DIN + kk)) * LSEQ + t0 + tl + 32 * it];
    float4 bv = *(const float4*)(Bw + (size_t)bk * N + bn);
    for (int k0 = 0; k0 < K; k0 += 8) {
        __syncthreads();
#pragma unroll
        for (int it = 0; it < 2; it++)
            As2[kk][tl + 32 * it] = pack2(gv[it], gv[it]);
        *(float4*)&Bs[bk][bn] = bv;
        __syncthreads();
        if (k0 + 8 < K) {
            int d = k0 + 8 + kk;
#pragma unroll
            for (int it = 0; it < 2; it++)
                gv[it] = gatedT[((size_t)(b * DIN + d)) * LSEQ + t0 + tl + 32 * it];
            bv = *(const float4*)(Bw + (size_t)(k0 + 8 + bk) * N + bn);
        }
#pragma unroll
        for (int k = 0; k < 8; k++) {
            ull a2[4], b2[4];
#pragma unroll
            for (int i = 0; i < 4; i++) a2[i] = As2[k][tm * 4 + i];
#pragma unroll
            for (int j = 0; j < 4; j++) b2[j] = *(const ull*)&Bs[k][tn * 2 + 32 * j];
#pragma unroll
            for (int i = 0; i < 4; i++)
#pragma unroll
                for (int j = 0; j < 4; j++)
                    acc[i][j] = ffma2(a2[i], b2[j], acc[i][j]);
        }
    }
#pragma unroll
    for (int j = 0; j < 4; j++) {
        __syncthreads();
#pragma unroll
        for (int i = 0; i < 4; i++) {
            int rl = tm * 4 + i;
            float lo, hi; unpack2(acc[i][j], lo, hi);
            sT[2 * tn][rl]     = lo;
            sT[2 * tn + 1][rl] = hi;
        }
        __syncthreads();
        int col = tid >> 3, r0 = (tid & 7) * 8;
        float* dst = out + ((size_t)(b * DIM + 32 * j + col)) * LSEQ + t0 + r0;
#pragma unroll
        for (int k = 0; k < 8; k++) dst[k] = sT[col][r0 + k];
    }
}

// ---------------- causal depthwise conv1d (k=4) + silu, dual-layout output ------
__global__ __launch_bounds__(256)
void conv1d_silu_T_kernel(const float* __restrict__ xrx, const float4* __restrict__ wp,
                          const float* __restrict__ bias,
                          float* __restrict__ xs, float* __restrict__ xsT)
{
    __shared__ float st[32][33];
    const int tx = threadIdx.x & 31, ty = threadIdx.x >> 5;
    const int t0 = blockIdx.x * 32, d0 = blockIdx.y * 32, b = blockIdx.z;
    const int d = d0 + tx;
    float4 w = wp[d];
    float bv = bias[d];
    const float* xb = xrx + (size_t)b * LSEQ * DIN + d;
#pragma unroll
    for (int k = 0; k < 4; k++) {
        int t = t0 + ty + 8 * k;
        float acc = bv;
        if (t - 3 >= 0) acc = fmaf(w.x, xb[(size_t)(t - 3) * DIN], acc);
        if (t - 2 >= 0) acc = fmaf(w.y, xb[(size_t)(t - 2) * DIN], acc);
        if (t - 1 >= 0) acc = fmaf(w.z, xb[(size_t)(t - 1) * DIN], acc);
        acc = fmaf(w.w, xb[(size_t)t * DIN], acc);
        float s = acc / (1.f + __expf(-acc));
        xs[((size_t)b * LSEQ + t) * DIN + d] = s;
        st[tx][ty + 8 * k] = s;
    }
    __syncthreads();
#pragma unroll
    for (int k = 0; k < 4; k++) {
        int dd = d0 + ty + 8 * k;
        xsT[((size_t)(b * DIN + dd)) * LSEQ + t0 + tx] = st[ty + 8 * k][tx];
    }
}

// ---------------- scan pass 1 (R8 form) ----------------
__global__ __launch_bounds__(256)
void scan_p1_kernel(const float* __restrict__ deltaT, const float* __restrict__ xsT,
                    const float* __restrict__ bc, const float* __restrict__ negA,
                    float* __restrict__ chA, float* __restrict__ chH)
{
    int gw = (blockIdx.x * blockDim.x + threadIdx.x) >> 5;
    int lane = threadIdx.x & 31;
    int half = lane >> 4, n = lane & 15;
    int chunk = gw >> 9;
    int wp = gw & 511;
    int pair = wp * 2 + half;
    int b = pair >> 8, d = pair & 255;
    int t0 = chunk * CHLEN;

    float A = negA[d * DSTATE + n];
    const float* dl = deltaT + (size_t)(b * DIN + d) * LSEQ + t0;
    const float* ul = xsT    + (size_t)(b * DIN + d) * LSEQ + t0;
    const float* xb = bc + ((size_t)b * LSEQ + t0) * 32;

    float h = 0.f, pA = 1.f;
    for (int t = 0; t < CHLEN; t++) {
        float dt  = dl[t];
        float ut  = ul[t];
        float Bn  = xb[t * 32 + n];
        float a = __expf(dt * A);
        pA *= a;
        h = fmaf(a, h, dt * ut * Bn);
    }
    int idx = (chunk * NPAIR + pair) * DSTATE + n;
    chA[idx] = pA;
    chH[idx] = h;
}

// ---------------- scan pass 2 ----------------
__global__ __launch_bounds__(256)
void scan_p2_kernel(const float* __restrict__ chA, const float* __restrict__ chH,
                    float* __restrict__ hst)
{
    int i = blockIdx.x * 256 + threadIdx.x;
    float h = 0.f;
    hst[i] = 0.f;
#pragma unroll
    for (int c = 0; c < NCH - 1; c++) {
        h = fmaf(chA[c * NPAIR * DSTATE + i], h, chH[c * NPAIR * DSTATE + i]);
        hst[(c + 1) * NPAIR * DSTATE + i] = h;
    }
}

// ---------------- scan pass 3 (R8 form, + fused gate) ----------------
__global__ __launch_bounds__(256)
void scan_p3_kernel(const float* __restrict__ deltaT, const float* __restrict__ xsT,
                    const float* __restrict__ bc, const float* __restrict__ negA,
                    const float* __restrict__ Dp, const float* __restrict__ hst,
                    const float* __restrict__ resT, float* __restrict__ gatedT)
{
    __shared__ float sy[8][2][32];
    int gw = (blockIdx.x * blockDim.x + threadIdx.x) >> 5;
    int lane = threadIdx.x & 31;
    int wslot = threadIdx.x >> 5;
    int half = lane >> 4, n = lane & 15;
    int chunk = gw >> 9;
    int wp = gw & 511;
    int pair = wp * 2 + half;
    int b = pair >> 8, d = pair & 255;
    int t0 = chunk * CHLEN;

    float A = negA[d * DSTATE + n];
    const float* dl = deltaT + (size_t)(b * DIN + d) * LSEQ + t0;
    const float* ul = xsT    + (size_t)(b * DIN + d) * LSEQ + t0;
    const float* xb = bc + ((size_t)b * LSEQ + t0) * 32;
    float h = hst[(chunk * NPAIR + pair) * DSTATE + n];

    int dp0 = (wp * 2) & 255;
    int bb  = (wp * 2) >> 8;
    float Dv0 = Dp[dp0], Dv1 = Dp[dp0 + 1];
    const float* u0p = xsT + (size_t)(bb * DIN + dp0)     * LSEQ + t0;
    const float* u1p = xsT + (size_t)(bb * DIN + dp0 + 1) * LSEQ + t0;
    const float* r0p = resT + (size_t)(bb * DIN + dp0)     * LSEQ + t0;
    const float* r1p = resT + (size_t)(bb * DIN + dp0 + 1) * LSEQ + t0;
    float* y0p = gatedT + (size_t)(bb * DIN + dp0)     * LSEQ + t0;
    float* y1p = gatedT + (size_t)(bb * DIN + dp0 + 1) * LSEQ + t0;

    for (int t = 0; t < CHLEN; t++) {
        float dt  = dl[t];
        float ut  = ul[t];
        float Bn  = xb[t * 32 + n];
        float Cn  = xb[t * 32 + 16 + n];
        float a = __expf(dt * A);
        h = fmaf(a, h, dt * ut * Bn);
        float yv = h * Cn;
        yv += __shfl_xor_sync(0xffffffffu, yv, 8);
        yv += __shfl_xor_sync(0xffffffffu, yv, 4);
        yv += __shfl_xor_sync(0xffffffffu, yv, 2);
        yv += __shfl_xor_sync(0xffffffffu, yv, 1);
        if (n == 0) sy[wslot][half][t & 31] = yv;
        if ((t & 31) == 31) {
            __syncwarp();
            int tb = t & ~31;
            float r0 = r0p[tb + lane];
            float r1 = r1p[tb + lane];
            float s0 = r0 / (1.f + __expf(-r0));
            float s1 = r1 / (1.f + __expf(-r1));
            y0p[tb + lane] = fmaf(u0p[tb + lane], Dv0, sy[wslot][0][lane]) * s0;
            y1p[tb + lane] = fmaf(u1p[tb + lane], Dv1, sy[wslot][1][lane]) * s1;
            __syncwarp();
        }
    }
}

// ---------------- launch ----------------
extern "C" void kernel_launch(void* const* d_in, const int* in_sizes, int n_in,
                              void* d_out, int out_size)
{
    const float* x         = (const float*)d_in[0];
    const float* conv1_w   = (const float*)d_in[1];
    const float* conv1_b   = (const float*)d_in[2];
    const float* conv2_w   = (const float*)d_in[3];
    const float* conv2_b   = (const float*)d_in[4];
    const float* ln_g      = (const float*)d_in[5];
    const float* ln_b      = (const float*)d_in[6];
    const float* in_proj_w = (const float*)d_in[7];
    const float* conv1d_w  = (const float*)d_in[8];
    const float* conv1d_b  = (const float*)d_in[9];
    const float* x_proj_w  = (const float*)d_in[10];
    const float* dt_proj_w = (const float*)d_in[11];
    const float* dt_proj_b = (const float*)d_in[12];
    const float* A_log     = (const float*)d_in[13];
    const float* Dp        = (const float*)d_in[14];
    const float* out_proj_w= (const float*)d_in[15];
    float* out = (float*)d_out;

    Scratch* s = nullptr;
    cudaGetSymbolAddress((void**)&s, g_scratch);

    const size_t p1stride = (size_t)BATCH * DIN * HW;
    const size_t p2stride = (size_t)BATCH * DIM * HW;

    // 0-2) precompute (conv1 stays at profiled slot 3)
    negA_wpack_kernel<<<17, 256>>>(A_log, s->negA, conv1d_w, s->wpack);
    weff_kernel<<<DIN, DIN>>>(x_proj_w, dt_proj_w, s->weff);
    wdup_kernel<<<(W1ELEMS + W2ELEMS + 255) / 256, 256>>>(conv1_w, conv2_w, s->wd1, s->wd2);
    // 3) conv1 split-K x2 (R8 exact)
    conv3x3_v8_kernel<DIM, DIN, 2><<<dim3(2, 1, BATCH * (DIN / 8) * 2), 256>>>(
        x, s->wd1, s->h1);
    // 4) inorm (sums 2 partials + bias) + leaky
    inorm_lrelu_kernel<2><<<BATCH * DIN, 256>>>(s->h1, p1stride, conv1_b, DIN, s->h1, nullptr);
    // 5) conv2 split-K x4 (R8 exact)
    conv3x3_v8_kernel<DIN, DIM, 4><<<dim3(2, 1, BATCH * (DIM / 8) * 4), 256>>>(
        s->h1, s->wd2, s->h2);
    // 6) inorm (sums 4 partials + bias) + leaky + residual
    inorm_lrelu_kernel<4><<<BATCH * DIM, 256>>>(s->h2, p2stride, conv2_b, DIM, s->h2, x);
    // 7) layernorm (coalesced) + transpose to (b*l, c)
    layernorm_v2_kernel<<<dim3(HW / 32, BATCH), 256>>>(s->h2, ln_g, ln_b, s->t);
    // 8) in_proj GEMM (xs rows + res transposed)
    gemm_inproj_kernel<<<dim3(BATCH * LSEQ / 128, 4), 256>>>(
        s->t, in_proj_w, s->xrx, s->resT);
    // 9) depthwise conv1d + silu
    conv1d_silu_T_kernel<<<dim3(LSEQ / 32, DIN / 32, BATCH), 256>>>(
        s->xrx, s->wpack, conv1d_b, s->xs, s->xsT);
    // 10) delta GEMM (softplus + transpose)
    gemm_delta_kernel<<<dim3(BATCH * LSEQ / 128, 2), 256>>>(
        s->xs, s->weff, dt_proj_b, s->deltaT);
    // 11) B/C GEMM (M-tile 64 -> 256 blocks)
    gemm_bc_kernel<<<BATCH * LSEQ / 64, 256>>>(s->xs, x_proj_w, s->bc);
    // 12) chunked selective scan (R8 exact)
    scan_p1_kernel<<<(NCH - 1) * 64, 256>>>(
        s->deltaT, s->xsT, s->bc, s->negA, s->chA, s->chH);
    scan_p2_kernel<<<NPAIR * DSTATE / 256, 256>>>(s->chA, s->chH, s->hst);
    scan_p3_kernel<<<NCH * 64, 256>>>(
        s->deltaT, s->xsT, s->bc, s->negA, Dp, s->hst, s->resT, s->gatedT);
    // 13) out_proj GEMM (M-tile 64 -> 256 blocks) + NCHW store
    gemm_out_kernel<<<BATCH * LSEQ / 64, 256>>>(s->gatedT, out_proj_w, out);
}

// round 12
// speedup vs baseline: 1.1925x; 1.0470x over previous
#include <cuda_runtime.h>
#include <cuda_bf16.h>
#include <cstdint>
#include <cstddef>

#define BATCH 4
#define DIM   128
#define DIN   256
#define HH    64
#define WW    64
#define HW    4096
#define LSEQ  4096
#define DSTATE 16
#define DTRANK 8
#define EPSV  1e-5f
#define SLOPE 0.01f

#define NCH   4
#define CHLEN (LSEQ/NCH)
#define NPAIR (BATCH*DIN)

typedef unsigned long long ull;

__device__ __forceinline__ ull pack2(float lo, float hi) {
    ull r; asm("mov.b64 %0, {%1, %2};" : "=l"(r) : "f"(lo), "f"(hi)); return r;
}
__device__ __forceinline__ void unpack2(ull p, float& lo, float& hi) {
    asm("mov.b64 {%0, %1}, %2;" : "=f"(lo), "=f"(hi) : "l"(p));
}
__device__ __forceinline__ ull ffma2(ull a, ull b, ull c) {
    ull d; asm("fma.rn.f32x2 %0, %1, %2, %3;" : "=l"(d) : "l"(a), "l"(b), "l"(c)); return d;
}
__device__ __forceinline__ float softplus_f(float x) {
    return (x > 20.f) ? x : log1pf(expf(x));
}
__device__ __forceinline__ uint32_t saddr(const void* p) {
    return (uint32_t)__cvta_generic_to_shared(p);
}
__device__ __forceinline__ void cpa4(uint32_t dst, const void* src) {
    asm volatile("cp.async.ca.shared.global [%0], [%1], 4;" :: "r"(dst), "l"(src));
}
__device__ __forceinline__ void cpa16(uint32_t dst, const void* src) {
    asm volatile("cp.async.cg.shared.global [%0], [%1], 16;" :: "r"(dst), "l"(src));
}

#define W1ELEMS (DIM * 9 * DIN)
#define W2ELEMS (DIN * 9 * DIM)

// ---------------- scratch ----------------
struct Scratch {
    float h1[2 * BATCH * DIN * HW];
    float h2[4 * BATCH * DIM * HW];
    float t [BATCH * LSEQ * DIM];
    float xrx[BATCH * LSEQ * DIN];
    float resT[NPAIR * LSEQ];
    float xs[BATCH * LSEQ * DIN];
    float xsT[NPAIR * LSEQ];
    float deltaT[NPAIR * LSEQ];
    float gatedT[NPAIR * LSEQ];
    float bc[BATCH * LSEQ * 2*DSTATE];
    float weff[DIN * DIN];
    float negA[DIN * DSTATE];
    float4 wpack[DIN];
    float wd1[W1ELEMS];                 // conv1 weights (plain): [ci][tap][oc]
    float wd2[W2ELEMS];                 // conv2 weights (plain): [ci][tap][oc]
    float chA[(NCH-1) * NPAIR * DSTATE];
    float chH[(NCH-1) * NPAIR * DSTATE];
    float hst[NCH * NPAIR * DSTATE];
};
__device__ Scratch g_scratch;

// ---------------- precompute kernels (3 launches; conv1 stays at slot 3) ---------
__global__ void negA_wpack_kernel(const float* __restrict__ A_log, float* __restrict__ negA,
                                  const float* __restrict__ w1d, float4* __restrict__ wp)
{
    if (blockIdx.x < 16) {
        int i = blockIdx.x * 256 + threadIdx.x;
        negA[i] = -expf(A_log[i]);
    } else {
        int d = threadIdx.x;
        wp[d] = make_float4(w1d[4*d], w1d[4*d+1], w1d[4*d+2], w1d[4*d+3]);
    }
}
__global__ __launch_bounds__(256)
void weff_kernel(const float* __restrict__ xw, const float* __restrict__ dtw,
                 float* __restrict__ weff)
{
    int k = blockIdx.x, d = threadIdx.x;
    float acc = 0.f;
#pragma unroll
    for (int r = 0; r < DTRANK; r++)
        acc = fmaf(xw[k * 40 + r], dtw[r * DIN + d], acc);
    weff[k * DIN + d] = acc;
}
__global__ __launch_bounds__(256)
void wdup_kernel(const float* __restrict__ w1, const float* __restrict__ w2,
                 float* __restrict__ wd1, float* __restrict__ wd2)
{
    int i = blockIdx.x * 256 + threadIdx.x;
    if (i < W1ELEMS) {
        int oc = i % DIN; int rest = i / DIN;
        int tap = rest % 9; int ci = rest / 9;
        wd1[i] = w1[((size_t)oc * DIM + ci) * 9 + tap];
    } else if (i < W1ELEMS + W2ELEMS) {
        int j = i - W1ELEMS;
        int oc = j % DIM; int rest = j / DIM;
        int tap = rest % 9; int ci = rest / 9;
        wd2[j] = w2[((size_t)oc * DIN + ci) * 9 + tap];
    }
}

// ---------------- conv v10: v8 + register-side weight duplication ----------------
// Weights stored plain (float[oc]); 2 LDS.128/tap instead of 4; duplication via
// pack2 on the alu pipe. Halves weight crossbar phases: 108 -> 90 per warp-ci.
template<int CIN, int COUT, int SPLIT>
__global__ __launch_bounds__(256, 2)
void conv3x3_v10_kernel(const float* __restrict__ x, const float* __restrict__ wd,
                        float* __restrict__ out)
{
    constexpr int OCPB = 8, CIC = 2, CSPAN = CIN / SPLIT;
    constexpr int NCHUNK = CSPAN / CIC;
    __shared__ float4 sx4[2][CIC * 18 * 36];
    __shared__ float4 swt[2][CIC * 9 * 2];     // [rowi][q] = oc 4q..4q+3 plain

    const int tid = threadIdx.x;
    const int tx = tid & 31, ty = tid >> 5;
    const int bx0 = blockIdx.x * 32;
    const int bz = blockIdx.z;
    constexpr int OCB = COUT / OCPB;
    const int b    = bz / (OCB * SPLIT);
    const int r    = bz % (OCB * SPLIT);
    const int oc0  = (r / SPLIT) * OCPB;
    const int part = r % SPLIT;
    const int cbase = part * CSPAN;
    const float* xb = x + (size_t)b * CIN * HW;
    float* out_part = out + (size_t)part * BATCH * COUT * HW;

    for (int i = tid; i < 2 * CIC * 18 * 36; i += 256)
        ((float4*)sx4)[i] = make_float4(0.f, 0.f, 0.f, 0.f);
    __syncthreads();

    auto load_chunk = [&](int buf, int c0) {
        for (int rr = ty; rr < CIC * 18; rr += 8) {
            int ci = (rr >= 18) ? 1 : 0;
            int p  = rr - 18 * ci;
            int gr = p - 1;
#pragma unroll
            for (int s = 0; s < 2; s++) {
                int xx = tx + 32 * s;
                if (xx < 34) {
                    int gx = bx0 + xx - 1;
                    if ((unsigned)gx < (unsigned)WW) {
                        const float* pc = xb + (size_t)(cbase + c0 + ci) * HW + gx;
                        uint32_t dst = saddr(&sx4[buf][rr * 36 + xx]);
                        if (p > 0)  cpa4(dst + 0,  pc + (size_t)gr * WW);
                        cpa4(dst + 4,  pc + (size_t)(gr + 16) * WW);
                        cpa4(dst + 8,  pc + (size_t)(gr + 32) * WW);
                        if (p < 17) cpa4(dst + 12, pc + (size_t)(gr + 48) * WW);
                    }
                }
            }
        }
        if (tid < CIC * 9 * 2) {
            int q = tid & 1;
            int rowi = tid >> 1;                   // 0..17 = ci*9+tap
            int ci = (rowi >= 9) ? 1 : 0;
            int tap = rowi - 9 * ci;
            const float* src = wd + ((size_t)(cbase + c0 + ci) * 9 + tap) * COUT + oc0 + 4 * q;
            cpa16(saddr(&swt[buf][rowi * 2 + q]), src);
        }
    };

    ull acc[OCPB][4];
#pragma unroll
    for (int i = 0; i < OCPB; i++)
#pragma unroll
        for (int q = 0; q < 4; q++) acc[i][q] = 0ull;

    load_chunk(0, 0);
    asm volatile("cp.async.commit_group;");

    for (int ch = 0; ch < NCHUNK; ch++) {
        const int cur = ch & 1;
        if (ch + 1 < NCHUNK) {
            load_chunk(cur ^ 1, (ch + 1) * CIC);
            asm volatile("cp.async.commit_group;");
            asm volatile("cp.async.wait_group 1;");
        } else {
            asm volatile("cp.async.wait_group 0;");
        }
        __syncthreads();

        const float4* sxb = sx4[cur];
        const float4* swb = swt[cur];
#pragma unroll
        for (int ci = 0; ci < CIC; ci++) {
#pragma unroll
            for (int tap = 0; tap < 9; tap++) {
                const int ti = tap / 3, tj = tap % 3;
                ulonglong2 A = *(const ulonglong2*)&sxb[(ci * 18 + ty + ti) * 36 + tx + tj];
                ulonglong2 C = *(const ulonglong2*)&sxb[(ci * 18 + ty + 8 + ti) * 36 + tx + tj];
                float4 wa = swb[(ci * 9 + tap) * 2 + 0];
                {
                    ull w0 = pack2(wa.x, wa.x), w1 = pack2(wa.y, wa.y);
                    ull w2 = pack2(wa.z, wa.z), w3 = pack2(wa.w, wa.w);
                    acc[0][0] = ffma2(A.x, w0, acc[0][0]); acc[0][1] = ffma2(A.y, w0, acc[0][1]);
                    acc[0][2] = ffma2(C.x, w0, acc[0][2]); acc[0][3] = ffma2(C.y, w0, acc[0][3]);
                    acc[1][0] = ffma2(A.x, w1, acc[1][0]); acc[1][1] = ffma2(A.y, w1, acc[1][1]);
                    acc[1][2] = ffma2(C.x, w1, acc[1][2]); acc[1][3] = ffma2(C.y, w1, acc[1][3]);
                    acc[2][0] = ffma2(A.x, w2, acc[2][0]); acc[2][1] = ffma2(A.y, w2, acc[2][1]);
                    acc[2][2] = ffma2(C.x, w2, acc[2][2]); acc[2][3] = ffma2(C.y, w2, acc[2][3]);
                    acc[3][0] = ffma2(A.x, w3, acc[3][0]); acc[3][1] = ffma2(A.y, w3, acc[3][1]);
                    acc[3][2] = ffma2(C.x, w3, acc[3][2]); acc[3][3] = ffma2(C.y, w3, acc[3][3]);
                }
                float4 wb = swb[(ci * 9 + tap) * 2 + 1];
                {
                    ull w4 = pack2(wb.x, wb.x), w5 = pack2(wb.y, wb.y);
                    ull w6 = pack2(wb.z, wb.z), w7 = pack2(wb.w, wb.w);
                    acc[4][0] = ffma2(A.x, w4, acc[4][0]); acc[4][1] = ffma2(A.y, w4, acc[4][1]);
                    acc[4][2] = ffma2(C.x, w4, acc[4][2]); acc[4][3] = ffma2(C.y, w4, acc[4][3]);
                    acc[5][0] = ffma2(A.x, w5, acc[5][0]); acc[5][1] = ffma2(A.y, w5, acc[5][1]);
                    acc[5][2] = ffma2(C.x, w5, acc[5][2]); acc[5][3] = ffma2(C.y, w5, acc[5][3]);
                    acc[6][0] = ffma2(A.x, w6, acc[6][0]); acc[6][1] = ffma2(A.y, w6, acc[6][1]);
                    acc[6][2] = ffma2(C.x, w6, acc[6][2]); acc[6][3] = ffma2(C.y, w6, acc[6][3]);
                    acc[7][0] = ffma2(A.x, w7, acc[7][0]); acc[7][1] = ffma2(A.y, w7, acc[7][1]);
                    acc[7][2] = ffma2(C.x, w7, acc[7][2]); acc[7][3] = ffma2(C.y, w7, acc[7][3]);
                }
            }
        }
        __syncthreads();
    }

    float* ob = out_part + (size_t)b * COUT * HW;
#pragma unroll
    for (int oc = 0; oc < OCPB; oc++) {
        float r0, r16, r32, r48, r8, r24, r40, r56;
        unpack2(acc[oc][0], r0,  r16);
        unpack2(acc[oc][1], r32, r48);
        unpack2(acc[oc][2], r8,  r24);
        unpack2(acc[oc][3], r40, r56);
        size_t base = ((size_t)(oc0 + oc) * HH) * WW + bx0 + tx;
        ob[base + (size_t)(ty)      * WW] = r0;
        ob[base + (size_t)(ty + 8)  * WW] = r8;
        ob[base + (size_t)(ty + 16) * WW] = r16;
        ob[base + (size_t)(ty + 24) * WW] = r24;
        ob[base + (size_t)(ty + 32) * WW] = r32;
        ob[base + (size_t)(ty + 40) * WW] = r40;
        ob[base + (size_t)(ty + 48) * WW] = r48;
        ob[base + (size_t)(ty + 56) * WW] = r56;
    }
}

// ---------------- instance norm + leaky, sums NPART split-K partials + bias -------
template<int NPART>
__global__ __launch_bounds__(256)
void inorm_lrelu_kernel(const float* __restrict__ in, size_t pstride,
                        const float* __restrict__ bias, int C,
                        float* __restrict__ out, const float* __restrict__ resid)
{
    __shared__ float s1[256], s2[256];
    const size_t base = (size_t)blockIdx.x * HW;
    const int c = blockIdx.x % C;
    const float bv = bias[c];
    const float* p = in + base;
    float v[16];
    float sum = 0.f, sq = 0.f;
#pragma unroll
    for (int i = 0; i < 16; i++) {
        int off = threadIdx.x + i * 256;
        float acc = bv + p[off];
        if (NPART >= 2) acc += p[pstride + off];
        if (NPART >= 3) acc += p[2 * pstride + off];
        if (NPART >= 4) acc += p[3 * pstride + off];
        v[i] = acc;
        sum += acc; sq += acc * acc;
    }
    s1[threadIdx.x] = sum; s2[threadIdx.x] = sq;
    __syncthreads();
    for (int off = 128; off; off >>= 1) {
        if (threadIdx.x < off) {
            s1[threadIdx.x] += s1[threadIdx.x + off];
            s2[threadIdx.x] += s2[threadIdx.x + off];
        }
        __syncthreads();
    }
    float mean = s1[0] * (1.f / HW);
    float var  = s2[0] * (1.f / HW) - mean * mean;
    float rstd = rsqrtf(var + EPSV);
    float* o = out + base;
    const float* rr = resid ? resid + base : nullptr;
#pragma unroll
    for (int i = 0; i < 16; i++) {
        float xv = v[i];
        float lr = xv > 0.f ? xv : SLOPE * xv;
        float val = (xv - mean) * rstd + lr;
        if (rr) val += rr[threadIdx.x + i * 256];
        o[threadIdx.x + i * 256] = val;
    }
}

// ---------------- layernorm over channels, coalesced via smem transpose ----------
__global__ __launch_bounds__(256)
void layernorm_v2_kernel(const float* __restrict__ h, const float* __restrict__ g,
                         const float* __restrict__ beta, float* __restrict__ t)
{
    __shared__ float sv[DIM][33];
    __shared__ float ps[8][33], ps2[8][33];
    __shared__ float smean[32], srstd[32];
    const int tx = threadIdx.x & 31, ty = threadIdx.x >> 5;
    const int l0 = blockIdx.x * 32, b = blockIdx.y;
    const float* hb = h + (size_t)b * DIM * HW + l0;

    for (int c = ty; c < DIM; c += 8)
        sv[c][tx] = hb[(size_t)c * HW + tx];
    __syncthreads();

    float sum = 0.f, sq = 0.f;
#pragma unroll
    for (int i = 0; i < 16; i++) {
        float v = sv[ty * 16 + i][tx];
        sum += v; sq += v * v;
    }
    ps[ty][tx] = sum; ps2[ty][tx] = sq;
    __syncthreads();
    if (ty == 0) {
        float s = 0.f, s2 = 0.f;
#pragma unroll
        for (int w = 0; w < 8; w++) { s += ps[w][tx]; s2 += ps2[w][tx]; }
        float mean = s * (1.f / DIM);
        float var  = s2 * (1.f / DIM) - mean * mean;
        smean[tx] = mean;
        srstd[tx] = rsqrtf(var + EPSV);
    }
    __syncthreads();

#pragma unroll
    for (int cc = 0; cc < 4; cc++) {
        int c = tx + 32 * cc;
        float gv = g[c], bv = beta[c];
        for (int l = ty; l < 32; l += 8) {
            float m = smean[l], rs = srstd[l];
            t[((size_t)(b * LSEQ + l0 + l)) * DIM + c] = (sv[c][l] - m) * rs * gv + bv;
        }
    }
}

// ---------------- in_proj GEMM (software-pipelined loads) ------------------------
__global__ __launch_bounds__(256)
void gemm_inproj_kernel(const float* __restrict__ A, const float* __restrict__ Bw,
                        float* __restrict__ xrx, float* __restrict__ resT)
{
    __shared__ ull   As2[8][128];
    __shared__ float Bs[8][128];
    __shared__ float sT[32][129];
    const int tid = threadIdx.x;
    const int tm = tid >> 4, tn = tid & 15;
    const int m0 = blockIdx.x * 128, n0 = blockIdx.y * 128;
    const int K = DIM, N = 2 * DIN;
    ull acc[8][4];
#pragma unroll
    for (int i = 0; i < 8; i++)
#pragma unroll
        for (int j = 0; j < 4; j++) acc[i][j] = 0ull;
    const int ar = tid >> 1, ak = (tid & 1) * 4;
    const int bk = tid >> 5, bn = (tid & 31) * 4;
    float4 av = *(const float4*)(A + (size_t)(m0 + ar) * K + ak);
    float4 bv = *(const float4*)(Bw + (size_t)bk * N + n0 + bn);
    for (int k0 = 0; k0 < K; k0 += 8) {
        __syncthreads();
        As2[ak + 0][ar] = pack2(av.x, av.x);
        As2[ak + 1][ar] = pack2(av.y, av.y);
        As2[ak + 2][ar] = pack2(av.z, av.z);
        As2[ak + 3][ar] = pack2(av.w, av.w);
        *(float4*)&Bs[bk][bn] = bv;
        __syncthreads();
        if (k0 + 8 < K) {
            av = *(const float4*)(A + (size_t)(m0 + ar) * K + k0 + 8 + ak);
            bv = *(const float4*)(Bw + (size_t)(k0 + 8 + bk) * N + n0 + bn);
        }
#pragma unroll
        for (int k = 0; k < 8; k++) {
            ull a2[8], b2[4];
#pragma unroll
            for (int i = 0; i < 8; i++) a2[i] = As2[k][tm * 8 + i];
#pragma unroll
            for (int j = 0; j < 4; j++) b2[j] = *(const ull*)&Bs[k][tn * 2 + 32 * j];
#pragma unroll
            for (int i = 0; i < 8; i++)
#pragma unroll
                for (int j = 0; j < 4; j++)
                    acc[i][j] = ffma2(a2[i], b2[j], acc[i][j]);
        }
    }
    if (n0 < DIN) {
#pragma unroll
        for (int i = 0; i < 8; i++) {
            int row = m0 + tm * 8 + i;
#pragma unroll
            for (int j = 0; j < 4; j++) {
                float lo, hi; unpack2(acc[i][j], lo, hi);
                *(float2*)(xrx + (size_t)row * DIN + n0 + tn * 2 + 32 * j) = make_float2(lo, hi);
            }
        }
    } else {
        const int b = m0 >> 12, t0 = m0 & 4095, d0 = n0 - DIN;
#pragma unroll
        for (int j = 0; j < 4; j++) {
            __syncthreads();
#pragma unroll
            for (int i = 0; i < 8; i++) {
                int rl = tm * 8 + i;
                float lo, hi; unpack2(acc[i][j], lo, hi);
                sT[2 * tn][rl]     = lo;
                sT[2 * tn + 1][rl] = hi;
            }
            __syncthreads();
            int col = tid >> 3, r0 = (tid & 7) * 16;
            float* dst = resT + ((size_t)(b * DIN + d0 + 32 * j + col)) * LSEQ + t0 + r0;
#pragma unroll
            for (int k = 0; k < 16; k++) dst[k] = sT[col][r0 + k];
        }
    }
}

// ---------------- delta GEMM (software-pipelined loads) --------------------------
__global__ __launch_bounds__(256)
void gemm_delta_kernel(const float* __restrict__ A, const float* __restrict__ Bw,
                       const float* __restrict__ dtb, float* __restrict__ deltaT)
{
    __shared__ ull   As2[8][128];
    __shared__ float Bs[8][128];
    __shared__ float sT[32][129];
    const int tid = threadIdx.x;
    const int tm = tid >> 4, tn = tid & 15;
    const int m0 = blockIdx.x * 128, n0 = blockIdx.y * 128;
    const int K = DIN, N = DIN;
    ull acc[8][4];
#pragma unroll
    for (int i = 0; i < 8; i++)
#pragma unroll
        for (int j = 0; j < 4; j++) acc[i][j] = 0ull;
    const int ar = tid >> 1, ak = (tid & 1) * 4;
    const int bk = tid >> 5, bn = (tid & 31) * 4;
    float4 av = *(const float4*)(A + (size_t)(m0 + ar) * K + ak);
    float4 bv = *(const float4*)(Bw + (size_t)bk * N + n0 + bn);
    for (int k0 = 0; k0 < K; k0 += 8) {
        __syncthreads();
        As2[ak + 0][ar] = pack2(av.x, av.x);
        As2[ak + 1][ar] = pack2(av.y, av.y);
        As2[ak + 2][ar] = pack2(av.z, av.z);
        As2[ak + 3][ar] = pack2(av.w, av.w);
        *(float4*)&Bs[bk][bn] = bv;
        __syncthreads();
        if (k0 + 8 < K) {
            av = *(const float4*)(A + (size_t)(m0 + ar) * K + k0 + 8 + ak);
            bv = *(const float4*)(Bw + (size_t)(k0 + 8 + bk) * N + n0 + bn);
        }
#pragma unroll
        for (int k = 0; k < 8; k++) {
            ull a2[8], b2[4];
#pragma unroll
            for (int i = 0; i < 8; i++) a2[i] = As2[k][tm * 8 + i];
#pragma unroll
            for (int j = 0; j < 4; j++) b2[j] = *(const ull*)&Bs[k][tn * 2 + 32 * j];
#pragma unroll
            for (int i = 0; i < 8; i++)
#pragma unroll
                for (int j = 0; j < 4; j++)
                    acc[i][j] = ffma2(a2[i], b2[j], acc[i][j]);
        }
    }
    const int b = m0 >> 12, t0 = m0 & 4095;
#pragma unroll
    for (int j = 0; j < 4; j++) {
        __syncthreads();
        float blo = dtb[n0 + 32 * j + 2 * tn];
        float bhi = dtb[n0 + 32 * j + 2 * tn + 1];
#pragma unroll
        for (int i = 0; i < 8; i++) {
            int rl = tm * 8 + i;
            float lo, hi; unpack2(acc[i][j], lo, hi);
            sT[2 * tn][rl]     = softplus_f(lo + blo);
            sT[2 * tn + 1][rl] = softplus_f(hi + bhi);
        }
        __syncthreads();
        int col = tid >> 3, r0 = (tid & 7) * 16;
        float* dst = deltaT + ((size_t)(b * DIN + n0 + 32 * j + col)) * LSEQ + t0 + r0;
#pragma unroll
        for (int k = 0; k < 16; k++) dst[k] = sT[col][r0 + k];
    }
}

// ---------------- BC GEMM: M-tile 64, software-pipelined -------------------------
__global__ __launch_bounds__(256)
void gemm_bc_kernel(const float* __restrict__ A, const float* __restrict__ xw,
                    float* __restrict__ bc)
{
    __shared__ ull   As2[16][64];
    __shared__ float Bs[16][32];
    const int tid = threadIdx.x;
    const int tm = tid >> 4, tn = tid & 15;
    const int m0 = blockIdx.x * 64;
    ull acc[4];
#pragma unroll
    for (int i = 0; i < 4; i++) acc[i] = 0ull;
    const int ar = tid >> 2, aq = (tid & 3) * 4;
    float4 a1 = *(const float4*)(A + (size_t)(m0 + ar) * DIN + aq);
    float bvv[2];
#pragma unroll
    for (int q = 0; q < 2; q++) {
        int idx = tid + q * 256;
        bvv[q] = xw[(size_t)(idx >> 5) * 40 + 8 + (idx & 31)];
    }
    for (int k0 = 0; k0 < DIN; k0 += 16) {
        __syncthreads();
        As2[aq + 0][ar] = pack2(a1.x, a1.x);
        As2[aq + 1][ar] = pack2(a1.y, a1.y);
        As2[aq + 2][ar] = pack2(a1.z, a1.z);
        As2[aq + 3][ar] = pack2(a1.w, a1.w);
#pragma unroll
        for (int q = 0; q < 2; q++) {
            int idx = tid + q * 256;
            Bs[idx >> 5][idx & 31] = bvv[q];
        }
        __syncthreads();
        if (k0 + 16 < DIN) {
            a1 = *(const float4*)(A + (size_t)(m0 + ar) * DIN + k0 + 16 + aq);
#pragma unroll
            for (int q = 0; q < 2; q++) {
                int idx = tid + q * 256;
                bvv[q] = xw[(size_t)(k0 + 16 + (idx >> 5)) * 40 + 8 + (idx & 31)];
            }
        }
#pragma unroll
        for (int k = 0; k < 16; k++) {
            ull b2 = *(const ull*)&Bs[k][2 * tn];
#pragma unroll
            for (int i = 0; i < 4; i++)
                acc[i] = ffma2(As2[k][tm * 4 + i], b2, acc[i]);
        }
    }
#pragma unroll
    for (int i = 0; i < 4; i++) {
        int row = m0 + tm * 4 + i;
        float lo, hi; unpack2(acc[i], lo, hi);
        *(float2*)(bc + (size_t)row * 32 + 2 * tn) = make_float2(lo, hi);
    }
}

// ---------------- out_proj GEMM: M-tile 64, software-pipelined -------------------
__global__ __launch_bounds__(256)
void gemm_out_kernel(const float* __restrict__ gatedT, const float* __restrict__ Bw,
                     float* __restrict__ out)
{
    __shared__ ull   As2[8][64];
    __shared__ float Bs[8][128];
    __shared__ float sT[32][65];
    const int tid = threadIdx.x;
    const int tm = tid >> 4, tn = tid & 15;
    const int m0 = blockIdx.x * 64;
    const int K = DIN, N = DIM;
    const int b = m0 >> 12, t0 = m0 & 4095;
    ull acc[4][4];
#pragma unroll
    for (int i = 0; i < 4; i++)
#pragma unroll
        for (int j = 0; j < 4; j++) acc[i][j] = 0ull;
    const int kk = tid >> 5, tl = tid & 31;
    const int bk = tid >> 5, bn = (tid & 31) * 4;
    float gv[2];
#pragma unroll
    for (int it = 0; it < 2; it++)
        gv[it] = gatedT[((size_t)(b * DIN + kk)) * LSEQ + t0 + tl + 32 * it];
    float4 bv = *(const float4*)(Bw + (size_t)bk * N + bn);
    for (int k0 = 0; k0 < K; k0 += 8) {
        __syncthreads();
#pragma unroll
        for (int it = 0; it < 2; it++)
            As2[kk][tl + 32 * it] = pack2(gv[it], gv[it]);
        *(float4*)&Bs[bk][bn] = bv;
        __syncthreads();
        if (k0 + 8 < K) {
            int d = k0 + 8 + kk;
#pragma unroll
            for (int it = 0; it < 2; it++)
                gv[it] = gatedT[((size_t)(b * DIN + d)) * LSEQ + t0 + tl + 32 * it];
            bv = *(const float4*)(Bw + (size_t)(k0 + 8 + bk) * N + bn);
        }
#pragma unroll
        for (int k = 0; k < 8; k++) {
            ull a2[4], b2[4];
#pragma unroll
            for (int i = 0; i < 4; i++) a2[i] = As2[k][tm * 4 + i];
#pragma unroll
            for (int j = 0; j < 4; j++) b2[j] = *(const ull*)&Bs[k][tn * 2 + 32 * j];
#pragma unroll
            for (int i = 0; i < 4; i++)
#pragma unroll
                for (int j = 0; j < 4; j++)
                    acc[i][j] = ffma2(a2[i], b2[j], acc[i][j]);
        }
    }
#pragma unroll
    for (int j = 0; j < 4; j++) {
        __syncthreads();
#pragma unroll
        for (int i = 0; i < 4; i++) {
            int rl = tm * 4 + i;
            float lo, hi; unpack2(acc[i][j], lo, hi);
            sT[2 * tn][rl]     = lo;
            sT[2 * tn + 1][rl] = hi;
        }
        __syncthreads();
        int col = tid >> 3, r0 = (tid & 7) * 8;
        float* dst = out + ((size_t)(b * DIM + 32 * j + col)) * LSEQ + t0 + r0;
#pragma unroll
        for (int k = 0; k < 8; k++) dst[k] = sT[col][r0 + k];
    }
}

// ---------------- causal depthwise conv1d (k=4) + silu, dual-layout output ------
__global__ __launch_bounds__(256)
void conv1d_silu_T_kernel(const float* __restrict__ xrx, const float4* __restrict__ wp,
                          const float* __restrict__ bias,
                          float* __restrict__ xs, float* __restrict__ xsT)
{
    __shared__ float st[32][33];
    const int tx = threadIdx.x & 31, ty = threadIdx.x >> 5;
    const int t0 = blockIdx.x * 32, d0 = blockIdx.y * 32, b = blockIdx.z;
    const int d = d0 + tx;
    float4 w = wp[d];
    float bv = bias[d];
    const float* xb = xrx + (size_t)b * LSEQ * DIN + d;
#pragma unroll
    for (int k = 0; k < 4; k++) {
        int t = t0 + ty + 8 * k;
        float acc = bv;
        if (t - 3 >= 0) acc = fmaf(w.x, xb[(size_t)(t - 3) * DIN], acc);
        if (t - 2 >= 0) acc = fmaf(w.y, xb[(size_t)(t - 2) * DIN], acc);
        if (t - 1 >= 0) acc = fmaf(w.z, xb[(size_t)(t - 1) * DIN], acc);
        acc = fmaf(w.w, xb[(size_t)t * DIN], acc);
        float s = acc / (1.f + __expf(-acc));
        xs[((size_t)b * LSEQ + t) * DIN + d] = s;
        st[tx][ty + 8 * k] = s;
    }
    __syncthreads();
#pragma unroll
    for (int k = 0; k < 4; k++) {
        int dd = d0 + ty + 8 * k;
        xsT[((size_t)(b * DIN + dd)) * LSEQ + t0 + tx] = st[ty + 8 * k][tx];
    }
}

// ---------------- scan pass 1 (R8 form) ----------------
__global__ __launch_bounds__(256)
void scan_p1_kernel(const float* __restrict__ deltaT, const float* __restrict__ xsT,
                    const float* __restrict__ bc, const float* __restrict__ negA,
                    float* __restrict__ chA, float* __restrict__ chH)
{
    int gw = (blockIdx.x * blockDim.x + threadIdx.x) >> 5;
    int lane = threadIdx.x & 31;
    int half = lane >> 4, n = lane & 15;
    int chunk = gw >> 9;
    int wp = gw & 511;
    int pair = wp * 2 + half;
    int b = pair >> 8, d = pair & 255;
    int t0 = chunk * CHLEN;

    float A = negA[d * DSTATE + n];
    const float* dl = deltaT + (size_t)(b * DIN + d) * LSEQ + t0;
    const float* ul = xsT    + (size_t)(b * DIN + d) * LSEQ + t0;
    const float* xb = bc + ((size_t)b * LSEQ + t0) * 32;

    float h = 0.f, pA = 1.f;
    for (int t = 0; t < CHLEN; t++) {
        float dt  = dl[t];
        float ut  = ul[t];
        float Bn  = xb[t * 32 + n];
        float a = __expf(dt * A);
        pA *= a;
        h = fmaf(a, h, dt * ut * Bn);
    }
    int idx = (chunk * NPAIR + pair) * DSTATE + n;
    chA[idx] = pA;
    chH[idx] = h;
}

// ---------------- scan pass 2 ----------------
__global__ __launch_bounds__(256)
void scan_p2_kernel(const float* __restrict__ chA, const float* __restrict__ chH,
                    float* __restrict__ hst)
{
    int i = blockIdx.x * 256 + threadIdx.x;
    float h = 0.f;
    hst[i] = 0.f;
#pragma unroll
    for (int c = 0; c < NCH - 1; c++) {
        h = fmaf(chA[c * NPAIR * DSTATE + i], h, chH[c * NPAIR * DSTATE + i]);
        hst[(c + 1) * NPAIR * DSTATE + i] = h;
    }
}

// ---------------- scan pass 3 (R8 form, + fused gate) ----------------
__global__ __launch_bounds__(256)
void scan_p3_kernel(const float* __restrict__ deltaT, const float* __restrict__ xsT,
                    const float* __restrict__ bc, const float* __restrict__ negA,
                    const float* __restrict__ Dp, const float* __restrict__ hst,
                    const float* __restrict__ resT, float* __restrict__ gatedT)
{
    __shared__ float sy[8][2][32];
    int gw = (blockIdx.x * blockDim.x + threadIdx.x) >> 5;
    int lane = threadIdx.x & 31;
    int wslot = threadIdx.x >> 5;
    int half = lane >> 4, n = lane & 15;
    int chunk = gw >> 9;
    int wp = gw & 511;
    int pair = wp * 2 + half;
    int b = pair >> 8, d = pair & 255;
    int t0 = chunk * CHLEN;

    float A = negA[d * DSTATE + n];
    const float* dl = deltaT + (size_t)(b * DIN + d) * LSEQ + t0;
    const float* ul = xsT    + (size_t)(b * DIN + d) * LSEQ + t0;
    const float* xb = bc + ((size_t)b * LSEQ + t0) * 32;
    float h = hst[(chunk * NPAIR + pair) * DSTATE + n];

    int dp0 = (wp * 2) & 255;
    int bb  = (wp * 2) >> 8;
    float Dv0 = Dp[dp0], Dv1 = Dp[dp0 + 1];
    const float* u0p = xsT + (size_t)(bb * DIN + dp0)     * LSEQ + t0;
    const float* u1p = xsT + (size_t)(bb * DIN + dp0 + 1) * LSEQ + t0;
    const float* r0p = resT + (size_t)(bb * DIN + dp0)     * LSEQ + t0;
    const float* r1p = resT + (size_t)(bb * DIN + dp0 + 1) * LSEQ + t0;
    float* y0p = gatedT + (size_t)(bb * DIN + dp0)     * LSEQ + t0;
    float* y1p = gatedT + (size_t)(bb * DIN + dp0 + 1) * LSEQ + t0;

    for (int t = 0; t < CHLEN; t++) {
        float dt  = dl[t];
        float ut  = ul[t];
        float Bn  = xb[t * 32 + n];
        float Cn  = xb[t * 32 + 16 + n];
        float a = __expf(dt * A);
        h = fmaf(a, h, dt * ut * Bn);
        float yv = h * Cn;
        yv += __shfl_xor_sync(0xffffffffu, yv, 8);
        yv += __shfl_xor_sync(0xffffffffu, yv, 4);
        yv += __shfl_xor_sync(0xffffffffu, yv, 2);
        yv += __shfl_xor_sync(0xffffffffu, yv, 1);
        if (n == 0) sy[wslot][half][t & 31] = yv;
        if ((t & 31) == 31) {
            __syncwarp();
            int tb = t & ~31;
            float r0 = r0p[tb + lane];
            float r1 = r1p[tb + lane];
            float s0 = r0 / (1.f + __expf(-r0));
            float s1 = r1 / (1.f + __expf(-r1));
            y0p[tb + lane] = fmaf(u0p[tb + lane], Dv0, sy[wslot][0][lane]) * s0;
            y1p[tb + lane] = fmaf(u1p[tb + lane], Dv1, sy[wslot][1][lane]) * s1;
            __syncwarp();
        }
    }
}

// ---------------- launch ----------------
extern "C" void kernel_launch(void* const* d_in, const int* in_sizes, int n_in,
                              void* d_out, int out_size)
{
    const float* x         = (const float*)d_in[0];
    const float* conv1_w   = (const float*)d_in[1];
    const float* conv1_b   = (const float*)d_in[2];
    const float* conv2_w   = (const float*)d_in[3];
    const float* conv2_b   = (const float*)d_in[4];
    const float* ln_g      = (const float*)d_in[5];
    const float* ln_b      = (const float*)d_in[6];
    const float* in_proj_w = (const float*)d_in[7];
    const float* conv1d_w  = (const float*)d_in[8];
    const float* conv1d_b  = (const float*)d_in[9];
    const float* x_proj_w  = (const float*)d_in[10];
    const float* dt_proj_w = (const float*)d_in[11];
    const float* dt_proj_b = (const float*)d_in[12];
    const float* A_log     = (const float*)d_in[13];
    const float* Dp        = (const float*)d_in[14];
    const float* out_proj_w= (const float*)d_in[15];
    float* out = (float*)d_out;

    Scratch* s = nullptr;
    cudaGetSymbolAddress((void**)&s, g_scratch);

    const size_t p1stride = (size_t)BATCH * DIN * HW;
    const size_t p2stride = (size_t)BATCH * DIM * HW;

    // 0-2) precompute (conv1 stays at profiled slot 3)
    negA_wpack_kernel<<<17, 256>>>(A_log, s->negA, conv1d_w, s->wpack);
    weff_kernel<<<DIN, DIN>>>(x_proj_w, dt_proj_w, s->weff);
    wdup_kernel<<<(W1ELEMS + W2ELEMS + 255) / 256, 256>>>(conv1_w, conv2_w, s->wd1, s->wd2);
    // 3) conv1 split-K x2
    conv3x3_v10_kernel<DIM, DIN, 2><<<dim3(2, 1, BATCH * (DIN / 8) * 2), 256>>>(
        x, s->wd1, s->h1);
    // 4) inorm (sums 2 partials + bias) + leaky
    inorm_lrelu_kernel<2><<<BATCH * DIN, 256>>>(s->h1, p1stride, conv1_b, DIN, s->h1, nullptr);
    // 5) conv2 split-K x4
    conv3x3_v10_kernel<DIN, DIM, 4><<<dim3(2, 1, BATCH * (DIM / 8) * 4), 256>>>(
        s->h1, s->wd2, s->h2);
    // 6) inorm (sums 4 partials + bias) + leaky + residual
    inorm_lrelu_kernel<4><<<BATCH * DIM, 256>>>(s->h2, p2stride, conv2_b, DIM, s->h2, x);
    // 7) layernorm (coalesced) + transpose to (b*l, c)
    layernorm_v2_kernel<<<dim3(HW / 32, BATCH), 256>>>(s->h2, ln_g, ln_b, s->t);
    // 8) in_proj GEMM (xs rows + res transposed)
    gemm_inproj_kernel<<<dim3(BATCH * LSEQ / 128, 4), 256>>>(
        s->t, in_proj_w, s->xrx, s->resT);
    // 9) depthwise conv1d + silu
    conv1d_silu_T_kernel<<<dim3(LSEQ / 32, DIN / 32, BATCH), 256>>>(
        s->xrx, s->wpack, conv1d_b, s->xs, s->xsT);
    // 10) delta GEMM (softplus + transpose)
    gemm_delta_kernel<<<dim3(BATCH * LSEQ / 128, 2), 256>>>(
        s->xs, s->weff, dt_proj_b, s->deltaT);
    // 11) B/C GEMM (M-tile 64)
    gemm_bc_kernel<<<BATCH * LSEQ / 64, 256>>>(s->xs, x_proj_w, s->bc);
    // 12) chunked selective scan
    scan_p1_kernel<<<(NCH - 1) * 64, 256>>>(
        s->deltaT, s->xsT, s->bc, s->negA, s->chA, s->chH);
    scan_p2_kernel<<<NPAIR * DSTATE / 256, 256>>>(s->chA, s->chH, s->hst);
    scan_p3_kernel<<<NCH * 64, 256>>>(
        s->deltaT, s->xsT, s->bc, s->negA, Dp, s->hst, s->resT, s->gatedT);
    // 13) out_proj GEMM (M-tile 64) + NCHW store
    gemm_out_kernel<<<BATCH * LSEQ / 64, 256>>>(s->gatedT, out_proj_w, out);
}

// round 13
// speedup vs baseline: 1.2437x; 1.0429x over previous
#include <cuda_runtime.h>
#include <cuda_bf16.h>
#include <cstdint>
#include <cstddef>

#define BATCH 4
#define DIM   128
#define DIN   256
#define HH    64
#define WW    64
#define HW    4096
#define LSEQ  4096
#define DSTATE 16
#define DTRANK 8
#define EPSV  1e-5f
#define SLOPE 0.01f

#define NCH   4
#define CHLEN (LSEQ/NCH)
#define NPAIR (BATCH*DIN)

typedef unsigned long long ull;

__device__ __forceinline__ ull pack2(float lo, float hi) {
    ull r; asm("mov.b64 %0, {%1, %2};" : "=l"(r) : "f"(lo), "f"(hi)); return r;
}
__device__ __forceinline__ void unpack2(ull p, float& lo, float& hi) {
    asm("mov.b64 {%0, %1}, %2;" : "=f"(lo), "=f"(hi) : "l"(p));
}
__device__ __forceinline__ ull ffma2(ull a, ull b, ull c) {
    ull d; asm("fma.rn.f32x2 %0, %1, %2, %3;" : "=l"(d) : "l"(a), "l"(b), "l"(c)); return d;
}
__device__ __forceinline__ float softplus_f(float x) {
    return (x > 20.f) ? x : log1pf(expf(x));
}
__device__ __forceinline__ uint32_t saddr(const void* p) {
    return (uint32_t)__cvta_generic_to_shared(p);
}
__device__ __forceinline__ void cpa4(uint32_t dst, const void* src) {
    asm volatile("cp.async.ca.shared.global [%0], [%1], 4;" :: "r"(dst), "l"(src));
}
__device__ __forceinline__ void cpa16(uint32_t dst, const void* src) {
    asm volatile("cp.async.cg.shared.global [%0], [%1], 16;" :: "r"(dst), "l"(src));
}

#define W1ELEMS (DIM * 9 * DIN)
#define W2ELEMS (DIN * 9 * DIM)

// ---------------- scratch ----------------
struct Scratch {
    float h1[2 * BATCH * DIN * HW];
    float h2[4 * BATCH * DIM * HW];
    float t [BATCH * LSEQ * DIM];
    float xrx[BATCH * LSEQ * DIN];
    float resT[NPAIR * LSEQ];
    float xs[BATCH * LSEQ * DIN];
    float xsT[NPAIR * LSEQ];
    float deltaT[NPAIR * LSEQ];
    float gatedT[NPAIR * LSEQ];
    float bc[BATCH * LSEQ * 2*DSTATE];
    float weff[DIN * DIN];
    float negA[DIN * DSTATE];
    float4 wpack[DIN];
    float wd1[W1ELEMS];
    float wd2[W2ELEMS];
    float chA[(NCH-1) * NPAIR * DSTATE];
    float chH[(NCH-1) * NPAIR * DSTATE];
    float hst[NCH * NPAIR * DSTATE];
};
__device__ Scratch g_scratch;

// ---------------- precompute kernels (3 launches; conv1 stays at slot 3) ---------
__global__ void negA_wpack_kernel(const float* __restrict__ A_log, float* __restrict__ negA,
                                  const float* __restrict__ w1d, float4* __restrict__ wp)
{
    if (blockIdx.x < 16) {
        int i = blockIdx.x * 256 + threadIdx.x;
        negA[i] = -expf(A_log[i]);
    } else {
        int d = threadIdx.x;
        wp[d] = make_float4(w1d[4*d], w1d[4*d+1], w1d[4*d+2], w1d[4*d+3]);
    }
}
__global__ __launch_bounds__(256)
void weff_kernel(const float* __restrict__ xw, const float* __restrict__ dtw,
                 float* __restrict__ weff)
{
    int k = blockIdx.x, d = threadIdx.x;
    float acc = 0.f;
#pragma unroll
    for (int r = 0; r < DTRANK; r++)
        acc = fmaf(xw[k * 40 + r], dtw[r * DIN + d], acc);
    weff[k * DIN + d] = acc;
}
__global__ __launch_bounds__(256)
void wdup_kernel(const float* __restrict__ w1, const float* __restrict__ w2,
                 float* __restrict__ wd1, float* __restrict__ wd2)
{
    int i = blockIdx.x * 256 + threadIdx.x;
    if (i < W1ELEMS) {
        int oc = i % DIN; int rest = i / DIN;
        int tap = rest % 9; int ci = rest / 9;
        wd1[i] = w1[((size_t)oc * DIM + ci) * 9 + tap];
    } else if (i < W1ELEMS + W2ELEMS) {
        int j = i - W1ELEMS;
        int oc = j % DIM; int rest = j / DIM;
        int tap = rest % 9; int ci = rest / 9;
        wd2[j] = w2[((size_t)oc * DIN + ci) * 9 + tap];
    }
}

// ---------------- conv v10 (exact R12 form) ---------------------------------------
template<int CIN, int COUT, int SPLIT>
__global__ __launch_bounds__(256, 2)
void conv3x3_v10_kernel(const float* __restrict__ x, const float* __restrict__ wd,
                        float* __restrict__ out)
{
    constexpr int OCPB = 8, CIC = 2, CSPAN = CIN / SPLIT;
    constexpr int NCHUNK = CSPAN / CIC;
    __shared__ float4 sx4[2][CIC * 18 * 36];
    __shared__ float4 swt[2][CIC * 9 * 2];

    const int tid = threadIdx.x;
    const int tx = tid & 31, ty = tid >> 5;
    const int bx0 = blockIdx.x * 32;
    const int bz = blockIdx.z;
    constexpr int OCB = COUT / OCPB;
    const int b    = bz / (OCB * SPLIT);
    const int r    = bz % (OCB * SPLIT);
    const int oc0  = (r / SPLIT) * OCPB;
    const int part = r % SPLIT;
    const int cbase = part * CSPAN;
    const float* xb = x + (size_t)b * CIN * HW;
    float* out_part = out + (size_t)part * BATCH * COUT * HW;

    for (int i = tid; i < 2 * CIC * 18 * 36; i += 256)
        ((float4*)sx4)[i] = make_float4(0.f, 0.f, 0.f, 0.f);
    __syncthreads();

    auto load_chunk = [&](int buf, int c0) {
        for (int rr = ty; rr < CIC * 18; rr += 8) {
            int ci = (rr >= 18) ? 1 : 0;
            int p  = rr - 18 * ci;
            int gr = p - 1;
#pragma unroll
            for (int s = 0; s < 2; s++) {
                int xx = tx + 32 * s;
                if (xx < 34) {
                    int gx = bx0 + xx - 1;
                    if ((unsigned)gx < (unsigned)WW) {
                        const float* pc = xb + (size_t)(cbase + c0 + ci) * HW + gx;
                        uint32_t dst = saddr(&sx4[buf][rr * 36 + xx]);
                        if (p > 0)  cpa4(dst + 0,  pc + (size_t)gr * WW);
                        cpa4(dst + 4,  pc + (size_t)(gr + 16) * WW);
                        cpa4(dst + 8,  pc + (size_t)(gr + 32) * WW);
                        if (p < 17) cpa4(dst + 12, pc + (size_t)(gr + 48) * WW);
                    }
                }
            }
        }
        if (tid < CIC * 9 * 2) {
            int q = tid & 1;
            int rowi = tid >> 1;
            int ci = (rowi >= 9) ? 1 : 0;
            int tap = rowi - 9 * ci;
            const float* src = wd + ((size_t)(cbase + c0 + ci) * 9 + tap) * COUT + oc0 + 4 * q;
            cpa16(saddr(&swt[buf][rowi * 2 + q]), src);
        }
    };

    ull acc[OCPB][4];
#pragma unroll
    for (int i = 0; i < OCPB; i++)
#pragma unroll
        for (int q = 0; q < 4; q++) acc[i][q] = 0ull;

    load_chunk(0, 0);
    asm volatile("cp.async.commit_group;");

    for (int ch = 0; ch < NCHUNK; ch++) {
        const int cur = ch & 1;
        if (ch + 1 < NCHUNK) {
            load_chunk(cur ^ 1, (ch + 1) * CIC);
            asm volatile("cp.async.commit_group;");
            asm volatile("cp.async.wait_group 1;");
        } else {
            asm volatile("cp.async.wait_group 0;");
        }
        __syncthreads();

        const float4* sxb = sx4[cur];
        const float4* swb = swt[cur];
#pragma unroll
        for (int ci = 0; ci < CIC; ci++) {
#pragma unroll
            for (int tap = 0; tap < 9; tap++) {
                const int ti = tap / 3, tj = tap % 3;
                ulonglong2 A = *(const ulonglong2*)&sxb[(ci * 18 + ty + ti) * 36 + tx + tj];
                ulonglong2 C = *(const ulonglong2*)&sxb[(ci * 18 + ty + 8 + ti) * 36 + tx + tj];
                float4 wa = swb[(ci * 9 + tap) * 2 + 0];
                {
                    ull w0 = pack2(wa.x, wa.x), w1 = pack2(wa.y, wa.y);
                    ull w2 = pack2(wa.z, wa.z), w3 = pack2(wa.w, wa.w);
                    acc[0][0] = ffma2(A.x, w0, acc[0][0]); acc[0][1] = ffma2(A.y, w0, acc[0][1]);
                    acc[0][2] = ffma2(C.x, w0, acc[0][2]); acc[0][3] = ffma2(C.y, w0, acc[0][3]);
                    acc[1][0] = ffma2(A.x, w1, acc[1][0]); acc[1][1] = ffma2(A.y, w1, acc[1][1]);
                    acc[1][2] = ffma2(C.x, w1, acc[1][2]); acc[1][3] = ffma2(C.y, w1, acc[1][3]);
                    acc[2][0] = ffma2(A.x, w2, acc[2][0]); acc[2][1] = ffma2(A.y, w2, acc[2][1]);
                    acc[2][2] = ffma2(C.x, w2, acc[2][2]); acc[2][3] = ffma2(C.y, w2, acc[2][3]);
                    acc[3][0] = ffma2(A.x, w3, acc[3][0]); acc[3][1] = ffma2(A.y, w3, acc[3][1]);
                    acc[3][2] = ffma2(C.x, w3, acc[3][2]); acc[3][3] = ffma2(C.y, w3, acc[3][3]);
                }
                float4 wb = swb[(ci * 9 + tap) * 2 + 1];
                {
                    ull w4 = pack2(wb.x, wb.x), w5 = pack2(wb.y, wb.y);
                    ull w6 = pack2(wb.z, wb.z), w7 = pack2(wb.w, wb.w);
                    acc[4][0] = ffma2(A.x, w4, acc[4][0]); acc[4][1] = ffma2(A.y, w4, acc[4][1]);
                    acc[4][2] = ffma2(C.x, w4, acc[4][2]); acc[4][3] = ffma2(C.y, w4, acc[4][3]);
                    acc[5][0] = ffma2(A.x, w5, acc[5][0]); acc[5][1] = ffma2(A.y, w5, acc[5][1]);
                    acc[5][2] = ffma2(C.x, w5, acc[5][2]); acc[5][3] = ffma2(C.y, w5, acc[5][3]);
                    acc[6][0] = ffma2(A.x, w6, acc[6][0]); acc[6][1] = ffma2(A.y, w6, acc[6][1]);
                    acc[6][2] = ffma2(C.x, w6, acc[6][2]); acc[6][3] = ffma2(C.y, w6, acc[6][3]);
                    acc[7][0] = ffma2(A.x, w7, acc[7][0]); acc[7][1] = ffma2(A.y, w7, acc[7][1]);
                    acc[7][2] = ffma2(C.x, w7, acc[7][2]); acc[7][3] = ffma2(C.y, w7, acc[7][3]);
                }
            }
        }
        __syncthreads();
    }

    float* ob = out_part + (size_t)b * COUT * HW;
#pragma unroll
    for (int oc = 0; oc < OCPB; oc++) {
        float r0, r16, r32, r48, r8, r24, r40, r56;
        unpack2(acc[oc][0], r0,  r16);
        unpack2(acc[oc][1], r32, r48);
        unpack2(acc[oc][2], r8,  r24);
        unpack2(acc[oc][3], r40, r56);
        size_t base = ((size_t)(oc0 + oc) * HH) * WW + bx0 + tx;
        ob[base + (size_t)(ty)      * WW] = r0;
        ob[base + (size_t)(ty + 8)  * WW] = r8;
        ob[base + (size_t)(ty + 16) * WW] = r16;
        ob[base + (size_t)(ty + 24) * WW] = r24;
        ob[base + (size_t)(ty + 32) * WW] = r32;
        ob[base + (size_t)(ty + 40) * WW] = r40;
        ob[base + (size_t)(ty + 48) * WW] = r48;
        ob[base + (size_t)(ty + 56) * WW] = r56;
    }
}

// ---------------- instance norm + leaky, sums NPART split-K partials + bias -------
template<int NPART>
__global__ __launch_bounds__(256)
void inorm_lrelu_kernel(const float* __restrict__ in, size_t pstride,
                        const float* __restrict__ bias, int C,
                        float* __restrict__ out, const float* __restrict__ resid)
{
    __shared__ float s1[256], s2[256];
    const size_t base = (size_t)blockIdx.x * HW;
    const int c = blockIdx.x % C;
    const float bv = bias[c];
    const float* p = in + base;
    float v[16];
    float sum = 0.f, sq = 0.f;
#pragma unroll
    for (int i = 0; i < 16; i++) {
        int off = threadIdx.x + i * 256;
        float acc = bv + p[off];
        if (NPART >= 2) acc += p[pstride + off];
        if (NPART >= 3) acc += p[2 * pstride + off];
        if (NPART >= 4) acc += p[3 * pstride + off];
        v[i] = acc;
        sum += acc; sq += acc * acc;
    }
    s1[threadIdx.x] = sum; s2[threadIdx.x] = sq;
    __syncthreads();
    for (int off = 128; off; off >>= 1) {
        if (threadIdx.x < off) {
            s1[threadIdx.x] += s1[threadIdx.x + off];
            s2[threadIdx.x] += s2[threadIdx.x + off];
        }
        __syncthreads();
    }
    float mean = s1[0] * (1.f / HW);
    float var  = s2[0] * (1.f / HW) - mean * mean;
    float rstd = rsqrtf(var + EPSV);
    float* o = out + base;
    const float* rr = resid ? resid + base : nullptr;
#pragma unroll
    for (int i = 0; i < 16; i++) {
        float xv = v[i];
        float lr = xv > 0.f ? xv : SLOPE * xv;
        float val = (xv - mean) * rstd + lr;
        if (rr) val += rr[threadIdx.x + i * 256];
        o[threadIdx.x + i * 256] = val;
    }
}

// ---------------- layernorm over channels, coalesced via smem transpose ----------
__global__ __launch_bounds__(256)
void layernorm_v2_kernel(const float* __restrict__ h, const float* __restrict__ g,
                         const float* __restrict__ beta, float* __restrict__ t)
{
    __shared__ float sv[DIM][33];
    __shared__ float ps[8][33], ps2[8][33];
    __shared__ float smean[32], srstd[32];
    const int tx = threadIdx.x & 31, ty = threadIdx.x >> 5;
    const int l0 = blockIdx.x * 32, b = blockIdx.y;
    const float* hb = h + (size_t)b * DIM * HW + l0;

    for (int c = ty; c < DIM; c += 8)
        sv[c][tx] = hb[(size_t)c * HW + tx];
    __syncthreads();

    float sum = 0.f, sq = 0.f;
#pragma unroll
    for (int i = 0; i < 16; i++) {
        float v = sv[ty * 16 + i][tx];
        sum += v; sq += v * v;
    }
    ps[ty][tx] = sum; ps2[ty][tx] = sq;
    __syncthreads();
    if (ty == 0) {
        float s = 0.f, s2 = 0.f;
#pragma unroll
        for (int w = 0; w < 8; w++) { s += ps[w][tx]; s2 += ps2[w][tx]; }
        float mean = s * (1.f / DIM);
        float var  = s2 * (1.f / DIM) - mean * mean;
        smean[tx] = mean;
        srstd[tx] = rsqrtf(var + EPSV);
    }
    __syncthreads();

#pragma unroll
    for (int cc = 0; cc < 4; cc++) {
        int c = tx + 32 * cc;
        float gv = g[c], bv = beta[c];
        for (int l = ty; l < 32; l += 8) {
            float m = smean[l], rs = srstd[l];
            t[((size_t)(b * LSEQ + l0 + l)) * DIM + c] = (sv[c][l] - m) * rs * gv + bv;
        }
    }
}

// ---------------- in_proj GEMM (software-pipelined loads) ------------------------
__global__ __launch_bounds__(256)
void gemm_inproj_kernel(const float* __restrict__ A, const float* __restrict__ Bw,
                        float* __restrict__ xrx, float* __restrict__ resT)
{
    __shared__ ull   As2[8][128];
    __shared__ float Bs[8][128];
    __shared__ float sT[32][129];
    const int tid = threadIdx.x;
    const int tm = tid >> 4, tn = tid & 15;
    const int m0 = blockIdx.x * 128, n0 = blockIdx.y * 128;
    const int K = DIM, N = 2 * DIN;
    ull acc[8][4];
#pragma unroll
    for (int i = 0; i < 8; i++)
#pragma unroll
        for (int j = 0; j < 4; j++) acc[i][j] = 0ull;
    const int ar = tid >> 1, ak = (tid & 1) * 4;
    const int bk = tid >> 5, bn = (tid & 31) * 4;
    float4 av = *(const float4*)(A + (size_t)(m0 + ar) * K + ak);
    float4 bv = *(const float4*)(Bw + (size_t)bk * N + n0 + bn);
    for (int k0 = 0; k0 < K; k0 += 8) {
        __syncthreads();
        As2[ak + 0][ar] = pack2(av.x, av.x);
        As2[ak + 1][ar] = pack2(av.y, av.y);
        As2[ak + 2][ar] = pack2(av.z, av.z);
        As2[ak + 3][ar] = pack2(av.w, av.w);
        *(float4*)&Bs[bk][bn] = bv;
        __syncthreads();
        if (k0 + 8 < K) {
            av = *(const float4*)(A + (size_t)(m0 + ar) * K + k0 + 8 + ak);
            bv = *(const float4*)(Bw + (size_t)(k0 + 8 + bk) * N + n0 + bn);
        }
#pragma unroll
        for (int k = 0; k < 8; k++) {
            ull a2[8], b2[4];
#pragma unroll
            for (int i = 0; i < 8; i++) a2[i] = As2[k][tm * 8 + i];
#pragma unroll
            for (int j = 0; j < 4; j++) b2[j] = *(const ull*)&Bs[k][tn * 2 + 32 * j];
#pragma unroll
            for (int i = 0; i < 8; i++)
#pragma unroll
                for (int j = 0; j < 4; j++)
                    acc[i][j] = ffma2(a2[i], b2[j], acc[i][j]);
        }
    }
    if (n0 < DIN) {
#pragma unroll
        for (int i = 0; i < 8; i++) {
            int row = m0 + tm * 8 + i;
#pragma unroll
            for (int j = 0; j < 4; j++) {
                float lo, hi; unpack2(acc[i][j], lo, hi);
                *(float2*)(xrx + (size_t)row * DIN + n0 + tn * 2 + 32 * j) = make_float2(lo, hi);
            }
        }
    } else {
        const int b = m0 >> 12, t0 = m0 & 4095, d0 = n0 - DIN;
#pragma unroll
        for (int j = 0; j < 4; j++) {
            __syncthreads();
#pragma unroll
            for (int i = 0; i < 8; i++) {
                int rl = tm * 8 + i;
                float lo, hi; unpack2(acc[i][j], lo, hi);
                sT[2 * tn][rl]     = lo;
                sT[2 * tn + 1][rl] = hi;
            }
            __syncthreads();
            int col = tid >> 3, r0 = (tid & 7) * 16;
            float* dst = resT + ((size_t)(b * DIN + d0 + 32 * j + col)) * LSEQ + t0 + r0;
#pragma unroll
            for (int k = 0; k < 16; k++) dst[k] = sT[col][r0 + k];
        }
    }
}

// ---------------- delta GEMM (software-pipelined loads) --------------------------
__global__ __launch_bounds__(256)
void gemm_delta_kernel(const float* __restrict__ A, const float* __restrict__ Bw,
                       const float* __restrict__ dtb, float* __restrict__ deltaT)
{
    __shared__ ull   As2[8][128];
    __shared__ float Bs[8][128];
    __shared__ float sT[32][129];
    const int tid = threadIdx.x;
    const int tm = tid >> 4, tn = tid & 15;
    const int m0 = blockIdx.x * 128, n0 = blockIdx.y * 128;
    const int K = DIN, N = DIN;
    ull acc[8][4];
#pragma unroll
    for (int i = 0; i < 8; i++)
#pragma unroll
        for (int j = 0; j < 4; j++) acc[i][j] = 0ull;
    const int ar = tid >> 1, ak = (tid & 1) * 4;
    const int bk = tid >> 5, bn = (tid & 31) * 4;
    float4 av = *(const float4*)(A + (size_t)(m0 + ar) * K + ak);
    float4 bv = *(const float4*)(Bw + (size_t)bk * N + n0 + bn);
    for (int k0 = 0; k0 < K; k0 += 8) {
        __syncthreads();
        As2[ak + 0][ar] = pack2(av.x, av.x);
        As2[ak + 1][ar] = pack2(av.y, av.y);
        As2[ak + 2][ar] = pack2(av.z, av.z);
        As2[ak + 3][ar] = pack2(av.w, av.w);
        *(float4*)&Bs[bk][bn] = bv;
        __syncthreads();
        if (k0 + 8 < K) {
            av = *(const float4*)(A + (size_t)(m0 + ar) * K + k0 + 8 + ak);
            bv = *(const float4*)(Bw + (size_t)(k0 + 8 + bk) * N + n0 + bn);
        }
#pragma unroll
        for (int k = 0; k < 8; k++) {
            ull a2[8], b2[4];
#pragma unroll
            for (int i = 0; i < 8; i++) a2[i] = As2[k][tm * 8 + i];
#pragma unroll
            for (int j = 0; j < 4; j++) b2[j] = *(const ull*)&Bs[k][tn * 2 + 32 * j];
#pragma unroll
            for (int i = 0; i < 8; i++)
#pragma unroll
                for (int j = 0; j < 4; j++)
                    acc[i][j] = ffma2(a2[i], b2[j], acc[i][j]);
        }
    }
    const int b = m0 >> 12, t0 = m0 & 4095;
#pragma unroll
    for (int j = 0; j < 4; j++) {
        __syncthreads();
        float blo = dtb[n0 + 32 * j + 2 * tn];
        float bhi = dtb[n0 + 32 * j + 2 * tn + 1];
#pragma unroll
        for (int i = 0; i < 8; i++) {
            int rl = tm * 8 + i;
            float lo, hi; unpack2(acc[i][j], lo, hi);
            sT[2 * tn][rl]     = softplus_f(lo + blo);
            sT[2 * tn + 1][rl] = softplus_f(hi + bhi);
        }
        __syncthreads();
        int col = tid >> 3, r0 = (tid & 7) * 16;
        float* dst = deltaT + ((size_t)(b * DIN + n0 + 32 * j + col)) * LSEQ + t0 + r0;
#pragma unroll
        for (int k = 0; k < 16; k++) dst[k] = sT[col][r0 + k];
    }
}

// ---------------- BC GEMM: M-tile 64, software-pipelined -------------------------
__global__ __launch_bounds__(256)
void gemm_bc_kernel(const float* __restrict__ A, const float* __restrict__ xw,
                    float* __restrict__ bc)
{
    __shared__ ull   As2[16][64];
    __shared__ float Bs[16][32];
    const int tid = threadIdx.x;
    const int tm = tid >> 4, tn = tid & 15;
    const int m0 = blockIdx.x * 64;
    ull acc[4];
#pragma unroll
    for (int i = 0; i < 4; i++) acc[i] = 0ull;
    const int ar = tid >> 2, aq = (tid & 3) * 4;
    float4 a1 = *(const float4*)(A + (size_t)(m0 + ar) * DIN + aq);
    float bvv[2];
#pragma unroll
    for (int q = 0; q < 2; q++) {
        int idx = tid + q * 256;
        bvv[q] = xw[(size_t)(idx >> 5) * 40 + 8 + (idx & 31)];
    }
    for (int k0 = 0; k0 < DIN; k0 += 16) {
        __syncthreads();
        As2[aq + 0][ar] = pack2(a1.x, a1.x);
        As2[aq + 1][ar] = pack2(a1.y, a1.y);
        As2[aq + 2][ar] = pack2(a1.z, a1.z);
        As2[aq + 3][ar] = pack2(a1.w, a1.w);
#pragma unroll
        for (int q = 0; q < 2; q++) {
            int idx = tid + q * 256;
            Bs[idx >> 5][idx & 31] = bvv[q];
        }
        __syncthreads();
        if (k0 + 16 < DIN) {
            a1 = *(const float4*)(A + (size_t)(m0 + ar) * DIN + k0 + 16 + aq);
#pragma unroll
            for (int q = 0; q < 2; q++) {
                int idx = tid + q * 256;
                bvv[q] = xw[(size_t)(k0 + 16 + (idx >> 5)) * 40 + 8 + (idx & 31)];
            }
        }
#pragma unroll
        for (int k = 0; k < 16; k++) {
            ull b2 = *(const ull*)&Bs[k][2 * tn];
#pragma unroll
            for (int i = 0; i < 4; i++)
                acc[i] = ffma2(As2[k][tm * 4 + i], b2, acc[i]);
        }
    }
#pragma unroll
    for (int i = 0; i < 4; i++) {
        int row = m0 + tm * 4 + i;
        float lo, hi; unpack2(acc[i], lo, hi);
        *(float2*)(bc + (size_t)row * 32 + 2 * tn) = make_float2(lo, hi);
    }
}

// ---------------- out_proj GEMM: M-tile 64, software-pipelined -------------------
__global__ __launch_bounds__(256)
void gemm_out_kernel(const float* __restrict__ gatedT, const float* __restrict__ Bw,
                     float* __restrict__ out)
{
    __shared__ ull   As2[8][64];
    __shared__ float Bs[8][128];
    __shared__ float sT[32][65];
    const int tid = threadIdx.x;
    const int tm = tid >> 4, tn = tid & 15;
    const int m0 = blockIdx.x * 64;
    const int K = DIN, N = DIM;
    const int b = m0 >> 12, t0 = m0 & 4095;
    ull acc[4][4];
#pragma unroll
    for (int i = 0; i < 4; i++)
#pragma unroll
        for (int j = 0; j < 4; j++) acc[i][j] = 0ull;
    const int kk = tid >> 5, tl = tid & 31;
    const int bk = tid >> 5, bn = (tid & 31) * 4;
    float gv[2];
#pragma unroll
    for (int it = 0; it < 2; it++)
        gv[it] = gatedT[((size_t)(b * DIN + kk)) * LSEQ + t0 + tl + 32 * it];
    float4 bv = *(const float4*)(Bw + (size_t)bk * N + bn);
    for (int k0 = 0; k0 < K; k0 += 8) {
        __syncthreads();
#pragma unroll
        for (int it = 0; it < 2; it++)
            As2[kk][tl + 32 * it] = pack2(gv[it], gv[it]);
        *(float4*)&Bs[bk][bn] = bv;
        __syncthreads();
        if (k0 + 8 < K) {
            int d = k0 + 8 + kk;
#pragma unroll
            for (int it = 0; it < 2; it++)
                gv[it] = gatedT[((size_t)(b * DIN + d)) * LSEQ + t0 + tl + 32 * it];
            bv = *(const float4*)(Bw + (size_t)(k0 + 8 + bk) * N + bn);
        }
#pragma unroll
        for (int k = 0; k < 8; k++) {
            ull a2[4], b2[4];
#pragma unroll
            for (int i = 0; i < 4; i++) a2[i] = As2[k][tm * 4 + i];
#pragma unroll
            for (int j = 0; j < 4; j++) b2[j] = *(const ull*)&Bs[k][tn * 2 + 32 * j];
#pragma unroll
            for (int i = 0; i < 4; i++)
#pragma unroll
                for (int j = 0; j < 4; j++)
                    acc[i][j] = ffma2(a2[i], b2[j], acc[i][j]);
        }
    }
#pragma unroll
    for (int j = 0; j < 4; j++) {
        __syncthreads();
#pragma unroll
        for (int i = 0; i < 4; i++) {
            int rl = tm * 4 + i;
            float lo, hi; unpack2(acc[i][j], lo, hi);
            sT[2 * tn][rl]     = lo;
            sT[2 * tn + 1][rl] = hi;
        }
        __syncthreads();
        int col = tid >> 3, r0 = (tid & 7) * 8;
        float* dst = out + ((size_t)(b * DIM + 32 * j + col)) * LSEQ + t0 + r0;
#pragma unroll
        for (int k = 0; k < 8; k++) dst[k] = sT[col][r0 + k];
    }
}

// ---------------- causal depthwise conv1d (k=4) + silu, dual-layout output ------
__global__ __launch_bounds__(256)
void conv1d_silu_T_kernel(const float* __restrict__ xrx, const float4* __restrict__ wp,
                          const float* __restrict__ bias,
                          float* __restrict__ xs, float* __restrict__ xsT)
{
    __shared__ float st[32][33];
    const int tx = threadIdx.x & 31, ty = threadIdx.x >> 5;
    const int t0 = blockIdx.x * 32, d0 = blockIdx.y * 32, b = blockIdx.z;
    const int d = d0 + tx;
    float4 w = wp[d];
    float bv = bias[d];
    const float* xb = xrx + (size_t)b * LSEQ * DIN + d;
#pragma unroll
    for (int k = 0; k < 4; k++) {
        int t = t0 + ty + 8 * k;
        float acc = bv;
        if (t - 3 >= 0) acc = fmaf(w.x, xb[(size_t)(t - 3) * DIN], acc);
        if (t - 2 >= 0) acc = fmaf(w.y, xb[(size_t)(t - 2) * DIN], acc);
        if (t - 1 >= 0) acc = fmaf(w.z, xb[(size_t)(t - 1) * DIN], acc);
        acc = fmaf(w.w, xb[(size_t)t * DIN], acc);
        float s = acc / (1.f + __expf(-acc));
        xs[((size_t)b * LSEQ + t) * DIN + d] = s;
        st[tx][ty + 8 * k] = s;
    }
    __syncthreads();
#pragma unroll
    for (int k = 0; k < 4; k++) {
        int dd = d0 + ty + 8 * k;
        xsT[((size_t)(b * DIN + dd)) * LSEQ + t0 + tx] = st[ty + 8 * k][tx];
    }
}

// ---------------- scan pass 1 (float4 broadcast loads) ----------------
__global__ __launch_bounds__(256)
void scan_p1_kernel(const float* __restrict__ deltaT, const float* __restrict__ xsT,
                    const float* __restrict__ bc, const float* __restrict__ negA,
                    float* __restrict__ chA, float* __restrict__ chH)
{
    int gw = (blockIdx.x * blockDim.x + threadIdx.x) >> 5;
    int lane = threadIdx.x & 31;
    int half = lane >> 4, n = lane & 15;
    int chunk = gw >> 9;
    int wp = gw & 511;
    int pair = wp * 2 + half;
    int b = pair >> 8, d = pair & 255;
    int t0 = chunk * CHLEN;

    float A = negA[d * DSTATE + n];
    const float* dl = deltaT + (size_t)(b * DIN + d) * LSEQ + t0;
    const float* ul = xsT    + (size_t)(b * DIN + d) * LSEQ + t0;
    const float* xb = bc + ((size_t)b * LSEQ + t0) * 32;

    float h = 0.f, pA = 1.f;
    for (int tb = 0; tb < CHLEN; tb += 4) {
        float4 d4 = *(const float4*)(dl + tb);
        float4 u4 = *(const float4*)(ul + tb);
#pragma unroll
        for (int q = 0; q < 4; q++) {
            float dt = (q == 0) ? d4.x : (q == 1) ? d4.y : (q == 2) ? d4.z : d4.w;
            float ut = (q == 0) ? u4.x : (q == 1) ? u4.y : (q == 2) ? u4.z : u4.w;
            float Bn = xb[(tb + q) * 32 + n];
            float a = __expf(dt * A);
            pA *= a;
            h = fmaf(a, h, dt * ut * Bn);
        }
    }
    int idx = (chunk * NPAIR + pair) * DSTATE + n;
    chA[idx] = pA;
    chH[idx] = h;
}

// ---------------- scan pass 2 ----------------
__global__ __launch_bounds__(256)
void scan_p2_kernel(const float* __restrict__ chA, const float* __restrict__ chH,
                    float* __restrict__ hst)
{
    int i = blockIdx.x * 256 + threadIdx.x;
    float h = 0.f;
    hst[i] = 0.f;
#pragma unroll
    for (int c = 0; c < NCH - 1; c++) {
        h = fmaf(chA[c * NPAIR * DSTATE + i], h, chH[c * NPAIR * DSTATE + i]);
        hst[(c + 1) * NPAIR * DSTATE + i] = h;
    }
}

// ---------------- scan pass 3 (float4 broadcast loads, R8 flush skeleton) --------
__global__ __launch_bounds__(256)
void scan_p3_kernel(const float* __restrict__ deltaT, const float* __restrict__ xsT,
                    const float* __restrict__ bc, const float* __restrict__ negA,
                    const float* __restrict__ Dp, const float* __restrict__ hst,
                    const float* __restrict__ resT, float* __restrict__ gatedT)
{
    __shared__ float sy[8][2][32];
    int gw = (blockIdx.x * blockDim.x + threadIdx.x) >> 5;
    int lane = threadIdx.x & 31;
    int wslot = threadIdx.x >> 5;
    int half = lane >> 4, n = lane & 15;
    int chunk = gw >> 9;
    int wp = gw & 511;
    int pair = wp * 2 + half;
    int b = pair >> 8, d = pair & 255;
    int t0 = chunk * CHLEN;

    float A = negA[d * DSTATE + n];
    const float* dl = deltaT + (size_t)(b * DIN + d) * LSEQ + t0;
    const float* ul = xsT    + (size_t)(b * DIN + d) * LSEQ + t0;
    const float* xb = bc + ((size_t)b * LSEQ + t0) * 32;
    float h = hst[(chunk * NPAIR + pair) * DSTATE + n];

    int dp0 = (wp * 2) & 255;
    int bb  = (wp * 2) >> 8;
    float Dv0 = Dp[dp0], Dv1 = Dp[dp0 + 1];
    const float* u0p = xsT + (size_t)(bb * DIN + dp0)     * LSEQ + t0;
    const float* u1p = xsT + (size_t)(bb * DIN + dp0 + 1) * LSEQ + t0;
    const float* r0p = resT + (size_t)(bb * DIN + dp0)     * LSEQ + t0;
    const float* r1p = resT + (size_t)(bb * DIN + dp0 + 1) * LSEQ + t0;
    float* y0p = gatedT + (size_t)(bb * DIN + dp0)     * LSEQ + t0;
    float* y1p = gatedT + (size_t)(bb * DIN + dp0 + 1) * LSEQ + t0;

    for (int tb = 0; tb < CHLEN; tb += 32) {
        for (int tq = 0; tq < 32; tq += 4) {
            float4 d4 = *(const float4*)(dl + tb + tq);
            float4 u4 = *(const float4*)(ul + tb + tq);
#pragma unroll
            for (int q = 0; q < 4; q++) {
                int t = tb + tq + q;
                float dt = (q == 0) ? d4.x : (q == 1) ? d4.y : (q == 2) ? d4.z : d4.w;
                float ut = (q == 0) ? u4.x : (q == 1) ? u4.y : (q == 2) ? u4.z : u4.w;
                float Bn  = xb[t * 32 + n];
                float Cn  = xb[t * 32 + 16 + n];
                float a = __expf(dt * A);
                h = fmaf(a, h, dt * ut * Bn);
                float yv = h * Cn;
                yv += __shfl_xor_sync(0xffffffffu, yv, 8);
                yv += __shfl_xor_sync(0xffffffffu, yv, 4);
                yv += __shfl_xor_sync(0xffffffffu, yv, 2);
                yv += __shfl_xor_sync(0xffffffffu, yv, 1);
                if (n == 0) sy[wslot][half][tq + q] = yv;
            }
        }
        __syncwarp();
        float r0 = r0p[tb + lane];
        float r1 = r1p[tb + lane];
        float s0 = r0 / (1.f + __expf(-r0));
        float s1 = r1 / (1.f + __expf(-r1));
        y0p[tb + lane] = fmaf(u0p[tb + lane], Dv0, sy[wslot][0][lane]) * s0;
        y1p[tb + lane] = fmaf(u1p[tb + lane], Dv1, sy[wslot][1][lane]) * s1;
        __syncwarp();
    }
}

// ---------------- launch ----------------
extern "C" void kernel_launch(void* const* d_in, const int* in_sizes, int n_in,
                              void* d_out, int out_size)
{
    const float* x         = (const float*)d_in[0];
    const float* conv1_w   = (const float*)d_in[1];
    const float* conv1_b   = (const float*)d_in[2];
    const float* conv2_w   = (const float*)d_in[3];
    const float* conv2_b   = (const float*)d_in[4];
    const float* ln_g      = (const float*)d_in[5];
    const float* ln_b      = (const float*)d_in[6];
    const float* in_proj_w = (const float*)d_in[7];
    const float* conv1d_w  = (const float*)d_in[8];
    const float* conv1d_b  = (const float*)d_in[9];
    const float* x_proj_w  = (const float*)d_in[10];
    const float* dt_proj_w = (const float*)d_in[11];
    const float* dt_proj_b = (const float*)d_in[12];
    const float* A_log     = (const float*)d_in[13];
    const float* Dp        = (const float*)d_in[14];
    const float* out_proj_w= (const float*)d_in[15];
    float* out = (float*)d_out;

    Scratch* s = nullptr;
    cudaGetSymbolAddress((void**)&s, g_scratch);

    const size_t p1stride = (size_t)BATCH * DIN * HW;
    const size_t p2stride = (size_t)BATCH * DIM * HW;

    // 0-2) precompute (conv1 stays at profiled slot 3)
    negA_wpack_kernel<<<17, 256>>>(A_log, s->negA, conv1d_w, s->wpack);
    weff_kernel<<<DIN, DIN>>>(x_proj_w, dt_proj_w, s->weff);
    wdup_kernel<<<(W1ELEMS + W2ELEMS + 255) / 256, 256>>>(conv1_w, conv2_w, s->wd1, s->wd2);
    // 3) conv1 split-K x2
    conv3x3_v10_kernel<DIM, DIN, 2><<<dim3(2, 1, BATCH * (DIN / 8) * 2), 256>>>(
        x, s->wd1, s->h1);
    // 4) inorm (sums 2 partials + bias) + leaky
    inorm_lrelu_kernel<2><<<BATCH * DIN, 256>>>(s->h1, p1stride, conv1_b, DIN, s->h1, nullptr);
    // 5) conv2 split-K x4
    conv3x3_v10_kernel<DIN, DIM, 4><<<dim3(2, 1, BATCH * (DIM / 8) * 4), 256>>>(
        s->h1, s->wd2, s->h2);
    // 6) inorm (sums 4 partials + bias) + leaky + residual
    inorm_lrelu_kernel<4><<<BATCH * DIM, 256>>>(s->h2, p2stride, conv2_b, DIM, s->h2, x);
    // 7) layernorm (coalesced) + transpose to (b*l, c)
    layernorm_v2_kernel<<<dim3(HW / 32, BATCH), 256>>>(s->h2, ln_g, ln_b, s->t);
    // 8) in_proj GEMM (xs rows + res transposed)
    gemm_inproj_kernel<<<dim3(BATCH * LSEQ / 128, 4), 256>>>(
        s->t, in_proj_w, s->xrx, s->resT);
    // 9) depthwise conv1d + silu
    conv1d_silu_T_kernel<<<dim3(LSEQ / 32, DIN / 32, BATCH), 256>>>(
        s->xrx, s->wpack, conv1d_b, s->xs, s->xsT);
    // 10) delta GEMM (softplus + transpose)
    gemm_delta_kernel<<<dim3(BATCH * LSEQ / 128, 2), 256>>>(
        s->xs, s->weff, dt_proj_b, s->deltaT);
    // 11) B/C GEMM (M-tile 64)
    gemm_bc_kernel<<<BATCH * LSEQ / 64, 256>>>(s->xs, x_proj_w, s->bc);
    // 12) chunked selective scan (vectorized broadcast loads)
    scan_p1_kernel<<<(NCH - 1) * 64, 256>>>(
        s->deltaT, s->xsT, s->bc, s->negA, s->chA, s->chH);
    scan_p2_kernel<<<NPAIR * DSTATE / 256, 256>>>(s->chA, s->chH, s->hst);
    scan_p3_kernel<<<NCH * 64, 256>>>(
        s->deltaT, s->xsT, s->bc, s->negA, Dp, s->hst, s->resT, s->gatedT);
    // 13) out_proj GEMM (M-tile 64) + NCHW store
    gemm_out_kernel<<<BATCH * LSEQ / 64, 256>>>(s->gatedT, out_proj_w, out);
}

// round 14
// speedup vs baseline: 1.3834x; 1.1123x over previous
#include <cuda_runtime.h>
#include <cuda_bf16.h>
#include <cstdint>
#include <cstddef>

#define BATCH 4
#define DIM   128
#define DIN   256
#define HH    64
#define WW    64
#define HW    4096
#define LSEQ  4096
#define DSTATE 16
#define DTRANK 8
#define EPSV  1e-5f
#define SLOPE 0.01f

#define NCH   8
#define CHLEN (LSEQ/NCH)
#define NPAIR (BATCH*DIN)

typedef unsigned long long ull;

__device__ __forceinline__ ull pack2(float lo, float hi) {
    ull r; asm("mov.b64 %0, {%1, %2};" : "=l"(r) : "f"(lo), "f"(hi)); return r;
}
__device__ __forceinline__ void unpack2(ull p, float& lo, float& hi) {
    asm("mov.b64 {%0, %1}, %2;" : "=f"(lo), "=f"(hi) : "l"(p));
}
__device__ __forceinline__ ull ffma2(ull a, ull b, ull c) {
    ull d; asm("fma.rn.f32x2 %0, %1, %2, %3;" : "=l"(d) : "l"(a), "l"(b), "l"(c)); return d;
}
__device__ __forceinline__ float softplus_f(float x) {
    return (x > 20.f) ? x : log1pf(expf(x));
}
__device__ __forceinline__ uint32_t saddr(const void* p) {
    return (uint32_t)__cvta_generic_to_shared(p);
}
__device__ __forceinline__ void cpa4(uint32_t dst, const void* src) {
    asm volatile("cp.async.ca.shared.global [%0], [%1], 4;" :: "r"(dst), "l"(src));
}
__device__ __forceinline__ void cpa16(uint32_t dst, const void* src) {
    asm volatile("cp.async.cg.shared.global [%0], [%1], 16;" :: "r"(dst), "l"(src));
}

#define W1ELEMS (DIM * 9 * DIN)
#define W2ELEMS (DIN * 9 * DIM)

// ---------------- scratch ----------------
struct Scratch {
    float h1[2 * BATCH * DIN * HW];
    float h2[4 * BATCH * DIM * HW];
    float t [BATCH * LSEQ * DIM];
    float xrx[BATCH * LSEQ * DIN];
    float resT[NPAIR * LSEQ];
    float xs[BATCH * LSEQ * DIN];
    float xsT[NPAIR * LSEQ];
    float deltaT[NPAIR * LSEQ];
    float gatedT[NPAIR * LSEQ];
    float bc[BATCH * LSEQ * 2*DSTATE];
    float weff[DIN * DIN];
    float negA[DIN * DSTATE];
    float4 wpack[DIN];
    float wd1[W1ELEMS];
    float wd2[W2ELEMS];
    float chA[(NCH-1) * NPAIR * DSTATE];
    float chH[(NCH-1) * NPAIR * DSTATE];
    float hst[NCH * NPAIR * DSTATE];
};
__device__ Scratch g_scratch;

// ---------------- precompute kernels (3 launches; conv1 stays at slot 3) ---------
__global__ void negA_wpack_kernel(const float* __restrict__ A_log, float* __restrict__ negA,
                                  const float* __restrict__ w1d, float4* __restrict__ wp)
{
    if (blockIdx.x < 16) {
        int i = blockIdx.x * 256 + threadIdx.x;
        negA[i] = -expf(A_log[i]);
    } else {
        int d = threadIdx.x;
        wp[d] = make_float4(w1d[4*d], w1d[4*d+1], w1d[4*d+2], w1d[4*d+3]);
    }
}
__global__ __launch_bounds__(256)
void weff_kernel(const float* __restrict__ xw, const float* __restrict__ dtw,
                 float* __restrict__ weff)
{
    int k = blockIdx.x, d = threadIdx.x;
    float acc = 0.f;
#pragma unroll
    for (int r = 0; r < DTRANK; r++)
        acc = fmaf(xw[k * 40 + r], dtw[r * DIN + d], acc);
    weff[k * DIN + d] = acc;
}
__global__ __launch_bounds__(256)
void wdup_kernel(const float* __restrict__ w1, const float* __restrict__ w2,
                 float* __restrict__ wd1, float* __restrict__ wd2)
{
    int i = blockIdx.x * 256 + threadIdx.x;
    if (i < W1ELEMS) {
        int oc = i % DIN; int rest = i / DIN;
        int tap = rest % 9; int ci = rest / 9;
        wd1[i] = w1[((size_t)oc * DIM + ci) * 9 + tap];
    } else if (i < W1ELEMS + W2ELEMS) {
        int j = i - W1ELEMS;
        int oc = j % DIM; int rest = j / DIM;
        int tap = rest % 9; int ci = rest / 9;
        wd2[j] = w2[((size_t)oc * DIN + ci) * 9 + tap];
    }
}

// ---------------- conv v10 (exact R12 form) ---------------------------------------
template<int CIN, int COUT, int SPLIT>
__global__ __launch_bounds__(256, 2)
void conv3x3_v10_kernel(const float* __restrict__ x, const float* __restrict__ wd,
                        float* __restrict__ out)
{
    constexpr int OCPB = 8, CIC = 2, CSPAN = CIN / SPLIT;
    constexpr int NCHUNK = CSPAN / CIC;
    __shared__ float4 sx4[2][CIC * 18 * 36];
    __shared__ float4 swt[2][CIC * 9 * 2];

    const int tid = threadIdx.x;
    const int tx = tid & 31, ty = tid >> 5;
    const int bx0 = blockIdx.x * 32;
    const int bz = blockIdx.z;
    constexpr int OCB = COUT / OCPB;
    const int b    = bz / (OCB * SPLIT);
    const int r    = bz % (OCB * SPLIT);
    const int oc0  = (r / SPLIT) * OCPB;
    const int part = r % SPLIT;
    const int cbase = part * CSPAN;
    const float* xb = x + (size_t)b * CIN * HW;
    float* out_part = out + (size_t)part * BATCH * COUT * HW;

    for (int i = tid; i < 2 * CIC * 18 * 36; i += 256)
        ((float4*)sx4)[i] = make_float4(0.f, 0.f, 0.f, 0.f);
    __syncthreads();

    auto load_chunk = [&](int buf, int c0) {
        for (int rr = ty; rr < CIC * 18; rr += 8) {
            int ci = (rr >= 18) ? 1 : 0;
            int p  = rr - 18 * ci;
            int gr = p - 1;
#pragma unroll
            for (int s = 0; s < 2; s++) {
                int xx = tx + 32 * s;
                if (xx < 34) {
                    int gx = bx0 + xx - 1;
                    if ((unsigned)gx < (unsigned)WW) {
                        const float* pc = xb + (size_t)(cbase + c0 + ci) * HW + gx;
                        uint32_t dst = saddr(&sx4[buf][rr * 36 + xx]);
                        if (p > 0)  cpa4(dst + 0,  pc + (size_t)gr * WW);
                        cpa4(dst + 4,  pc + (size_t)(gr + 16) * WW);
                        cpa4(dst + 8,  pc + (size_t)(gr + 32) * WW);
                        if (p < 17) cpa4(dst + 12, pc + (size_t)(gr + 48) * WW);
                    }
                }
            }
        }
        if (tid < CIC * 9 * 2) {
            int q = tid & 1;
            int rowi = tid >> 1;
            int ci = (rowi >= 9) ? 1 : 0;
            int tap = rowi - 9 * ci;
            const float* src = wd + ((size_t)(cbase + c0 + ci) * 9 + tap) * COUT + oc0 + 4 * q;
            cpa16(saddr(&swt[buf][rowi * 2 + q]), src);
        }
    };

    ull acc[OCPB][4];
#pragma unroll
    for (int i = 0; i < OCPB; i++)
#pragma unroll
        for (int q = 0; q < 4; q++) acc[i][q] = 0ull;

    load_chunk(0, 0);
    asm volatile("cp.async.commit_group;");

    for (int ch = 0; ch < NCHUNK; ch++) {
        const int cur = ch & 1;
        if (ch + 1 < NCHUNK) {
            load_chunk(cur ^ 1, (ch + 1) * CIC);
            asm volatile("cp.async.commit_group;");
            asm volatile("cp.async.wait_group 1;");
        } else {
            asm volatile("cp.async.wait_group 0;");
        }
        __syncthreads();

        const float4* sxb = sx4[cur];
        const float4* swb = swt[cur];
#pragma unroll
        for (int ci = 0; ci < CIC; ci++) {
#pragma unroll
            for (int tap = 0; tap < 9; tap++) {
                const int ti = tap / 3, tj = tap % 3;
                ulonglong2 A = *(const ulonglong2*)&sxb[(ci * 18 + ty + ti) * 36 + tx + tj];
                ulonglong2 C = *(const ulonglong2*)&sxb[(ci * 18 + ty + 8 + ti) * 36 + tx + tj];
                float4 wa = swb[(ci * 9 + tap) * 2 + 0];
                {
                    ull w0 = pack2(wa.x, wa.x), w1 = pack2(wa.y, wa.y);
                    ull w2 = pack2(wa.z, wa.z), w3 = pack2(wa.w, wa.w);
                    acc[0][0] = ffma2(A.x, w0, acc[0][0]); acc[0][1] = ffma2(A.y, w0, acc[0][1]);
                    acc[0][2] = ffma2(C.x, w0, acc[0][2]); acc[0][3] = ffma2(C.y, w0, acc[0][3]);
                    acc[1][0] = ffma2(A.x, w1, acc[1][0]); acc[1][1] = ffma2(A.y, w1, acc[1][1]);
                    acc[1][2] = ffma2(C.x, w1, acc[1][2]); acc[1][3] = ffma2(C.y, w1, acc[1][3]);
                    acc[2][0] = ffma2(A.x, w2, acc[2][0]); acc[2][1] = ffma2(A.y, w2, acc[2][1]);
                    acc[2][2] = ffma2(C.x, w2, acc[2][2]); acc[2][3] = ffma2(C.y, w2, acc[2][3]);
                    acc[3][0] = ffma2(A.x, w3, acc[3][0]); acc[3][1] = ffma2(A.y, w3, acc[3][1]);
                    acc[3][2] = ffma2(C.x, w3, acc[3][2]); acc[3][3] = ffma2(C.y, w3, acc[3][3]);
                }
                float4 wb = swb[(ci * 9 + tap) * 2 + 1];
                {
                    ull w4 = pack2(wb.x, wb.x), w5 = pack2(wb.y, wb.y);
                    ull w6 = pack2(wb.z, wb.z), w7 = pack2(wb.w, wb.w);
                    acc[4][0] = ffma2(A.x, w4, acc[4][0]); acc[4][1] = ffma2(A.y, w4, acc[4][1]);
                    acc[4][2] = ffma2(C.x, w4, acc[4][2]); acc[4][3] = ffma2(C.y, w4, acc[4][3]);
                    acc[5][0] = ffma2(A.x, w5, acc[5][0]); acc[5][1] = ffma2(A.y, w5, acc[5][1]);
                    acc[5][2] = ffma2(C.x, w5, acc[5][2]); acc[5][3] = ffma2(C.y, w5, acc[5][3]);
                    acc[6][0] = ffma2(A.x, w6, acc[6][0]); acc[6][1] = ffma2(A.y, w6, acc[6][1]);
                    acc[6][2] = ffma2(C.x, w6, acc[6][2]); acc[6][3] = ffma2(C.y, w6, acc[6][3]);
                    acc[7][0] = ffma2(A.x, w7, acc[7][0]); acc[7][1] = ffma2(A.y, w7, acc[7][1]);
                    acc[7][2] = ffma2(C.x, w7, acc[7][2]); acc[7][3] = ffma2(C.y, w7, acc[7][3]);
                }
            }
        }
        __syncthreads();
    }

    float* ob = out_part + (size_t)b * COUT * HW;
#pragma unroll
    for (int oc = 0; oc < OCPB; oc++) {
        float r0, r16, r32, r48, r8, r24, r40, r56;
        unpack2(acc[oc][0], r0,  r16);
        unpack2(acc[oc][1], r32, r48);
        unpack2(acc[oc][2], r8,  r24);
        unpack2(acc[oc][3], r40, r56);
        size_t base = ((size_t)(oc0 + oc) * HH) * WW + bx0 + tx;
        ob[base + (size_t)(ty)      * WW] = r0;
        ob[base + (size_t)(ty + 8)  * WW] = r8;
        ob[base + (size_t)(ty + 16) * WW] = r16;
        ob[base + (size_t)(ty + 24) * WW] = r24;
        ob[base + (size_t)(ty + 32) * WW] = r32;
        ob[base + (size_t)(ty + 40) * WW] = r40;
        ob[base + (size_t)(ty + 48) * WW] = r48;
        ob[base + (size_t)(ty + 56) * WW] = r56;
    }
}

// ---------------- instance norm + leaky, sums NPART split-K partials + bias -------
template<int NPART>
__global__ __launch_bounds__(256)
void inorm_lrelu_kernel(const float* __restrict__ in, size_t pstride,
                        const float* __restrict__ bias, int C,
                        float* __restrict__ out, const float* __restrict__ resid)
{
    __shared__ float s1[256], s2[256];
    const size_t base = (size_t)blockIdx.x * HW;
    const int c = blockIdx.x % C;
    const float bv = bias[c];
    const float* p = in + base;
    float v[16];
    float sum = 0.f, sq = 0.f;
#pragma unroll
    for (int i = 0; i < 16; i++) {
        int off = threadIdx.x + i * 256;
        float acc = bv + p[off];
        if (NPART >= 2) acc += p[pstride + off];
        if (NPART >= 3) acc += p[2 * pstride + off];
        if (NPART >= 4) acc += p[3 * pstride + off];
        v[i] = acc;
        sum += acc; sq += acc * acc;
    }
    s1[threadIdx.x] = sum; s2[threadIdx.x] = sq;
    __syncthreads();
    for (int off = 128; off; off >>= 1) {
        if (threadIdx.x < off) {
            s1[threadIdx.x] += s1[threadIdx.x + off];
            s2[threadIdx.x] += s2[threadIdx.x + off];
        }
        __syncthreads();
    }
    float mean = s1[0] * (1.f / HW);
    float var  = s2[0] * (1.f / HW) - mean * mean;
    float rstd = rsqrtf(var + EPSV);
    float* o = out + base;
    const float* rr = resid ? resid + base : nullptr;
#pragma unroll
    for (int i = 0; i < 16; i++) {
        float xv = v[i];
        float lr = xv > 0.f ? xv : SLOPE * xv;
        float val = (xv - mean) * rstd + lr;
        if (rr) val += rr[threadIdx.x + i * 256];
        o[threadIdx.x + i * 256] = val;
    }
}

// ---------------- layernorm over channels, coalesced via smem transpose ----------
__global__ __launch_bounds__(256)
void layernorm_v2_kernel(const float* __restrict__ h, const float* __restrict__ g,
                         const float* __restrict__ beta, float* __restrict__ t)
{
    __shared__ float sv[DIM][33];
    __shared__ float ps[8][33], ps2[8][33];
    __shared__ float smean[32], srstd[32];
    const int tx = threadIdx.x & 31, ty = threadIdx.x >> 5;
    const int l0 = blockIdx.x * 32, b = blockIdx.y;
    const float* hb = h + (size_t)b * DIM * HW + l0;

    for (int c = ty; c < DIM; c += 8)
        sv[c][tx] = hb[(size_t)c * HW + tx];
    __syncthreads();

    float sum = 0.f, sq = 0.f;
#pragma unroll
    for (int i = 0; i < 16; i++) {
        float v = sv[ty * 16 + i][tx];
        sum += v; sq += v * v;
    }
    ps[ty][tx] = sum; ps2[ty][tx] = sq;
    __syncthreads();
    if (ty == 0) {
        float s = 0.f, s2 = 0.f;
#pragma unroll
        for (int w = 0; w < 8; w++) { s += ps[w][tx]; s2 += ps2[w][tx]; }
        float mean = s * (1.f / DIM);
        float var  = s2 * (1.f / DIM) - mean * mean;
        smean[tx] = mean;
        srstd[tx] = rsqrtf(var + EPSV);
    }
    __syncthreads();

#pragma unroll
    for (int cc = 0; cc < 4; cc++) {
        int c = tx + 32 * cc;
        float gv = g[c], bv = beta[c];
        for (int l = ty; l < 32; l += 8) {
            float m = smean[l], rs = srstd[l];
            t[((size_t)(b * LSEQ + l0 + l)) * DIM + c] = (sv[c][l] - m) * rs * gv + bv;
        }
    }
}

// ---------------- in_proj GEMM (software-pipelined loads) ------------------------
__global__ __launch_bounds__(256)
void gemm_inproj_kernel(const float* __restrict__ A, const float* __restrict__ Bw,
                        float* __restrict__ xrx, float* __restrict__ resT)
{
    __shared__ ull   As2[8][128];
    __shared__ float Bs[8][128];
    __shared__ float sT[32][129];
    const int tid = threadIdx.x;
    const int tm = tid >> 4, tn = tid & 15;
    const int m0 = blockIdx.x * 128, n0 = blockIdx.y * 128;
    const int K = DIM, N = 2 * DIN;
    ull acc[8][4];
#pragma unroll
    for (int i = 0; i < 8; i++)
#pragma unroll
        for (int j = 0; j < 4; j++) acc[i][j] = 0ull;
    const int ar = tid >> 1, ak = (tid & 1) * 4;
    const int bk = tid >> 5, bn = (tid & 31) * 4;
    float4 av = *(const float4*)(A + (size_t)(m0 + ar) * K + ak);
    float4 bv = *(const float4*)(Bw + (size_t)bk * N + n0 + bn);
    for (int k0 = 0; k0 < K; k0 += 8) {
        __syncthreads();
        As2[ak + 0][ar] = pack2(av.x, av.x);
        As2[ak + 1][ar] = pack2(av.y, av.y);
        As2[ak + 2][ar] = pack2(av.z, av.z);
        As2[ak + 3][ar] = pack2(av.w, av.w);
        *(float4*)&Bs[bk][bn] = bv;
        __syncthreads();
        if (k0 + 8 < K) {
            av = *(const float4*)(A + (size_t)(m0 + ar) * K + k0 + 8 + ak);
            bv = *(const float4*)(Bw + (size_t)(k0 + 8 + bk) * N + n0 + bn);
        }
#pragma unroll
        for (int k = 0; k < 8; k++) {
            ull a2[8], b2[4];
#pragma unroll
            for (int i = 0; i < 8; i++) a2[i] = As2[k][tm * 8 + i];
#pragma unroll
            for (int j = 0; j < 4; j++) b2[j] = *(const ull*)&Bs[k][tn * 2 + 32 * j];
#pragma unroll
            for (int i = 0; i < 8; i++)
#pragma unroll
                for (int j = 0; j < 4; j++)
                    acc[i][j] = ffma2(a2[i], b2[j], acc[i][j]);
        }
    }
    if (n0 < DIN) {
#pragma unroll
        for (int i = 0; i < 8; i++) {
            int row = m0 + tm * 8 + i;
#pragma unroll
            for (int j = 0; j < 4; j++) {
                float lo, hi; unpack2(acc[i][j], lo, hi);
                *(float2*)(xrx + (size_t)row * DIN + n0 + tn * 2 + 32 * j) = make_float2(lo, hi);
            }
        }
    } else {
        const int b = m0 >> 12, t0 = m0 & 4095, d0 = n0 - DIN;
#pragma unroll
        for (int j = 0; j < 4; j++) {
            __syncthreads();
#pragma unroll
            for (int i = 0; i < 8; i++) {
                int rl = tm * 8 + i;
                float lo, hi; unpack2(acc[i][j], lo, hi);
                sT[2 * tn][rl]     = lo;
                sT[2 * tn + 1][rl] = hi;
            }
            __syncthreads();
            int col = tid >> 3, r0 = (tid & 7) * 16;
            float* dst = resT + ((size_t)(b * DIN + d0 + 32 * j + col)) * LSEQ + t0 + r0;
#pragma unroll
            for (int k = 0; k < 16; k++) dst[k] = sT[col][r0 + k];
        }
    }
}

// ---------------- delta GEMM (software-pipelined loads) --------------------------
__global__ __launch_bounds__(256)
void gemm_delta_kernel(const float* __restrict__ A, const float* __restrict__ Bw,
                       const float* __restrict__ dtb, float* __restrict__ deltaT)
{
    __shared__ ull   As2[8][128];
    __shared__ float Bs[8][128];
    __shared__ float sT[32][129];
    const int tid = threadIdx.x;
    const int tm = tid >> 4, tn = tid & 15;
    const int m0 = blockIdx.x * 128, n0 = blockIdx.y * 128;
    const int K = DIN, N = DIN;
    ull acc[8][4];
#pragma unroll
    for (int i = 0; i < 8; i++)
#pragma unroll
        for (int j = 0; j < 4; j++) acc[i][j] = 0ull;
    const int ar = tid >> 1, ak = (tid & 1) * 4;
    const int bk = tid >> 5, bn = (tid & 31) * 4;
    float4 av = *(const float4*)(A + (size_t)(m0 + ar) * K + ak);
    float4 bv = *(const float4*)(Bw + (size_t)bk * N + n0 + bn);
    for (int k0 = 0; k0 < K; k0 += 8) {
        __syncthreads();
        As2[ak + 0][ar] = pack2(av.x, av.x);
        As2[ak + 1][ar] = pack2(av.y, av.y);
        As2[ak + 2][ar] = pack2(av.z, av.z);
        As2[ak + 3][ar] = pack2(av.w, av.w);
        *(float4*)&Bs[bk][bn] = bv;
        __syncthreads();
        if (k0 + 8 < K) {
            av = *(const float4*)(A + (size_t)(m0 + ar) * K + k0 + 8 + ak);
            bv = *(const float4*)(Bw + (size_t)(k0 + 8 + bk) * N + n0 + bn);
        }
#pragma unroll
        for (int k = 0; k < 8; k++) {
            ull a2[8], b2[4];
#pragma unroll
            for (int i = 0; i < 8; i++) a2[i] = As2[k][tm * 8 + i];
#pragma unroll
            for (int j = 0; j < 4; j++) b2[j] = *(const ull*)&Bs[k][tn * 2 + 32 * j];
#pragma unroll
            for (int i = 0; i < 8; i++)
#pragma unroll
                for (int j = 0; j < 4; j++)
                    acc[i][j] = ffma2(a2[i], b2[j], acc[i][j]);
        }
    }
    const int b = m0 >> 12, t0 = m0 & 4095;
#pragma unroll
    for (int j = 0; j < 4; j++) {
        __syncthreads();
        float blo = dtb[n0 + 32 * j + 2 * tn];
        float bhi = dtb[n0 + 32 * j + 2 * tn + 1];
#pragma unroll
        for (int i = 0; i < 8; i++) {
            int rl = tm * 8 + i;
            float lo, hi; unpack2(acc[i][j], lo, hi);
            sT[2 * tn][rl]     = softplus_f(lo + blo);
            sT[2 * tn + 1][rl] = softplus_f(hi + bhi);
        }
        __syncthreads();
        int col = tid >> 3, r0 = (tid & 7) * 16;
        float* dst = deltaT + ((size_t)(b * DIN + n0 + 32 * j + col)) * LSEQ + t0 + r0;
#pragma unroll
        for (int k = 0; k < 16; k++) dst[k] = sT[col][r0 + k];
    }
}

// ---------------- BC GEMM: M-tile 64, software-pipelined -------------------------
__global__ __launch_bounds__(256)
void gemm_bc_kernel(const float* __restrict__ A, const float* __restrict__ xw,
                    float* __restrict__ bc)
{
    __shared__ ull   As2[16][64];
    __shared__ float Bs[16][32];
    const int tid = threadIdx.x;
    const int tm = tid >> 4, tn = tid & 15;
    const int m0 = blockIdx.x * 64;
    ull acc[4];
#pragma unroll
    for (int i = 0; i < 4; i++) acc[i] = 0ull;
    const int ar = tid >> 2, aq = (tid & 3) * 4;
    float4 a1 = *(const float4*)(A + (size_t)(m0 + ar) * DIN + aq);
    float bvv[2];
#pragma unroll
    for (int q = 0; q < 2; q++) {
        int idx = tid + q * 256;
        bvv[q] = xw[(size_t)(idx >> 5) * 40 + 8 + (idx & 31)];
    }
    for (int k0 = 0; k0 < DIN; k0 += 16) {
        __syncthreads();
        As2[aq + 0][ar] = pack2(a1.x, a1.x);
        As2[aq + 1][ar] = pack2(a1.y, a1.y);
        As2[aq + 2][ar] = pack2(a1.z, a1.z);
        As2[aq + 3][ar] = pack2(a1.w, a1.w);
#pragma unroll
        for (int q = 0; q < 2; q++) {
            int idx = tid + q * 256;
            Bs[idx >> 5][idx & 31] = bvv[q];
        }
        __syncthreads();
        if (k0 + 16 < DIN) {
            a1 = *(const float4*)(A + (size_t)(m0 + ar) * DIN + k0 + 16 + aq);
#pragma unroll
            for (int q = 0; q < 2; q++) {
                int idx = tid + q * 256;
                bvv[q] = xw[(size_t)(k0 + 16 + (idx >> 5)) * 40 + 8 + (idx & 31)];
            }
        }
#pragma unroll
        for (int k = 0; k < 16; k++) {
            ull b2 = *(const ull*)&Bs[k][2 * tn];
#pragma unroll
            for (int i = 0; i < 4; i++)
                acc[i] = ffma2(As2[k][tm * 4 + i], b2, acc[i]);
        }
    }
#pragma unroll
    for (int i = 0; i < 4; i++) {
        int row = m0 + tm * 4 + i;
        float lo, hi; unpack2(acc[i], lo, hi);
        *(float2*)(bc + (size_t)row * 32 + 2 * tn) = make_float2(lo, hi);
    }
}

// ---------------- out_proj GEMM: M-tile 64, software-pipelined -------------------
__global__ __launch_bounds__(256)
void gemm_out_kernel(const float* __restrict__ gatedT, const float* __restrict__ Bw,
                     float* __restrict__ out)
{
    __shared__ ull   As2[8][64];
    __shared__ float Bs[8][128];
    __shared__ float sT[32][65];
    const int tid = threadIdx.x;
    const int tm = tid >> 4, tn = tid & 15;
    const int m0 = blockIdx.x * 64;
    const int K = DIN, N = DIM;
    const int b = m0 >> 12, t0 = m0 & 4095;
    ull acc[4][4];
#pragma unroll
    for (int i = 0; i < 4; i++)
#pragma unroll
        for (int j = 0; j < 4; j++) acc[i][j] = 0ull;
    const int kk = tid >> 5, tl = tid & 31;
    const int bk = tid >> 5, bn = (tid & 31) * 4;
    float gv[2];
#pragma unroll
    for (int it = 0; it < 2; it++)
        gv[it] = gatedT[((size_t)(b * DIN + kk)) * LSEQ + t0 + tl + 32 * it];
    float4 bv = *(const float4*)(Bw + (size_t)bk * N + bn);
    for (int k0 = 0; k0 < K; k0 += 8) {
        __syncthreads();
#pragma unroll
        for (int it = 0; it < 2; it++)
            As2[kk][tl + 32 * it] = pack2(gv[it], gv[it]);
        *(float4*)&Bs[bk][bn] = bv;
        __syncthreads();
        if (k0 + 8 < K) {
            int d = k0 + 8 + kk;
#pragma unroll
            for (int it = 0; it < 2; it++)
                gv[it] = gatedT[((size_t)(b * DIN + d)) * LSEQ + t0 + tl + 32 * it];
            bv = *(const float4*)(Bw + (size_t)(k0 + 8 + bk) * N + bn);
        }
#pragma unroll
        for (int k = 0; k < 8; k++) {
            ull a2[4], b2[4];
#pragma unroll
            for (int i = 0; i < 4; i++) a2[i] = As2[k][tm * 4 + i];
#pragma unroll
            for (int j = 0; j < 4; j++) b2[j] = *(const ull*)&Bs[k][tn * 2 + 32 * j];
#pragma unroll
            for (int i = 0; i < 4; i++)
#pragma unroll
                for (int j = 0; j < 4; j++)
                    acc[i][j] = ffma2(a2[i], b2[j], acc[i][j]);
        }
    }
#pragma unroll
    for (int j = 0; j < 4; j++) {
        __syncthreads();
#pragma unroll
        for (int i = 0; i < 4; i++) {
            int rl = tm * 4 + i;
            float lo, hi; unpack2(acc[i][j], lo, hi);
            sT[2 * tn][rl]     = lo;
            sT[2 * tn + 1][rl] = hi;
        }
        __syncthreads();
        int col = tid >> 3, r0 = (tid & 7) * 8;
        float* dst = out + ((size_t)(b * DIM + 32 * j + col)) * LSEQ + t0 + r0;
#pragma unroll
        for (int k = 0; k < 8; k++) dst[k] = sT[col][r0 + k];
    }
}

// ---------------- causal depthwise conv1d (k=4) + silu, smem-staged --------------
__global__ __launch_bounds__(256)
void conv1d_silu_T_kernel(const float* __restrict__ xrx, const float4* __restrict__ wp,
                          const float* __restrict__ bias,
                          float* __restrict__ xs, float* __restrict__ xsT)
{
    __shared__ float sin_[35][32];
    __shared__ float st[32][33];
    const int tx = threadIdx.x & 31, ty = threadIdx.x >> 5;
    const int t0 = blockIdx.x * 32, d0 = blockIdx.y * 32, b = blockIdx.z;
    const int d = d0 + tx;

    // stage inputs t0-3 .. t0+31 (rows 0..34), zero left pad
    for (int r = ty; r < 35; r += 8) {
        int t = t0 - 3 + r;
        sin_[r][tx] = (t >= 0) ? xrx[((size_t)b * LSEQ + t) * DIN + d] : 0.f;
    }
    __syncthreads();

    float4 w = wp[d];
    float bv = bias[d];
#pragma unroll
    for (int k = 0; k < 4; k++) {
        int tt = ty + 8 * k;           // local output index; input rows tt..tt+3
        float acc = bv;
        acc = fmaf(w.x, sin_[tt][tx],     acc);
        acc = fmaf(w.y, sin_[tt + 1][tx], acc);
        acc = fmaf(w.z, sin_[tt + 2][tx], acc);
        acc = fmaf(w.w, sin_[tt + 3][tx], acc);
        float s = acc / (1.f + __expf(-acc));
        xs[((size_t)b * LSEQ + t0 + tt) * DIN + d] = s;
        st[tx][tt] = s;
    }
    __syncthreads();
#pragma unroll
    for (int k = 0; k < 4; k++) {
        int dd = d0 + ty + 8 * k;
        xsT[((size_t)(b * DIN + dd)) * LSEQ + t0 + tx] = st[ty + 8 * k][tx];
    }
}

// ---------------- scan pass 1 (float4 broadcast loads, NCH=8) --------------------
__global__ __launch_bounds__(256)
void scan_p1_kernel(const float* __restrict__ deltaT, const float* __restrict__ xsT,
                    const float* __restrict__ bc, const float* __restrict__ negA,
                    float* __restrict__ chA, float* __restrict__ chH)
{
    int gw = (blockIdx.x * blockDim.x + threadIdx.x) >> 5;
    int lane = threadIdx.x & 31;
    int half = lane >> 4, n = lane & 15;
    int chunk = gw >> 9;
    int wp = gw & 511;
    int pair = wp * 2 + half;
    int b = pair >> 8, d = pair & 255;
    int t0 = chunk * CHLEN;

    float A = negA[d * DSTATE + n];
    const float* dl = deltaT + (size_t)(b * DIN + d) * LSEQ + t0;
    const float* ul = xsT    + (size_t)(b * DIN + d) * LSEQ + t0;
    const float* xb = bc + ((size_t)b * LSEQ + t0) * 32;

    float h = 0.f, pA = 1.f;
    for (int tb = 0; tb < CHLEN; tb += 4) {
        float4 d4 = *(const float4*)(dl + tb);
        float4 u4 = *(const float4*)(ul + tb);
#pragma unroll
        for (int q = 0; q < 4; q++) {
            float dt = (q == 0) ? d4.x : (q == 1) ? d4.y : (q == 2) ? d4.z : d4.w;
            float ut = (q == 0) ? u4.x : (q == 1) ? u4.y : (q == 2) ? u4.z : u4.w;
            float Bn = xb[(tb + q) * 32 + n];
            float a = __expf(dt * A);
            pA *= a;
            h = fmaf(a, h, dt * ut * Bn);
        }
    }
    int idx = (chunk * NPAIR + pair) * DSTATE + n;
    chA[idx] = pA;
    chH[idx] = h;
}

// ---------------- scan pass 2 ----------------
__global__ __launch_bounds__(256)
void scan_p2_kernel(const float* __restrict__ chA, const float* __restrict__ chH,
                    float* __restrict__ hst)
{
    int i = blockIdx.x * 256 + threadIdx.x;
    float h = 0.f;
    hst[i] = 0.f;
#pragma unroll
    for (int c = 0; c < NCH - 1; c++) {
        h = fmaf(chA[c * NPAIR * DSTATE + i], h, chH[c * NPAIR * DSTATE + i]);
        hst[(c + 1) * NPAIR * DSTATE + i] = h;
    }
}

// ---------------- scan pass 3 (float4 broadcast loads, NCH=8) --------------------
__global__ __launch_bounds__(256)
void scan_p3_kernel(const float* __restrict__ deltaT, const float* __restrict__ xsT,
                    const float* __restrict__ bc, const float* __restrict__ negA,
                    const float* __restrict__ Dp, const float* __restrict__ hst,
                    const float* __restrict__ resT, float* __restrict__ gatedT)
{
    __shared__ float sy[8][2][32];
    int gw = (blockIdx.x * blockDim.x + threadIdx.x) >> 5;
    int lane = threadIdx.x & 31;
    int wslot = threadIdx.x >> 5;
    int half = lane >> 4, n = lane & 15;
    int chunk = gw >> 9;
    int wp = gw & 511;
    int pair = wp * 2 + half;
    int b = pair >> 8, d = pair & 255;
    int t0 = chunk * CHLEN;

    float A = negA[d * DSTATE + n];
    const float* dl = deltaT + (size_t)(b * DIN + d) * LSEQ + t0;
    const float* ul = xsT    + (size_t)(b * DIN + d) * LSEQ + t0;
    const float* xb = bc + ((size_t)b * LSEQ + t0) * 32;
    float h = hst[(chunk * NPAIR + pair) * DSTATE + n];

    int dp0 = (wp * 2) & 255;
    int bb  = (wp * 2) >> 8;
    float Dv0 = Dp[dp0], Dv1 = Dp[dp0 + 1];
    const float* u0p = xsT + (size_t)(bb * DIN + dp0)     * LSEQ + t0;
    const float* u1p = xsT + (size_t)(bb * DIN + dp0 + 1) * LSEQ + t0;
    const float* r0p = resT + (size_t)(bb * DIN + dp0)     * LSEQ + t0;
    const float* r1p = resT + (size_t)(bb * DIN + dp0 + 1) * LSEQ + t0;
    float* y0p = gatedT + (size_t)(bb * DIN + dp0)     * LSEQ + t0;
    float* y1p = gatedT + (size_t)(bb * DIN + dp0 + 1) * LSEQ + t0;

    for (int tb = 0; tb < CHLEN; tb += 32) {
        for (int tq = 0; tq < 32; tq += 4) {
            float4 d4 = *(const float4*)(dl + tb + tq);
            float4 u4 = *(const float4*)(ul + tb + tq);
#pragma unroll
            for (int q = 0; q < 4; q++) {
                int t = tb + tq + q;
                float dt = (q == 0) ? d4.x : (q == 1) ? d4.y : (q == 2) ? d4.z : d4.w;
                float ut = (q == 0) ? u4.x : (q == 1) ? u4.y : (q == 2) ? u4.z : u4.w;
                float Bn  = xb[t * 32 + n];
                float Cn  = xb[t * 32 + 16 + n];
                float a = __expf(dt * A);
                h = fmaf(a, h, dt * ut * Bn);
                float yv = h * Cn;
                yv += __shfl_xor_sync(0xffffffffu, yv, 8);
                yv += __shfl_xor_sync(0xffffffffu, yv, 4);
                yv += __shfl_xor_sync(0xffffffffu, yv, 2);
                yv += __shfl_xor_sync(0xffffffffu, yv, 1);
                if (n == 0) sy[wslot][half][tq + q] = yv;
            }
        }
        __syncwarp();
        float r0 = r0p[tb + lane];
        float r1 = r1p[tb + lane];
        float s0 = r0 / (1.f + __expf(-r0));
        float s1 = r1 / (1.f + __expf(-r1));
        y0p[tb + lane] = fmaf(u0p[tb + lane], Dv0, sy[wslot][0][lane]) * s0;
        y1p[tb + lane] = fmaf(u1p[tb + lane], Dv1, sy[wslot][1][lane]) * s1;
        __syncwarp();
    }
}

// ---------------- launch ----------------
extern "C" void kernel_launch(void* const* d_in, const int* in_sizes, int n_in,
                              void* d_out, int out_size)
{
    const float* x         = (const float*)d_in[0];
    const float* conv1_w   = (const float*)d_in[1];
    const float* conv1_b   = (const float*)d_in[2];
    const float* conv2_w   = (const float*)d_in[3];
    const float* conv2_b   = (const float*)d_in[4];
    const float* ln_g      = (const float*)d_in[5];
    const float* ln_b      = (const float*)d_in[6];
    const float* in_proj_w = (const float*)d_in[7];
    const float* conv1d_w  = (const float*)d_in[8];
    const float* conv1d_b  = (const float*)d_in[9];
    const float* x_proj_w  = (const float*)d_in[10];
    const float* dt_proj_w = (const float*)d_in[11];
    const float* dt_proj_b = (const float*)d_in[12];
    const float* A_log     = (const float*)d_in[13];
    const float* Dp        = (const float*)d_in[14];
    const float* out_proj_w= (const float*)d_in[15];
    float* out = (float*)d_out;

    Scratch* s = nullptr;
    cudaGetSymbolAddress((void**)&s, g_scratch);

    const size_t p1stride = (size_t)BATCH * DIN * HW;
    const size_t p2stride = (size_t)BATCH * DIM * HW;

    // 0-2) precompute (conv1 stays at profiled slot 3)
    negA_wpack_kernel<<<17, 256>>>(A_log, s->negA, conv1d_w, s->wpack);
    weff_kernel<<<DIN, DIN>>>(x_proj_w, dt_proj_w, s->weff);
    wdup_kernel<<<(W1ELEMS + W2ELEMS + 255) / 256, 256>>>(conv1_w, conv2_w, s->wd1, s->wd2);
    // 3) conv1 split-K x2
    conv3x3_v10_kernel<DIM, DIN, 2><<<dim3(2, 1, BATCH * (DIN / 8) * 2), 256>>>(
        x, s->wd1, s->h1);
    // 4) inorm (sums 2 partials + bias) + leaky
    inorm_lrelu_kernel<2><<<BATCH * DIN, 256>>>(s->h1, p1stride, conv1_b, DIN, s->h1, nullptr);
    // 5) conv2 split-K x4
    conv3x3_v10_kernel<DIN, DIM, 4><<<dim3(2, 1, BATCH * (DIM / 8) * 4), 256>>>(
        s->h1, s->wd2, s->h2);
    // 6) inorm (sums 4 partials + bias) + leaky + residual
    inorm_lrelu_kernel<4><<<BATCH * DIM, 256>>>(s->h2, p2stride, conv2_b, DIM, s->h2, x);
    // 7) layernorm (coalesced) + transpose to (b*l, c)
    layernorm_v2_kernel<<<dim3(HW / 32, BATCH), 256>>>(s->h2, ln_g, ln_b, s->t);
    // 8) in_proj GEMM (xs rows + res transposed)
    gemm_inproj_kernel<<<dim3(BATCH * LSEQ / 128, 4), 256>>>(
        s->t, in_proj_w, s->xrx, s->resT);
    // 9) depthwise conv1d + silu (smem-staged)
    conv1d_silu_T_kernel<<<dim3(LSEQ / 32, DIN / 32, BATCH), 256>>>(
        s->xrx, s->wpack, conv1d_b, s->xs, s->xsT);
    // 10) delta GEMM (softplus + transpose)
    gemm_delta_kernel<<<dim3(BATCH * LSEQ / 128, 2), 256>>>(
        s->xs, s->weff, dt_proj_b, s->deltaT);
    // 11) B/C GEMM (M-tile 64)
    gemm_bc_kernel<<<BATCH * LSEQ / 64, 256>>>(s->xs, x_proj_w, s->bc);
    // 12) chunked selective scan (NCH=8)
    scan_p1_kernel<<<(NCH - 1) * 64, 256>>>(
        s->deltaT, s->xsT, s->bc, s->negA, s->chA, s->chH);
    scan_p2_kernel<<<NPAIR * DSTATE / 256, 256>>>(s->chA, s->chH, s->hst);
    scan_p3_kernel<<<NCH * 64, 256>>>(
        s->deltaT, s->xsT, s->bc, s->negA, Dp, s->hst, s->resT, s->gatedT);
    // 13) out_proj GEMM (M-tile 64) + NCHW store
    gemm_out_kernel<<<BATCH * LSEQ / 64, 256>>>(s->gatedT, out_proj_w, out);
}

// round 16
// speedup vs baseline: 1.3980x; 1.0105x over previous
#include <cuda_runtime.h>
#include <cuda_bf16.h>
#include <cstdint>
#include <cstddef>

#define BATCH 4
#define DIM   128
#define DIN   256
#define HH    64
#define WW    64
#define HW    4096
#define LSEQ  4096
#define DSTATE 16
#define DTRANK 8
#define EPSV  1e-5f
#define SLOPE 0.01f

#define NCH   16
#define CHLEN (LSEQ/NCH)
#define NPAIR (BATCH*DIN)

typedef unsigned long long ull;

__device__ __forceinline__ ull pack2(float lo, float hi) {
    ull r; asm("mov.b64 %0, {%1, %2};" : "=l"(r) : "f"(lo), "f"(hi)); return r;
}
__device__ __forceinline__ void unpack2(ull p, float& lo, float& hi) {
    asm("mov.b64 {%0, %1}, %2;" : "=f"(lo), "=f"(hi) : "l"(p));
}
__device__ __forceinline__ ull ffma2(ull a, ull b, ull c) {
    ull d; asm("fma.rn.f32x2 %0, %1, %2, %3;" : "=l"(d) : "l"(a), "l"(b), "l"(c)); return d;
}
__device__ __forceinline__ float softplus_f(float x) {
    return (x > 20.f) ? x : log1pf(expf(x));
}
__device__ __forceinline__ uint32_t saddr(const void* p) {
    return (uint32_t)__cvta_generic_to_shared(p);
}
__device__ __forceinline__ void cpa4(uint32_t dst, const void* src) {
    asm volatile("cp.async.ca.shared.global [%0], [%1], 4;" :: "r"(dst), "l"(src));
}
__device__ __forceinline__ void cpa16(uint32_t dst, const void* src) {
    asm volatile("cp.async.cg.shared.global [%0], [%1], 16;" :: "r"(dst), "l"(src));
}

#define W1ELEMS (DIM * 9 * DIN)
#define W2ELEMS (DIN * 9 * DIM)

// ---------------- scratch ----------------
struct Scratch {
    float h1[2 * BATCH * DIN * HW];
    float h2[4 * BATCH * DIM * HW];
    float t [BATCH * LSEQ * DIM];
    float xrx[BATCH * LSEQ * DIN];
    float resT[NPAIR * LSEQ];
    float xs[BATCH * LSEQ * DIN];
    float xsT[NPAIR * LSEQ];
    float deltaT[NPAIR * LSEQ];
    float gatedT[NPAIR * LSEQ];
    float bc[BATCH * LSEQ * 2*DSTATE];
    float weff[DIN * DIN];
    float negA[DIN * DSTATE];
    float4 wpack[DIN];
    float wd1[W1ELEMS];
    float wd2[W2ELEMS];
    float chA[(NCH-1) * NPAIR * DSTATE];
    float chH[(NCH-1) * NPAIR * DSTATE];
    float hst[NCH * NPAIR * DSTATE];
};
__device__ Scratch g_scratch;

// ---------------- precompute kernels (3 launches; conv1 stays at slot 3) ---------
__global__ void negA_wpack_kernel(const float* __restrict__ A_log, float* __restrict__ negA,
                                  const float* __restrict__ w1d, float4* __restrict__ wp)
{
    if (blockIdx.x < 16) {
        int i = blockIdx.x * 256 + threadIdx.x;
        negA[i] = -expf(A_log[i]);
    } else {
        int d = threadIdx.x;
        wp[d] = make_float4(w1d[4*d], w1d[4*d+1], w1d[4*d+2], w1d[4*d+3]);
    }
}
__global__ __launch_bounds__(256)
void weff_kernel(const float* __restrict__ xw, const float* __restrict__ dtw,
                 float* __restrict__ weff)
{
    int k = blockIdx.x, d = threadIdx.x;
    float acc = 0.f;
#pragma unroll
    for (int r = 0; r < DTRANK; r++)
        acc = fmaf(xw[k * 40 + r], dtw[r * DIN + d], acc);
    weff[k * DIN + d] = acc;
}
__global__ __launch_bounds__(256)
void wdup_kernel(const float* __restrict__ w1, const float* __restrict__ w2,
                 float* __restrict__ wd1, float* __restrict__ wd2)
{
    int i = blockIdx.x * 256 + threadIdx.x;
    if (i < W1ELEMS) {
        int oc = i % DIN; int rest = i / DIN;
        int tap = rest % 9; int ci = rest / 9;
        wd1[i] = w1[((size_t)oc * DIM + ci) * 9 + tap];
    } else if (i < W1ELEMS + W2ELEMS) {
        int j = i - W1ELEMS;
        int oc = j % DIM; int rest = j / DIM;
        int tap = rest % 9; int ci = rest / 9;
        wd2[j] = w2[((size_t)oc * DIN + ci) * 9 + tap];
    }
}

// ---------------- conv v10 (exact R12 form; frozen) -------------------------------
template<int CIN, int COUT, int SPLIT>
__global__ __launch_bounds__(256, 2)
void conv3x3_v10_kernel(const float* __restrict__ x, const float* __restrict__ wd,
                        float* __restrict__ out)
{
    constexpr int OCPB = 8, CIC = 2, CSPAN = CIN / SPLIT;
    constexpr int NCHUNK = CSPAN / CIC;
    __shared__ float4 sx4[2][CIC * 18 * 36];
    __shared__ float4 swt[2][CIC * 9 * 2];

    const int tid = threadIdx.x;
    const int tx = tid & 31, ty = tid >> 5;
    const int bx0 = blockIdx.x * 32;
    const int bz = blockIdx.z;
    constexpr int OCB = COUT / OCPB;
    const int b    = bz / (OCB * SPLIT);
    const int r    = bz % (OCB * SPLIT);
    const int oc0  = (r / SPLIT) * OCPB;
    const int part = r % SPLIT;
    const int cbase = part * CSPAN;
    const float* xb = x + (size_t)b * CIN * HW;
    float* out_part = out + (size_t)part * BATCH * COUT * HW;

    for (int i = tid; i < 2 * CIC * 18 * 36; i += 256)
        ((float4*)sx4)[i] = make_float4(0.f, 0.f, 0.f, 0.f);
    __syncthreads();

    auto load_chunk = [&](int buf, int c0) {
        for (int rr = ty; rr < CIC * 18; rr += 8) {
            int ci = (rr >= 18) ? 1 : 0;
            int p  = rr - 18 * ci;
            int gr = p - 1;
#pragma unroll
            for (int s = 0; s < 2; s++) {
                int xx = tx + 32 * s;
                if (xx < 34) {
                    int gx = bx0 + xx - 1;
                    if ((unsigned)gx < (unsigned)WW) {
                        const float* pc = xb + (size_t)(cbase + c0 + ci) * HW + gx;
                        uint32_t dst = saddr(&sx4[buf][rr * 36 + xx]);
                        if (p > 0)  cpa4(dst + 0,  pc + (size_t)gr * WW);
                        cpa4(dst + 4,  pc + (size_t)(gr + 16) * WW);
                        cpa4(dst + 8,  pc + (size_t)(gr + 32) * WW);
                        if (p < 17) cpa4(dst + 12, pc + (size_t)(gr + 48) * WW);
                    }
                }
            }
        }
        if (tid < CIC * 9 * 2) {
            int q = tid & 1;
            int rowi = tid >> 1;
            int ci = (rowi >= 9) ? 1 : 0;
            int tap = rowi - 9 * ci;
            const float* src = wd + ((size_t)(cbase + c0 + ci) * 9 + tap) * COUT + oc0 + 4 * q;
            cpa16(saddr(&swt[buf][rowi * 2 + q]), src);
        }
    };

    ull acc[OCPB][4];
#pragma unroll
    for (int i = 0; i < OCPB; i++)
#pragma unroll
        for (int q = 0; q < 4; q++) acc[i][q] = 0ull;

    load_chunk(0, 0);
    asm volatile("cp.async.commit_group;");

    for (int ch = 0; ch < NCHUNK; ch++) {
        const int cur = ch & 1;
        if (ch + 1 < NCHUNK) {
            load_chunk(cur ^ 1, (ch + 1) * CIC);
            asm volatile("cp.async.commit_group;");
            asm volatile("cp.async.wait_group 1;");
        } else {
            asm volatile("cp.async.wait_group 0;");
        }
        __syncthreads();

        const float4* sxb = sx4[cur];
        const float4* swb = swt[cur];
#pragma unroll
        for (int ci = 0; ci < CIC; ci++) {
#pragma unroll
            for (int tap = 0; tap < 9; tap++) {
                const int ti = tap / 3, tj = tap % 3;
                ulonglong2 A = *(const ulonglong2*)&sxb[(ci * 18 + ty + ti) * 36 + tx + tj];
                ulonglong2 C = *(const ulonglong2*)&sxb[(ci * 18 + ty + 8 + ti) * 36 + tx + tj];
                float4 wa = swb[(ci * 9 + tap) * 2 + 0];
                {
                    ull w0 = pack2(wa.x, wa.x), w1 = pack2(wa.y, wa.y);
                    ull w2 = pack2(wa.z, wa.z), w3 = pack2(wa.w, wa.w);
                    acc[0][0] = ffma2(A.x, w0, acc[0][0]); acc[0][1] = ffma2(A.y, w0, acc[0][1]);
                    acc[0][2] = ffma2(C.x, w0, acc[0][2]); acc[0][3] = ffma2(C.y, w0, acc[0][3]);
                    acc[1][0] = ffma2(A.x, w1, acc[1][0]); acc[1][1] = ffma2(A.y, w1, acc[1][1]);
                    acc[1][2] = ffma2(C.x, w1, acc[1][2]); acc[1][3] = ffma2(C.y, w1, acc[1][3]);
                    acc[2][0] = ffma2(A.x, w2, acc[2][0]); acc[2][1] = ffma2(A.y, w2, acc[2][1]);
                    acc[2][2] = ffma2(C.x, w2, acc[2][2]); acc[2][3] = ffma2(C.y, w2, acc[2][3]);
                    acc[3][0] = ffma2(A.x, w3, acc[3][0]); acc[3][1] = ffma2(A.y, w3, acc[3][1]);
                    acc[3][2] = ffma2(C.x, w3, acc[3][2]); acc[3][3] = ffma2(C.y, w3, acc[3][3]);
                }
                float4 wb = swb[(ci * 9 + tap) * 2 + 1];
                {
                    ull w4 = pack2(wb.x, wb.x), w5 = pack2(wb.y, wb.y);
                    ull w6 = pack2(wb.z, wb.z), w7 = pack2(wb.w, wb.w);
                    acc[4][0] = ffma2(A.x, w4, acc[4][0]); acc[4][1] = ffma2(A.y, w4, acc[4][1]);
                    acc[4][2] = ffma2(C.x, w4, acc[4][2]); acc[4][3] = ffma2(C.y, w4, acc[4][3]);
                    acc[5][0] = ffma2(A.x, w5, acc[5][0]); acc[5][1] = ffma2(A.y, w5, acc[5][1]);
                    acc[5][2] = ffma2(C.x, w5, acc[5][2]); acc[5][3] = ffma2(C.y, w5, acc[5][3]);
                    acc[6][0] = ffma2(A.x, w6, acc[6][0]); acc[6][1] = ffma2(A.y, w6, acc[6][1]);
                    acc[6][2] = ffma2(C.x, w6, acc[6][2]); acc[6][3] = ffma2(C.y, w6, acc[6][3]);
                    acc[7][0] = ffma2(A.x, w7, acc[7][0]); acc[7][1] = ffma2(A.y, w7, acc[7][1]);
                    acc[7][2] = ffma2(C.x, w7, acc[7][2]); acc[7][3] = ffma2(C.y, w7, acc[7][3]);
                }
            }
        }
        __syncthreads();
    }

    float* ob = out_part + (size_t)b * COUT * HW;
#pragma unroll
    for (int oc = 0; oc < OCPB; oc++) {
        float r0, r16, r32, r48, r8, r24, r40, r56;
        unpack2(acc[oc][0], r0,  r16);
        unpack2(acc[oc][1], r32, r48);
        unpack2(acc[oc][2], r8,  r24);
        unpack2(acc[oc][3], r40, r56);
        size_t base = ((size_t)(oc0 + oc) * HH) * WW + bx0 + tx;
        ob[base + (size_t)(ty)      * WW] = r0;
        ob[base + (size_t)(ty + 8)  * WW] = r8;
        ob[base + (size_t)(ty + 16) * WW] = r16;
        ob[base + (size_t)(ty + 24) * WW] = r24;
        ob[base + (size_t)(ty + 32) * WW] = r32;
        ob[base + (size_t)(ty + 40) * WW] = r40;
        ob[base + (size_t)(ty + 48) * WW] = r48;
        ob[base + (size_t)(ty + 56) * WW] = r56;
    }
}

// ---------------- instance norm + leaky, sums NPART split-K partials + bias -------
template<int NPART>
__global__ __launch_bounds__(256)
void inorm_lrelu_kernel(const float* __restrict__ in, size_t pstride,
                        const float* __restrict__ bias, int C,
                        float* __restrict__ out, const float* __restrict__ resid)
{
    __shared__ float s1[256], s2[256];
    const size_t base = (size_t)blockIdx.x * HW;
    const int c = blockIdx.x % C;
    const float bv = bias[c];
    const float* p = in + base;
    float v[16];
    float sum = 0.f, sq = 0.f;
#pragma unroll
    for (int i = 0; i < 16; i++) {
        int off = threadIdx.x + i * 256;
        float acc = bv + p[off];
        if (NPART >= 2) acc += p[pstride + off];
        if (NPART >= 3) acc += p[2 * pstride + off];
        if (NPART >= 4) acc += p[3 * pstride + off];
        v[i] = acc;
        sum += acc; sq += acc * acc;
    }
    s1[threadIdx.x] = sum; s2[threadIdx.x] = sq;
    __syncthreads();
    for (int off = 128; off; off >>= 1) {
        if (threadIdx.x < off) {
            s1[threadIdx.x] += s1[threadIdx.x + off];
            s2[threadIdx.x] += s2[threadIdx.x + off];
        }
        __syncthreads();
    }
    float mean = s1[0] * (1.f / HW);
    float var  = s2[0] * (1.f / HW) - mean * mean;
    float rstd = rsqrtf(var + EPSV);
    float* o = out + base;
    const float* rr = resid ? resid + base : nullptr;
#pragma unroll
    for (int i = 0; i < 16; i++) {
        float xv = v[i];
        float lr = xv > 0.f ? xv : SLOPE * xv;
        float val = (xv - mean) * rstd + lr;
        if (rr) val += rr[threadIdx.x + i * 256];
        o[threadIdx.x + i * 256] = val;
    }
}

// ---------------- layernorm over channels, coalesced via smem transpose ----------
__global__ __launch_bounds__(256)
void layernorm_v2_kernel(const float* __restrict__ h, const float* __restrict__ g,
                         const float* __restrict__ beta, float* __restrict__ t)
{
    __shared__ float sv[DIM][33];
    __shared__ float ps[8][33], ps2[8][33];
    __shared__ float smean[32], srstd[32];
    const int tx = threadIdx.x & 31, ty = threadIdx.x >> 5;
    const int l0 = blockIdx.x * 32, b = blockIdx.y;
    const float* hb = h + (size_t)b * DIM * HW + l0;

    for (int c = ty; c < DIM; c += 8)
        sv[c][tx] = hb[(size_t)c * HW + tx];
    __syncthreads();

    float sum = 0.f, sq = 0.f;
#pragma unroll
    for (int i = 0; i < 16; i++) {
        float v = sv[ty * 16 + i][tx];
        sum += v; sq += v * v;
    }
    ps[ty][tx] = sum; ps2[ty][tx] = sq;
    __syncthreads();
    if (ty == 0) {
        float s = 0.f, s2 = 0.f;
#pragma unroll
        for (int w = 0; w < 8; w++) { s += ps[w][tx]; s2 += ps2[w][tx]; }
        float mean = s * (1.f / DIM);
        float var  = s2 * (1.f / DIM) - mean * mean;
        smean[tx] = mean;
        srstd[tx] = rsqrtf(var + EPSV);
    }
    __syncthreads();

#pragma unroll
    for (int cc = 0; cc < 4; cc++) {
        int c = tx + 32 * cc;
        float gv = g[c], bv = beta[c];
        for (int l = ty; l < 32; l += 8) {
            float m = smean[l], rs = srstd[l];
            t[((size_t)(b * LSEQ + l0 + l)) * DIM + c] = (sv[c][l] - m) * rs * gv + bv;
        }
    }
}

// ---------------- in_proj GEMM (K-step 16, software-pipelined) -------------------
__global__ __launch_bounds__(256)
void gemm_inproj_kernel(const float* __restrict__ A, const float* __restrict__ Bw,
                        float* __restrict__ xrx, float* __restrict__ resT)
{
    __shared__ ull   As2[16][128];
    __shared__ float Bs[16][128];
    __shared__ float sT[32][129];
    const int tid = threadIdx.x;
    const int tm = tid >> 4, tn = tid & 15;
    const int m0 = blockIdx.x * 128, n0 = blockIdx.y * 128;
    const int K = DIM, N = 2 * DIN;
    ull acc[8][4];
#pragma unroll
    for (int i = 0; i < 8; i++)
#pragma unroll
        for (int j = 0; j < 4; j++) acc[i][j] = 0ull;
    const int ar = tid >> 1, ak = (tid & 1) * 8;
    const int bk = tid >> 4, bn = (tid & 15) * 8;
    float4 av0 = *(const float4*)(A + (size_t)(m0 + ar) * K + ak);
    float4 av1 = *(const float4*)(A + (size_t)(m0 + ar) * K + ak + 4);
    float4 bv0 = *(const float4*)(Bw + (size_t)bk * N + n0 + bn);
    float4 bv1 = *(const float4*)(Bw + (size_t)bk * N + n0 + bn + 4);
    for (int k0 = 0; k0 < K; k0 += 16) {
        __syncthreads();
        As2[ak + 0][ar] = pack2(av0.x, av0.x);
        As2[ak + 1][ar] = pack2(av0.y, av0.y);
        As2[ak + 2][ar] = pack2(av0.z, av0.z);
        As2[ak + 3][ar] = pack2(av0.w, av0.w);
        As2[ak + 4][ar] = pack2(av1.x, av1.x);
        As2[ak + 5][ar] = pack2(av1.y, av1.y);
        As2[ak + 6][ar] = pack2(av1.z, av1.z);
        As2[ak + 7][ar] = pack2(av1.w, av1.w);
        *(float4*)&Bs[bk][bn]     = bv0;
        *(float4*)&Bs[bk][bn + 4] = bv1;
        __syncthreads();
        if (k0 + 16 < K) {
            av0 = *(const float4*)(A + (size_t)(m0 + ar) * K + k0 + 16 + ak);
            av1 = *(const float4*)(A + (size_t)(m0 + ar) * K + k0 + 16 + ak + 4);
            bv0 = *(const float4*)(Bw + (size_t)(k0 + 16 + bk) * N + n0 + bn);
            bv1 = *(const float4*)(Bw + (size_t)(k0 + 16 + bk) * N + n0 + bn + 4);
        }
#pragma unroll
        for (int k = 0; k < 16; k++) {
            ull a2[8], b2[4];
#pragma unroll
            for (int i = 0; i < 8; i++) a2[i] = As2[k][tm * 8 + i];
#pragma unroll
            for (int j = 0; j < 4; j++) b2[j] = *(const ull*)&Bs[k][tn * 2 + 32 * j];
#pragma unroll
            for (int i = 0; i < 8; i++)
#pragma unroll
                for (int j = 0; j < 4; j++)
                    acc[i][j] = ffma2(a2[i], b2[j], acc[i][j]);
        }
    }
    if (n0 < DIN) {
#pragma unroll
        for (int i = 0; i < 8; i++) {
            int row = m0 + tm * 8 + i;
#pragma unroll
            for (int j = 0; j < 4; j++) {
                float lo, hi; unpack2(acc[i][j], lo, hi);
                *(float2*)(xrx + (size_t)row * DIN + n0 + tn * 2 + 32 * j) = make_float2(lo, hi);
            }
        }
    } else {
        const int b = m0 >> 12, t0 = m0 & 4095, d0 = n0 - DIN;
#pragma unroll
        for (int j = 0; j < 4; j++) {
            __syncthreads();
#pragma unroll
            for (int i = 0; i < 8; i++) {
                int rl = tm * 8 + i;
                float lo, hi; unpack2(acc[i][j], lo, hi);
                sT[2 * tn][rl]     = lo;
                sT[2 * tn + 1][rl] = hi;
            }
            __syncthreads();
            int col = tid >> 3, r0 = (tid & 7) * 16;
            float* dst = resT + ((size_t)(b * DIN + d0 + 32 * j + col)) * LSEQ + t0 + r0;
#pragma unroll
            for (int k = 0; k < 16; k++) dst[k] = sT[col][r0 + k];
        }
    }
}

// ---------------- delta GEMM (K-step 16, software-pipelined) ---------------------
__global__ __launch_bounds__(256)
void gemm_delta_kernel(const float* __restrict__ A, const float* __restrict__ Bw,
                       const float* __restrict__ dtb, float* __restrict__ deltaT)
{
    __shared__ ull   As2[16][128];
    __shared__ float Bs[16][128];
    __shared__ float sT[32][129];
    const int tid = threadIdx.x;
    const int tm = tid >> 4, tn = tid & 15;
    const int m0 = blockIdx.x * 128, n0 = blockIdx.y * 128;
    const int K = DIN, N = DIN;
    ull acc[8][4];
#pragma unroll
    for (int i = 0; i < 8; i++)
#pragma unroll
        for (int j = 0; j < 4; j++) acc[i][j] = 0ull;
    const int ar = tid >> 1, ak = (tid & 1) * 8;
    const int bk = tid >> 4, bn = (tid & 15) * 8;
    float4 av0 = *(const float4*)(A + (size_t)(m0 + ar) * K + ak);
    float4 av1 = *(const float4*)(A + (size_t)(m0 + ar) * K + ak + 4);
    float4 bv0 = *(const float4*)(Bw + (size_t)bk * N + n0 + bn);
    float4 bv1 = *(const float4*)(Bw + (size_t)bk * N + n0 + bn + 4);
    for (int k0 = 0; k0 < K; k0 += 16) {
        __syncthreads();
        As2[ak + 0][ar] = pack2(av0.x, av0.x);
        As2[ak + 1][ar] = pack2(av0.y, av0.y);
        As2[ak + 2][ar] = pack2(av0.z, av0.z);
        As2[ak + 3][ar] = pack2(av0.w, av0.w);
        As2[ak + 4][ar] = pack2(av1.x, av1.x);
        As2[ak + 5][ar] = pack2(av1.y, av1.y);
        As2[ak + 6][ar] = pack2(av1.z, av1.z);
        As2[ak + 7][ar] = pack2(av1.w, av1.w);
        *(float4*)&Bs[bk][bn]     = bv0;
        *(float4*)&Bs[bk][bn + 4] = bv1;
        __syncthreads();
        if (k0 + 16 < K) {
            av0 = *(const float4*)(A + (size_t)(m0 + ar) * K + k0 + 16 + ak);
            av1 = *(const float4*)(A + (size_t)(m0 + ar) * K + k0 + 16 + ak + 4);
            bv0 = *(const float4*)(Bw + (size_t)(k0 + 16 + bk) * N + n0 + bn);
            bv1 = *(const float4*)(Bw + (size_t)(k0 + 16 + bk) * N + n0 + bn + 4);
        }
#pragma unroll
        for (int k = 0; k < 16; k++) {
            ull a2[8], b2[4];
#pragma unroll
            for (int i = 0; i < 8; i++) a2[i] = As2[k][tm * 8 + i];
#pragma unroll
            for (int j = 0; j < 4; j++) b2[j] = *(const ull*)&Bs[k][tn * 2 + 32 * j];
#pragma unroll
            for (int i = 0; i < 8; i++)
#pragma unroll
                for (int j = 0; j < 4; j++)
                    acc[i][j] = ffma2(a2[i], b2[j], acc[i][j]);
        }
    }
    const int b = m0 >> 12, t0 = m0 & 4095;
#pragma unroll
    for (int j = 0; j < 4; j++) {
        __syncthreads();
        float blo = dtb[n0 + 32 * j + 2 * tn];
        float bhi = dtb[n0 + 32 * j + 2 * tn + 1];
#pragma unroll
        for (int i = 0; i < 8; i++) {
            int rl = tm * 8 + i;
            float lo, hi; unpack2(acc[i][j], lo, hi);
            sT[2 * tn][rl]     = softplus_f(lo + blo);
            sT[2 * tn + 1][rl] = softplus_f(hi + bhi);
        }
        __syncthreads();
        int col = tid >> 3, r0 = (tid & 7) * 16;
        float* dst = deltaT + ((size_t)(b * DIN + n0 + 32 * j + col)) * LSEQ + t0 + r0;
#pragma unroll
        for (int k = 0; k < 16; k++) dst[k] = sT[col][r0 + k];
    }
}

// ---------------- BC GEMM: M-tile 64, software-pipelined -------------------------
__global__ __launch_bounds__(256)
void gemm_bc_kernel(const float* __restrict__ A, const float* __restrict__ xw,
                    float* __restrict__ bc)
{
    __shared__ ull   As2[16][64];
    __shared__ float Bs[16][32];
    const int tid = threadIdx.x;
    const int tm = tid >> 4, tn = tid & 15;
    const int m0 = blockIdx.x * 64;
    ull acc[4];
#pragma unroll
    for (int i = 0; i < 4; i++) acc[i] = 0ull;
    const int ar = tid >> 2, aq = (tid & 3) * 4;
    float4 a1 = *(const float4*)(A + (size_t)(m0 + ar) * DIN + aq);
    float bvv[2];
#pragma unroll
    for (int q = 0; q < 2; q++) {
        int idx = tid + q * 256;
        bvv[q] = xw[(size_t)(idx >> 5) * 40 + 8 + (idx & 31)];
    }
    for (int k0 = 0; k0 < DIN; k0 += 16) {
        __syncthreads();
        As2[aq + 0][ar] = pack2(a1.x, a1.x);
        As2[aq + 1][ar] = pack2(a1.y, a1.y);
        As2[aq + 2][ar] = pack2(a1.z, a1.z);
        As2[aq + 3][ar] = pack2(a1.w, a1.w);
#pragma unroll
        for (int q = 0; q < 2; q++) {
            int idx = tid + q * 256;
            Bs[idx >> 5][idx & 31] = bvv[q];
        }
        __syncthreads();
        if (k0 + 16 < DIN) {
            a1 = *(const float4*)(A + (size_t)(m0 + ar) * DIN + k0 + 16 + aq);
#pragma unroll
            for (int q = 0; q < 2; q++) {
                int idx = tid + q * 256;
                bvv[q] = xw[(size_t)(k0 + 16 + (idx >> 5)) * 40 + 8 + (idx & 31)];
            }
        }
#pragma unroll
        for (int k = 0; k < 16; k++) {
            ull b2 = *(const ull*)&Bs[k][2 * tn];
#pragma unroll
            for (int i = 0; i < 4; i++)
                acc[i] = ffma2(As2[k][tm * 4 + i], b2, acc[i]);
        }
    }
#pragma unroll
    for (int i = 0; i < 4; i++) {
        int row = m0 + tm * 4 + i;
        float lo, hi; unpack2(acc[i], lo, hi);
        *(float2*)(bc + (size_t)row * 32 + 2 * tn) = make_float2(lo, hi);
    }
}

// ---------------- out_proj GEMM: M-tile 64, software-pipelined -------------------
__global__ __launch_bounds__(256)
void gemm_out_kernel(const float* __restrict__ gatedT, const float* __restrict__ Bw,
                     float* __restrict__ out)
{
    __shared__ ull   As2[8][64];
    __shared__ float Bs[8][128];
    __shared__ float sT[32][65];
    const int tid = threadIdx.x;
    const int tm = tid >> 4, tn = tid & 15;
    const int m0 = blockIdx.x * 64;
    const int K = DIN, N = DIM;
    const int b = m0 >> 12, t0 = m0 & 4095;
    ull acc[4][4];
#pragma unroll
    for (int i = 0; i < 4; i++)
#pragma unroll
        for (int j = 0; j < 4; j++) acc[i][j] = 0ull;
    const int kk = tid >> 5, tl = tid & 31;
    const int bk = tid >> 5, bn = (tid & 31) * 4;
    float gv[2];
#pragma unroll
    for (int it = 0; it < 2; it++)
        gv[it] = gatedT[((size_t)(b * DIN + kk)) * LSEQ + t0 + tl + 32 * it];
    float4 bv = *(const float4*)(Bw + (size_t)bk * N + bn);
    for (int k0 = 0; k0 < K; k0 += 8) {
        __syncthreads();
#pragma unroll
        for (int it = 0; it < 2; it++)
            As2[kk][tl + 32 * it] = pack2(gv[it], gv[it]);
        *(float4*)&Bs[bk][bn] = bv;
        __syncthreads();
        if (k0 + 8 < K) {
            int d = k0 + 8 + kk;
#pragma unroll
            for (int it = 0; it < 2; it++)
                gv[it] = gatedT[((size_t)(b * DIN + d)) * LSEQ + t0 + tl + 32 * it];
            bv = *(const float4*)(Bw + (size_t)(k0 + 8 + bk) * N + bn);
        }
#pragma unroll
        for (int k = 0; k < 8; k++) {
            ull a2[4], b2[4];
#pragma unroll
            for (int i = 0; i < 4; i++) a2[i] = As2[k][tm * 4 + i];
#pragma unroll
            for (int j = 0; j < 4; j++) b2[j] = *(const ull*)&Bs[k][tn * 2 + 32 * j];
#pragma unroll
            for (int i = 0; i < 4; i++)
#pragma unroll
                for (int j = 0; j < 4; j++)
                    acc[i][j] = ffma2(a2[i], b2[j], acc[i][j]);
        }
    }
#pragma unroll
    for (int j = 0; j < 4; j++) {
        __syncthreads();
#pragma unroll
        for (int i = 0; i < 4; i++) {
            int rl = tm * 4 + i;
            float lo, hi; unpack2(acc[i][j], lo, hi);
            sT[2 * tn][rl]     = lo;
            sT[2 * tn + 1][rl] = hi;
        }
        __syncthreads();
        int col = tid >> 3, r0 = (tid & 7) * 8;
        float* dst = out + ((size_t)(b * DIM + 32 * j + col)) * LSEQ + t0 + r0;
#pragma unroll
        for (int k = 0; k < 8; k++) dst[k] = sT[col][r0 + k];
    }
}

// ---------------- causal depthwise conv1d (k=4) + silu, smem-staged --------------
__global__ __launch_bounds__(256)
void conv1d_silu_T_kernel(const float* __restrict__ xrx, const float4* __restrict__ wp,
                          const float* __restrict__ bias,
                          float* __restrict__ xs, float* __restrict__ xsT)
{
    __shared__ float sin_[35][32];
    __shared__ float st[32][33];
    const int tx = threadIdx.x & 31, ty = threadIdx.x >> 5;
    const int t0 = blockIdx.x * 32, d0 = blockIdx.y * 32, b = blockIdx.z;
    const int d = d0 + tx;

    for (int r = ty; r < 35; r += 8) {
        int t = t0 - 3 + r;
        sin_[r][tx] = (t >= 0) ? xrx[((size_t)b * LSEQ + t) * DIN + d] : 0.f;
    }
    __syncthreads();

    float4 w = wp[d];
    float bv = bias[d];
#pragma unroll
    for (int k = 0; k < 4; k++) {
        int tt = ty + 8 * k;
        float acc = bv;
        acc = fmaf(w.x, sin_[tt][tx],     acc);
        acc = fmaf(w.y, sin_[tt + 1][tx], acc);
        acc = fmaf(w.z, sin_[tt + 2][tx], acc);
        acc = fmaf(w.w, sin_[tt + 3][tx], acc);
        float s = acc / (1.f + __expf(-acc));
        xs[((size_t)b * LSEQ + t0 + tt) * DIN + d] = s;
        st[tx][tt] = s;
    }
    __syncthreads();
#pragma unroll
    for (int k = 0; k < 4; k++) {
        int dd = d0 + ty + 8 * k;
        xsT[((size_t)(b * DIN + dd)) * LSEQ + t0 + tx] = st[ty + 8 * k][tx];
    }
}

// ---------------- scan pass 1 (float4 broadcast loads, NCH=16) -------------------
__global__ __launch_bounds__(256)
void scan_p1_kernel(const float* __restrict__ deltaT, const float* __restrict__ xsT,
                    const float* __restrict__ bc, const float* __restrict__ negA,
                    float* __restrict__ chA, float* __restrict__ chH)
{
    int gw = (blockIdx.x * blockDim.x + threadIdx.x) >> 5;
    int lane = threadIdx.x & 31;
    int half = lane >> 4, n = lane & 15;
    int chunk = gw >> 9;
    int wp = gw & 511;
    int pair = wp * 2 + half;
    int b = pair >> 8, d = pair & 255;
    int t0 = chunk * CHLEN;

    float A = negA[d * DSTATE + n];
    const float* dl = deltaT + (size_t)(b * DIN + d) * LSEQ + t0;
    const float* ul = xsT    + (size_t)(b * DIN + d) * LSEQ + t0;
    const float* xb = bc + ((size_t)b * LSEQ + t0) * 32;

    float h = 0.f, pA = 1.f;
    for (int tb = 0; tb < CHLEN; tb += 4) {
        float4 d4 = *(const float4*)(dl + tb);
        float4 u4 = *(const float4*)(ul + tb);
#pragma unroll
        for (int q = 0; q < 4; q++) {
            float dt = (q == 0) ? d4.x : (q == 1) ? d4.y : (q == 2) ? d4.z : d4.w;
            float ut = (q == 0) ? u4.x : (q == 1) ? u4.y : (q == 2) ? u4.z : u4.w;
            float Bn = xb[(tb + q) * 32 + n];
            float a = __expf(dt * A);
            pA *= a;
            h = fmaf(a, h, dt * ut * Bn);
        }
    }
    int idx = (chunk * NPAIR + pair) * DSTATE + n;
    chA[idx] = pA;
    chH[idx] = h;
}

// ---------------- scan pass 2 ----------------
__global__ __launch_bounds__(256)
void scan_p2_kernel(const float* __restrict__ chA, const float* __restrict__ chH,
                    float* __restrict__ hst)
{
    int i = blockIdx.x * 256 + threadIdx.x;
    float h = 0.f;
    hst[i] = 0.f;
#pragma unroll
    for (int c = 0; c < NCH - 1; c++) {
        h = fmaf(chA[c * NPAIR * DSTATE + i], h, chH[c * NPAIR * DSTATE + i]);
        hst[(c + 1) * NPAIR * DSTATE + i] = h;
    }
}

// ---------------- scan pass 3 (float4 broadcast loads, NCH=16) -------------------
__global__ __launch_bounds__(256)
void scan_p3_kernel(const float* __restrict__ deltaT, const float* __restrict__ xsT,
                    const float* __restrict__ bc, const float* __restrict__ negA,
                    const float* __restrict__ Dp, const float* __restrict__ hst,
                    const float* __restrict__ resT, float* __restrict__ gatedT)
{
    __shared__ float sy[8][2][32];
    int gw = (blockIdx.x * blockDim.x + threadIdx.x) >> 5;
    int lane = threadIdx.x & 31;
    int wslot = threadIdx.x >> 5;
    int half = lane >> 4, n = lane & 15;
    int chunk = gw >> 9;
    int wp = gw & 511;
    int pair = wp * 2 + half;
    int b = pair >> 8, d = pair & 255;
    int t0 = chunk * CHLEN;

    float A = negA[d * DSTATE + n];
    const float* dl = deltaT + (size_t)(b * DIN + d) * LSEQ + t0;
    const float* ul = xsT    + (size_t)(b * DIN + d) * LSEQ + t0;
    const float* xb = bc + ((size_t)b * LSEQ + t0) * 32;
    float h = hst[(chunk * NPAIR + pair) * DSTATE + n];

    int dp0 = (wp * 2) & 255;
    int bb  = (wp * 2) >> 8;
    float Dv0 = Dp[dp0], Dv1 = Dp[dp0 + 1];
    const float* u0p = xsT + (size_t)(bb * DIN + dp0)     * LSEQ + t0;
    const float* u1p = xsT + (size_t)(bb * DIN + dp0 + 1) * LSEQ + t0;
    const float* r0p = resT + (size_t)(bb * DIN + dp0)     * LSEQ + t0;
    const float* r1p = resT + (size_t)(bb * DIN + dp0 + 1) * LSEQ + t0;
    float* y0p = gatedT + (size_t)(bb * DIN + dp0)     * LSEQ + t0;
    float* y1p = gatedT + (size_t)(bb * DIN + dp0 + 1) * LSEQ + t0;

    for (int tb = 0; tb < CHLEN; tb += 32) {
        for (int tq = 0; tq < 32; tq += 4) {
            float4 d4 = *(const float4*)(dl + tb + tq);
            float4 u4 = *(const float4*)(ul + tb + tq);
#pragma unroll
            for (int q = 0; q < 4; q++) {
                int t = tb + tq + q;
                float dt = (q == 0) ? d4.x : (q == 1) ? d4.y : (q == 2) ? d4.z : d4.w;
                float ut = (q == 0) ? u4.x : (q == 1) ? u4.y : (q == 2) ? u4.z : u4.w;
                float Bn  = xb[t * 32 + n];
                float Cn  = xb[t * 32 + 16 + n];
                float a = __expf(dt * A);
                h = fmaf(a, h, dt * ut * Bn);
                float yv = h * Cn;
                yv += __shfl_xor_sync(0xffffffffu, yv, 8);
                yv += __shfl_xor_sync(0xffffffffu, yv, 4);
                yv += __shfl_xor_sync(0xffffffffu, yv, 2);
                yv += __shfl_xor_sync(0xffffffffu, yv, 1);
                if (n == 0) sy[wslot][half][tq + q] = yv;
            }
        }
        __syncwarp();
        float r0 = r0p[tb + lane];
        float r1 = r1p[tb + lane];
        float s0 = r0 / (1.f + __expf(-r0));
        float s1 = r1 / (1.f + __expf(-r1));
        y0p[tb + lane] = fmaf(u0p[tb + lane], Dv0, sy[wslot][0][lane]) * s0;
        y1p[tb + lane] = fmaf(u1p[tb + lane], Dv1, sy[wslot][1][lane]) * s1;
        __syncwarp();
    }
}

// ---------------- launch ----------------
extern "C" void kernel_launch(void* const* d_in, const int* in_sizes, int n_in,
                              void* d_out, int out_size)
{
    const float* x         = (const float*)d_in[0];
    const float* conv1_w   = (const float*)d_in[1];
    const float* conv1_b   = (const float*)d_in[2];
    const float* conv2_w   = (const float*)d_in[3];
    const float* conv2_b   = (const float*)d_in[4];
    const float* ln_g      = (const float*)d_in[5];
    const float* ln_b      = (const float*)d_in[6];
    const float* in_proj_w = (const float*)d_in[7];
    const float* conv1d_w  = (const float*)d_in[8];
    const float* conv1d_b  = (const float*)d_in[9];
    const float* x_proj_w  = (const float*)d_in[10];
    const float* dt_proj_w = (const float*)d_in[11];
    const float* dt_proj_b = (const float*)d_in[12];
    const float* A_log     = (const float*)d_in[13];
    const float* Dp        = (const float*)d_in[14];
    const float* out_proj_w= (const float*)d_in[15];
    float* out = (float*)d_out;

    Scratch* s = nullptr;
    cudaGetSymbolAddress((void**)&s, g_scratch);

    const size_t p1stride = (size_t)BATCH * DIN * HW;
    const size_t p2stride = (size_t)BATCH * DIM * HW;

    // 0-2) precompute (conv1 stays at profiled slot 3)
    negA_wpack_kernel<<<17, 256>>>(A_log, s->negA, conv1d_w, s->wpack);
    weff_kernel<<<DIN, DIN>>>(x_proj_w, dt_proj_w, s->weff);
    wdup_kernel<<<(W1ELEMS + W2ELEMS + 255) / 256, 256>>>(conv1_w, conv2_w, s->wd1, s->wd2);
    // 3) conv1 split-K x2
    conv3x3_v10_kernel<DIM, DIN, 2><<<dim3(2, 1, BATCH * (DIN / 8) * 2), 256>>>(
        x, s->wd1, s->h1);
    // 4) inorm (sums 2 partials + bias) + leaky
    inorm_lrelu_kernel<2><<<BATCH * DIN, 256>>>(s->h1, p1stride, conv1_b, DIN, s->h1, nullptr);
    // 5) conv2 split-K x4
    conv3x3_v10_kernel<DIN, DIM, 4><<<dim3(2, 1, BATCH * (DIM / 8) * 4), 256>>>(
        s->h1, s->wd2, s->h2);
    // 6) inorm (sums 4 partials + bias) + leaky + residual
    inorm_lrelu_kernel<4><<<BATCH * DIM, 256>>>(s->h2, p2stride, conv2_b, DIM, s->h2, x);
    // 7) layernorm (coalesced) + transpose to (b*l, c)
    layernorm_v2_kernel<<<dim3(HW / 32, BATCH), 256>>>(s->h2, ln_g, ln_b, s->t);
    // 8) in_proj GEMM (K-step 16)
    gemm_inproj_kernel<<<dim3(BATCH * LSEQ / 128, 4), 256>>>(
        s->t, in_proj_w, s->xrx, s->resT);
    // 9) depthwise conv1d + silu (smem-staged)
    conv1d_silu_T_kernel<<<dim3(LSEQ / 32, DIN / 32, BATCH), 256>>>(
        s->xrx, s->wpack, conv1d_b, s->xs, s->xsT);
    // 10) delta GEMM (K-step 16)
    gemm_delta_kernel<<<dim3(BATCH * LSEQ / 128, 2), 256>>>(
        s->xs, s->weff, dt_proj_b, s->deltaT);
    // 11) B/C GEMM (M-tile 64)
    gemm_bc_kernel<<<BATCH * LSEQ / 64, 256>>>(s->xs, x_proj_w, s->bc);
    // 12) chunked selective scan (NCH=16)
    scan_p1_kernel<<<(NCH - 1) * 64, 256>>>(
        s->deltaT, s->xsT, s->bc, s->negA, s->chA, s->chH);
    scan_p2_kernel<<<NPAIR * DSTATE / 256, 256>>>(s->chA, s->chH, s->hst);
    scan_p3_kernel<<<NCH * 64, 256>>>(
        s->deltaT, s->xsT, s->bc, s->negA, Dp, s->hst, s->resT, s->gatedT);
    // 13) out_proj GEMM (M-tile 64) + NCHW store
    gemm_out_kernel<<<BATCH * LSEQ / 64, 256>>>(s->gatedT, out_proj_w, out);
}

// round 17
// speedup vs baseline: 1.4373x; 1.0281x over previous
#include <cuda_runtime.h>
#include <cuda_bf16.h>
#include <cstdint>
#include <cstddef>

#define BATCH 4
#define DIM   128
#define DIN   256
#define HH    64
#define WW    64
#define HW    4096
#define LSEQ  4096
#define DSTATE 16
#define DTRANK 8
#define EPSV  1e-5f
#define SLOPE 0.01f

#define NCH   32
#define CHLEN (LSEQ/NCH)
#define NPAIR (BATCH*DIN)

typedef unsigned long long ull;

__device__ __forceinline__ ull pack2(float lo, float hi) {
    ull r; asm("mov.b64 %0, {%1, %2};" : "=l"(r) : "f"(lo), "f"(hi)); return r;
}
__device__ __forceinline__ void unpack2(ull p, float& lo, float& hi) {
    asm("mov.b64 {%0, %1}, %2;" : "=f"(lo), "=f"(hi) : "l"(p));
}
__device__ __forceinline__ ull ffma2(ull a, ull b, ull c) {
    ull d; asm("fma.rn.f32x2 %0, %1, %2, %3;" : "=l"(d) : "l"(a), "l"(b), "l"(c)); return d;
}
__device__ __forceinline__ float softplus_f(float x) {
    return (x > 20.f) ? x : log1pf(expf(x));
}
__device__ __forceinline__ uint32_t saddr(const void* p) {
    return (uint32_t)__cvta_generic_to_shared(p);
}
__device__ __forceinline__ void cpa4(uint32_t dst, const void* src) {
    asm volatile("cp.async.ca.shared.global [%0], [%1], 4;" :: "r"(dst), "l"(src));
}
__device__ __forceinline__ void cpa16(uint32_t dst, const void* src) {
    asm volatile("cp.async.cg.shared.global [%0], [%1], 16;" :: "r"(dst), "l"(src));
}

#define W1ELEMS (DIM * 9 * DIN)
#define W2ELEMS (DIN * 9 * DIM)

// ---------------- scratch ----------------
struct Scratch {
    float h1[2 * BATCH * DIN * HW];
    float h2[4 * BATCH * DIM * HW];
    float t [BATCH * LSEQ * DIM];
    float xrx[BATCH * LSEQ * DIN];
    float resT[NPAIR * LSEQ];
    float xs[BATCH * LSEQ * DIN];
    float xsT[NPAIR * LSEQ];
    float deltaT[NPAIR * LSEQ];
    float gatedT[NPAIR * LSEQ];
    float bc[BATCH * LSEQ * 2*DSTATE];
    float weff[DIN * DIN];
    float negA[DIN * DSTATE];
    float4 wpack[DIN];
    float wd1[W1ELEMS];
    float wd2[W2ELEMS];
    float chA[(NCH-1) * NPAIR * DSTATE];
    float chH[(NCH-1) * NPAIR * DSTATE];
    float hst[NCH * NPAIR * DSTATE];
};
__device__ Scratch g_scratch;

// ---------------- merged precompute (1 launch; block-range dispatch) -------------
// blocks [0,16): negA; block 16: conv1d wpack; [17,273): weff; [273,...): wdup
__global__ __launch_bounds__(256)
void precompute_kernel(const float* __restrict__ A_log, float* __restrict__ negA,
                       const float* __restrict__ w1d, float4* __restrict__ wp,
                       const float* __restrict__ xw, const float* __restrict__ dtw,
                       float* __restrict__ weff,
                       const float* __restrict__ w1, const float* __restrict__ w2,
                       float* __restrict__ wd1, float* __restrict__ wd2)
{
    const int bx = blockIdx.x;
    if (bx < 16) {
        int i = bx * 256 + threadIdx.x;
        negA[i] = -expf(A_log[i]);
    } else if (bx == 16) {
        int d = threadIdx.x;
        wp[d] = make_float4(w1d[4*d], w1d[4*d+1], w1d[4*d+2], w1d[4*d+3]);
    } else if (bx < 17 + DIN) {
        int k = bx - 17, d = threadIdx.x;
        float acc = 0.f;
#pragma unroll
        for (int r = 0; r < DTRANK; r++)
            acc = fmaf(xw[k * 40 + r], dtw[r * DIN + d], acc);
        weff[k * DIN + d] = acc;
    } else {
        int i = (bx - 17 - DIN) * 256 + threadIdx.x;
        if (i < W1ELEMS) {
            int oc = i % DIN; int rest = i / DIN;
            int tap = rest % 9; int ci = rest / 9;
            wd1[i] = w1[((size_t)oc * DIM + ci) * 9 + tap];
        } else if (i < W1ELEMS + W2ELEMS) {
            int j = i - W1ELEMS;
            int oc = j % DIM; int rest = j / DIM;
            int tap = rest % 9; int ci = rest / 9;
            wd2[j] = w2[((size_t)oc * DIN + ci) * 9 + tap];
        }
    }
}

// ---------------- conv v10 (exact R12 form; frozen) -------------------------------
template<int CIN, int COUT, int SPLIT>
__global__ __launch_bounds__(256, 2)
void conv3x3_v10_kernel(const float* __restrict__ x, const float* __restrict__ wd,
                        float* __restrict__ out)
{
    constexpr int OCPB = 8, CIC = 2, CSPAN = CIN / SPLIT;
    constexpr int NCHUNK = CSPAN / CIC;
    __shared__ float4 sx4[2][CIC * 18 * 36];
    __shared__ float4 swt[2][CIC * 9 * 2];

    const int tid = threadIdx.x;
    const int tx = tid & 31, ty = tid >> 5;
    const int bx0 = blockIdx.x * 32;
    const int bz = blockIdx.z;
    constexpr int OCB = COUT / OCPB;
    const int b    = bz / (OCB * SPLIT);
    const int r    = bz % (OCB * SPLIT);
    const int oc0  = (r / SPLIT) * OCPB;
    const int part = r % SPLIT;
    const int cbase = part * CSPAN;
    const float* xb = x + (size_t)b * CIN * HW;
    float* out_part = out + (size_t)part * BATCH * COUT * HW;

    for (int i = tid; i < 2 * CIC * 18 * 36; i += 256)
        ((float4*)sx4)[i] = make_float4(0.f, 0.f, 0.f, 0.f);
    __syncthreads();

    auto load_chunk = [&](int buf, int c0) {
        for (int rr = ty; rr < CIC * 18; rr += 8) {
            int ci = (rr >= 18) ? 1 : 0;
            int p  = rr - 18 * ci;
            int gr = p - 1;
#pragma unroll
            for (int s = 0; s < 2; s++) {
                int xx = tx + 32 * s;
                if (xx < 34) {
                    int gx = bx0 + xx - 1;
                    if ((unsigned)gx < (unsigned)WW) {
                        const float* pc = xb + (size_t)(cbase + c0 + ci) * HW + gx;
                        uint32_t dst = saddr(&sx4[buf][rr * 36 + xx]);
                        if (p > 0)  cpa4(dst + 0,  pc + (size_t)gr * WW);
                        cpa4(dst + 4,  pc + (size_t)(gr + 16) * WW);
                        cpa4(dst + 8,  pc + (size_t)(gr + 32) * WW);
                        if (p < 17) cpa4(dst + 12, pc + (size_t)(gr + 48) * WW);
                    }
                }
            }
        }
        if (tid < CIC * 9 * 2) {
            int q = tid & 1;
            int rowi = tid >> 1;
            int ci = (rowi >= 9) ? 1 : 0;
            int tap = rowi - 9 * ci;
            const float* src = wd + ((size_t)(cbase + c0 + ci) * 9 + tap) * COUT + oc0 + 4 * q;
            cpa16(saddr(&swt[buf][rowi * 2 + q]), src);
        }
    };

    ull acc[OCPB][4];
#pragma unroll
    for (int i = 0; i < OCPB; i++)
#pragma unroll
        for (int q = 0; q < 4; q++) acc[i][q] = 0ull;

    load_chunk(0, 0);
    asm volatile("cp.async.commit_group;");

    for (int ch = 0; ch < NCHUNK; ch++) {
        const int cur = ch & 1;
        if (ch + 1 < NCHUNK) {
            load_chunk(cur ^ 1, (ch + 1) * CIC);
            asm volatile("cp.async.commit_group;");
            asm volatile("cp.async.wait_group 1;");
        } else {
            asm volatile("cp.async.wait_group 0;");
        }
        __syncthreads();

        const float4* sxb = sx4[cur];
        const float4* swb = swt[cur];
#pragma unroll
        for (int ci = 0; ci < CIC; ci++) {
#pragma unroll
            for (int tap = 0; tap < 9; tap++) {
                const int ti = tap / 3, tj = tap % 3;
                ulonglong2 A = *(const ulonglong2*)&sxb[(ci * 18 + ty + ti) * 36 + tx + tj];
                ulonglong2 C = *(const ulonglong2*)&sxb[(ci * 18 + ty + 8 + ti) * 36 + tx + tj];
                float4 wa = swb[(ci * 9 + tap) * 2 + 0];
                {
                    ull w0 = pack2(wa.x, wa.x), w1 = pack2(wa.y, wa.y);
                    ull w2 = pack2(wa.z, wa.z), w3 = pack2(wa.w, wa.w);
                    acc[0][0] = ffma2(A.x, w0, acc[0][0]); acc[0][1] = ffma2(A.y, w0, acc[0][1]);
                    acc[0][2] = ffma2(C.x, w0, acc[0][2]); acc[0][3] = ffma2(C.y, w0, acc[0][3]);
                    acc[1][0] = ffma2(A.x, w1, acc[1][0]); acc[1][1] = ffma2(A.y, w1, acc[1][1]);
                    acc[1][2] = ffma2(C.x, w1, acc[1][2]); acc[1][3] = ffma2(C.y, w1, acc[1][3]);
                    acc[2][0] = ffma2(A.x, w2, acc[2][0]); acc[2][1] = ffma2(A.y, w2, acc[2][1]);
                    acc[2][2] = ffma2(C.x, w2, acc[2][2]); acc[2][3] = ffma2(C.y, w2, acc[2][3]);
                    acc[3][0] = ffma2(A.x, w3, acc[3][0]); acc[3][1] = ffma2(A.y, w3, acc[3][1]);
                    acc[3][2] = ffma2(C.x, w3, acc[3][2]); acc[3][3] = ffma2(C.y, w3, acc[3][3]);
                }
                float4 wb = swb[(ci * 9 + tap) * 2 + 1];
                {
                    ull w4 = pack2(wb.x, wb.x), w5 = pack2(wb.y, wb.y);
                    ull w6 = pack2(wb.z, wb.z), w7 = pack2(wb.w, wb.w);
                    acc[4][0] = ffma2(A.x, w4, acc[4][0]); acc[4][1] = ffma2(A.y, w4, acc[4][1]);
                    acc[4][2] = ffma2(C.x, w4, acc[4][2]); acc[4][3] = ffma2(C.y, w4, acc[4][3]);
                    acc[5][0] = ffma2(A.x, w5, acc[5][0]); acc[5][1] = ffma2(A.y, w5, acc[5][1]);
                    acc[5][2] = ffma2(C.x, w5, acc[5][2]); acc[5][3] = ffma2(C.y, w5, acc[5][3]);
                    acc[6][0] = ffma2(A.x, w6, acc[6][0]); acc[6][1] = ffma2(A.y, w6, acc[6][1]);
                    acc[6][2] = ffma2(C.x, w6, acc[6][2]); acc[6][3] = ffma2(C.y, w6, acc[6][3]);
                    acc[7][0] = ffma2(A.x, w7, acc[7][0]); acc[7][1] = ffma2(A.y, w7, acc[7][1]);
                    acc[7][2] = ffma2(C.x, w7, acc[7][2]); acc[7][3] = ffma2(C.y, w7, acc[7][3]);
                }
            }
        }
        __syncthreads();
    }

    float* ob = out_part + (size_t)b * COUT * HW;
#pragma unroll
    for (int oc = 0; oc < OCPB; oc++) {
        float r0, r16, r32, r48, r8, r24, r40, r56;
        unpack2(acc[oc][0], r0,  r16);
        unpack2(acc[oc][1], r32, r48);
        unpack2(acc[oc][2], r8,  r24);
        unpack2(acc[oc][3], r40, r56);
        size_t base = ((size_t)(oc0 + oc) * HH) * WW + bx0 + tx;
        ob[base + (size_t)(ty)      * WW] = r0;
        ob[base + (size_t)(ty + 8)  * WW] = r8;
        ob[base + (size_t)(ty + 16) * WW] = r16;
        ob[base + (size_t)(ty + 24) * WW] = r24;
        ob[base + (size_t)(ty + 32) * WW] = r32;
        ob[base + (size_t)(ty + 40) * WW] = r40;
        ob[base + (size_t)(ty + 48) * WW] = r48;
        ob[base + (size_t)(ty + 56) * WW] = r56;
    }
}

// ---------------- instance norm + leaky, sums NPART split-K partials + bias -------
template<int NPART>
__global__ __launch_bounds__(256)
void inorm_lrelu_kernel(const float* __restrict__ in, size_t pstride,
                        const float* __restrict__ bias, int C,
                        float* __restrict__ out, const float* __restrict__ resid)
{
    __shared__ float s1[256], s2[256];
    const size_t base = (size_t)blockIdx.x * HW;
    const int c = blockIdx.x % C;
    const float bv = bias[c];
    const float* p = in + base;
    float v[16];
    float sum = 0.f, sq = 0.f;
#pragma unroll
    for (int i = 0; i < 16; i++) {
        int off = threadIdx.x + i * 256;
        float acc = bv + p[off];
        if (NPART >= 2) acc += p[pstride + off];
        if (NPART >= 3) acc += p[2 * pstride + off];
        if (NPART >= 4) acc += p[3 * pstride + off];
        v[i] = acc;
        sum += acc; sq += acc * acc;
    }
    s1[threadIdx.x] = sum; s2[threadIdx.x] = sq;
    __syncthreads();
    for (int off = 128; off; off >>= 1) {
        if (threadIdx.x < off) {
            s1[threadIdx.x] += s1[threadIdx.x + off];
            s2[threadIdx.x] += s2[threadIdx.x + off];
        }
        __syncthreads();
    }
    float mean = s1[0] * (1.f / HW);
    float var  = s2[0] * (1.f / HW) - mean * mean;
    float rstd = rsqrtf(var + EPSV);
    float* o = out + base;
    const float* rr = resid ? resid + base : nullptr;
#pragma unroll
    for (int i = 0; i < 16; i++) {
        float xv = v[i];
        float lr = xv > 0.f ? xv : SLOPE * xv;
        float val = (xv - mean) * rstd + lr;
        if (rr) val += rr[threadIdx.x + i * 256];
        o[threadIdx.x + i * 256] = val;
    }
}

// ---------------- layernorm over channels, coalesced via smem transpose ----------
__global__ __launch_bounds__(256)
void layernorm_v2_kernel(const float* __restrict__ h, const float* __restrict__ g,
                         const float* __restrict__ beta, float* __restrict__ t)
{
    __shared__ float sv[DIM][33];
    __shared__ float ps[8][33], ps2[8][33];
    __shared__ float smean[32], srstd[32];
    const int tx = threadIdx.x & 31, ty = threadIdx.x >> 5;
    const int l0 = blockIdx.x * 32, b = blockIdx.y;
    const float* hb = h + (size_t)b * DIM * HW + l0;

    for (int c = ty; c < DIM; c += 8)
        sv[c][tx] = hb[(size_t)c * HW + tx];
    __syncthreads();

    float sum = 0.f, sq = 0.f;
#pragma unroll
    for (int i = 0; i < 16; i++) {
        float v = sv[ty * 16 + i][tx];
        sum += v; sq += v * v;
    }
    ps[ty][tx] = sum; ps2[ty][tx] = sq;
    __syncthreads();
    if (ty == 0) {
        float s = 0.f, s2 = 0.f;
#pragma unroll
        for (int w = 0; w < 8; w++) { s += ps[w][tx]; s2 += ps2[w][tx]; }
        float mean = s * (1.f / DIM);
        float var  = s2 * (1.f / DIM) - mean * mean;
        smean[tx] = mean;
        srstd[tx] = rsqrtf(var + EPSV);
    }
    __syncthreads();

#pragma unroll
    for (int cc = 0; cc < 4; cc++) {
        int c = tx + 32 * cc;
        float gv = g[c], bv = beta[c];
        for (int l = ty; l < 32; l += 8) {
            float m = smean[l], rs = srstd[l];
            t[((size_t)(b * LSEQ + l0 + l)) * DIM + c] = (sv[c][l] - m) * rs * gv + bv;
        }
    }
}

// ---------------- in_proj GEMM (K-step 16, software-pipelined) -------------------
__global__ __launch_bounds__(256)
void gemm_inproj_kernel(const float* __restrict__ A, const float* __restrict__ Bw,
                        float* __restrict__ xrx, float* __restrict__ resT)
{
    __shared__ ull   As2[16][128];
    __shared__ float Bs[16][128];
    __shared__ float sT[32][129];
    const int tid = threadIdx.x;
    const int tm = tid >> 4, tn = tid & 15;
    const int m0 = blockIdx.x * 128, n0 = blockIdx.y * 128;
    const int K = DIM, N = 2 * DIN;
    ull acc[8][4];
#pragma unroll
    for (int i = 0; i < 8; i++)
#pragma unroll
        for (int j = 0; j < 4; j++) acc[i][j] = 0ull;
    const int ar = tid >> 1, ak = (tid & 1) * 8;
    const int bk = tid >> 4, bn = (tid & 15) * 8;
    float4 av0 = *(const float4*)(A + (size_t)(m0 + ar) * K + ak);
    float4 av1 = *(const float4*)(A + (size_t)(m0 + ar) * K + ak + 4);
    float4 bv0 = *(const float4*)(Bw + (size_t)bk * N + n0 + bn);
    float4 bv1 = *(const float4*)(Bw + (size_t)bk * N + n0 + bn + 4);
    for (int k0 = 0; k0 < K; k0 += 16) {
        __syncthreads();
        As2[ak + 0][ar] = pack2(av0.x, av0.x);
        As2[ak + 1][ar] = pack2(av0.y, av0.y);
        As2[ak + 2][ar] = pack2(av0.z, av0.z);
        As2[ak + 3][ar] = pack2(av0.w, av0.w);
        As2[ak + 4][ar] = pack2(av1.x, av1.x);
        As2[ak + 5][ar] = pack2(av1.y, av1.y);
        As2[ak + 6][ar] = pack2(av1.z, av1.z);
        As2[ak + 7][ar] = pack2(av1.w, av1.w);
        *(float4*)&Bs[bk][bn]     = bv0;
        *(float4*)&Bs[bk][bn + 4] = bv1;
        __syncthreads();
        if (k0 + 16 < K) {
            av0 = *(const float4*)(A + (size_t)(m0 + ar) * K + k0 + 16 + ak);
            av1 = *(const float4*)(A + (size_t)(m0 + ar) * K + k0 + 16 + ak + 4);
            bv0 = *(const float4*)(Bw + (size_t)(k0 + 16 + bk) * N + n0 + bn);
            bv1 = *(const float4*)(Bw + (size_t)(k0 + 16 + bk) * N + n0 + bn + 4);
        }
#pragma unroll
        for (int k = 0; k < 16; k++) {
            ull a2[8], b2[4];
#pragma unroll
            for (int i = 0; i < 8; i++) a2[i] = As2[k][tm * 8 + i];
#pragma unroll
            for (int j = 0; j < 4; j++) b2[j] = *(const ull*)&Bs[k][tn * 2 + 32 * j];
#pragma unroll
            for (int i = 0; i < 8; i++)
#pragma unroll
                for (int j = 0; j < 4; j++)
                    acc[i][j] = ffma2(a2[i], b2[j], acc[i][j]);
        }
    }
    if (n0 < DIN) {
#pragma unroll
        for (int i = 0; i < 8; i++) {
            int row = m0 + tm * 8 + i;
#pragma unroll
            for (int j = 0; j < 4; j++) {
                float lo, hi; unpack2(acc[i][j], lo, hi);
                *(float2*)(xrx + (size_t)row * DIN + n0 + tn * 2 + 32 * j) = make_float2(lo, hi);
            }
        }
    } else {
        const int b = m0 >> 12, t0 = m0 & 4095, d0 = n0 - DIN;
#pragma unroll
        for (int j = 0; j < 4; j++) {
            __syncthreads();
#pragma unroll
            for (int i = 0; i < 8; i++) {
                int rl = tm * 8 + i;
                float lo, hi; unpack2(acc[i][j], lo, hi);
                sT[2 * tn][rl]     = lo;
                sT[2 * tn + 1][rl] = hi;
            }
            __syncthreads();
            int col = tid >> 3, r0 = (tid & 7) * 16;
            float* dst = resT + ((size_t)(b * DIN + d0 + 32 * j + col)) * LSEQ + t0 + r0;
#pragma unroll
            for (int k = 0; k < 16; k++) dst[k] = sT[col][r0 + k];
        }
    }
}

// ---------------- delta GEMM (K-step 16, software-pipelined) ---------------------
__global__ __launch_bounds__(256)
void gemm_delta_kernel(const float* __restrict__ A, const float* __restrict__ Bw,
                       const float* __restrict__ dtb, float* __restrict__ deltaT)
{
    __shared__ ull   As2[16][128];
    __shared__ float Bs[16][128];
    __shared__ float sT[32][129];
    const int tid = threadIdx.x;
    const int tm = tid >> 4, tn = tid & 15;
    const int m0 = blockIdx.x * 128, n0 = blockIdx.y * 128;
    const int K = DIN, N = DIN;
    ull acc[8][4];
#pragma unroll
    for (int i = 0; i < 8; i++)
#pragma unroll
        for (int j = 0; j < 4; j++) acc[i][j] = 0ull;
    const int ar = tid >> 1, ak = (tid & 1) * 8;
    const int bk = tid >> 4, bn = (tid & 15) * 8;
    float4 av0 = *(const float4*)(A + (size_t)(m0 + ar) * K + ak);
    float4 av1 = *(const float4*)(A + (size_t)(m0 + ar) * K + ak + 4);
    float4 bv0 = *(const float4*)(Bw + (size_t)bk * N + n0 + bn);
    float4 bv1 = *(const float4*)(Bw + (size_t)bk * N + n0 + bn + 4);
    for (int k0 = 0; k0 < K; k0 += 16) {
        __syncthreads();
        As2[ak + 0][ar] = pack2(av0.x, av0.x);
        As2[ak + 1][ar] = pack2(av0.y, av0.y);
        As2[ak + 2][ar] = pack2(av0.z, av0.z);
        As2[ak + 3][ar] = pack2(av0.w, av0.w);
        As2[ak + 4][ar] = pack2(av1.x, av1.x);
        As2[ak + 5][ar] = pack2(av1.y, av1.y);
        As2[ak + 6][ar] = pack2(av1.z, av1.z);
        As2[ak + 7][ar] = pack2(av1.w, av1.w);
        *(float4*)&Bs[bk][bn]     = bv0;
        *(float4*)&Bs[bk][bn + 4] = bv1;
        __syncthreads();
        if (k0 + 16 < K) {
            av0 = *(const float4*)(A + (size_t)(m0 + ar) * K + k0 + 16 + ak);
            av1 = *(const float4*)(A + (size_t)(m0 + ar) * K + k0 + 16 + ak + 4);
            bv0 = *(const float4*)(Bw + (size_t)(k0 + 16 + bk) * N + n0 + bn);
            bv1 = *(const float4*)(Bw + (size_t)(k0 + 16 + bk) * N + n0 + bn + 4);
        }
#pragma unroll
        for (int k = 0; k < 16; k++) {
            ull a2[8], b2[4];
#pragma unroll
            for (int i = 0; i < 8; i++) a2[i] = As2[k][tm * 8 + i];
#pragma unroll
            for (int j = 0; j < 4; j++) b2[j] = *(const ull*)&Bs[k][tn * 2 + 32 * j];
#pragma unroll
            for (int i = 0; i < 8; i++)
#pragma unroll
                for (int j = 0; j < 4; j++)
                    acc[i][j] = ffma2(a2[i], b2[j], acc[i][j]);
        }
    }
    const int b = m0 >> 12, t0 = m0 & 4095;
#pragma unroll
    for (int j = 0; j < 4; j++) {
        __syncthreads();
        float blo = dtb[n0 + 32 * j + 2 * tn];
        float bhi = dtb[n0 + 32 * j + 2 * tn + 1];
#pragma unroll
        for (int i = 0; i < 8; i++) {
            int rl = tm * 8 + i;
            float lo, hi; unpack2(acc[i][j], lo, hi);
            sT[2 * tn][rl]     = softplus_f(lo + blo);
            sT[2 * tn + 1][rl] = softplus_f(hi + bhi);
        }
        __syncthreads();
        int col = tid >> 3, r0 = (tid & 7) * 16;
        float* dst = deltaT + ((size_t)(b * DIN + n0 + 32 * j + col)) * LSEQ + t0 + r0;
#pragma unroll
        for (int k = 0; k < 16; k++) dst[k] = sT[col][r0 + k];
    }
}

// ---------------- BC GEMM: M-tile 64, software-pipelined -------------------------
__global__ __launch_bounds__(256)
void gemm_bc_kernel(const float* __restrict__ A, const float* __restrict__ xw,
                    float* __restrict__ bc)
{
    __shared__ ull   As2[16][64];
    __shared__ float Bs[16][32];
    const int tid = threadIdx.x;
    const int tm = tid >> 4, tn = tid & 15;
    const int m0 = blockIdx.x * 64;
    ull acc[4];
#pragma unroll
    for (int i = 0; i < 4; i++) acc[i] = 0ull;
    const int ar = tid >> 2, aq = (tid & 3) * 4;
    float4 a1 = *(const float4*)(A + (size_t)(m0 + ar) * DIN + aq);
    float bvv[2];
#pragma unroll
    for (int q = 0; q < 2; q++) {
        int idx = tid + q * 256;
        bvv[q] = xw[(size_t)(idx >> 5) * 40 + 8 + (idx & 31)];
    }
    for (int k0 = 0; k0 < DIN; k0 += 16) {
        __syncthreads();
        As2[aq + 0][ar] = pack2(a1.x, a1.x);
        As2[aq + 1][ar] = pack2(a1.y, a1.y);
        As2[aq + 2][ar] = pack2(a1.z, a1.z);
        As2[aq + 3][ar] = pack2(a1.w, a1.w);
#pragma unroll
        for (int q = 0; q < 2; q++) {
            int idx = tid + q * 256;
            Bs[idx >> 5][idx & 31] = bvv[q];
        }
        __syncthreads();
        if (k0 + 16 < DIN) {
            a1 = *(const float4*)(A + (size_t)(m0 + ar) * DIN + k0 + 16 + aq);
#pragma unroll
            for (int q = 0; q < 2; q++) {
                int idx = tid + q * 256;
                bvv[q] = xw[(size_t)(k0 + 16 + (idx >> 5)) * 40 + 8 + (idx & 31)];
            }
        }
#pragma unroll
        for (int k = 0; k < 16; k++) {
            ull b2 = *(const ull*)&Bs[k][2 * tn];
#pragma unroll
            for (int i = 0; i < 4; i++)
                acc[i] = ffma2(As2[k][tm * 4 + i], b2, acc[i]);
        }
    }
#pragma unroll
    for (int i = 0; i < 4; i++) {
        int row = m0 + tm * 4 + i;
        float lo, hi; unpack2(acc[i], lo, hi);
        *(float2*)(bc + (size_t)row * 32 + 2 * tn) = make_float2(lo, hi);
    }
}

// ---------------- out_proj GEMM: M-tile 64, software-pipelined -------------------
__global__ __launch_bounds__(256)
void gemm_out_kernel(const float* __restrict__ gatedT, const float* __restrict__ Bw,
                     float* __restrict__ out)
{
    __shared__ ull   As2[8][64];
    __shared__ float Bs[8][128];
    __shared__ float sT[32][65];
    const int tid = threadIdx.x;
    const int tm = tid >> 4, tn = tid & 15;
    const int m0 = blockIdx.x * 64;
    const int K = DIN, N = DIM;
    const int b = m0 >> 12, t0 = m0 & 4095;
    ull acc[4][4];
#pragma unroll
    for (int i = 0; i < 4; i++)
#pragma unroll
        for (int j = 0; j < 4; j++) acc[i][j] = 0ull;
    const int kk = tid >> 5, tl = tid & 31;
    const int bk = tid >> 5, bn = (tid & 31) * 4;
    float gv[2];
#pragma unroll
    for (int it = 0; it < 2; it++)
        gv[it] = gatedT[((size_t)(b * DIN + kk)) * LSEQ + t0 + tl + 32 * it];
    float4 bv = *(const float4*)(Bw + (size_t)bk * N + bn);
    for (int k0 = 0; k0 < K; k0 += 8) {
        __syncthreads();
#pragma unroll
        for (int it = 0; it < 2; it++)
            As2[kk][tl + 32 * it] = pack2(gv[it], gv[it]);
        *(float4*)&Bs[bk][bn] = bv;
        __syncthreads();
        if (k0 + 8 < K) {
            int d = k0 + 8 + kk;
#pragma unroll
            for (int it = 0; it < 2; it++)
                gv[it] = gatedT[((size_t)(b * DIN + d)) * LSEQ + t0 + tl + 32 * it];
            bv = *(const float4*)(Bw + (size_t)(k0 + 8 + bk) * N + bn);
        }
#pragma unroll
        for (int k = 0; k < 8; k++) {
            ull a2[4], b2[4];
#pragma unroll
            for (int i = 0; i < 4; i++) a2[i] = As2[k][tm * 4 + i];
#pragma unroll
            for (int j = 0; j < 4; j++) b2[j] = *(const ull*)&Bs[k][tn * 2 + 32 * j];
#pragma unroll
            for (int i = 0; i < 4; i++)
#pragma unroll
                for (int j = 0; j < 4; j++)
                    acc[i][j] = ffma2(a2[i], b2[j], acc[i][j]);
        }
    }
#pragma unroll
    for (int j = 0; j < 4; j++) {
        __syncthreads();
#pragma unroll
        for (int i = 0; i < 4; i++) {
            int rl = tm * 4 + i;
            float lo, hi; unpack2(acc[i][j], lo, hi);
            sT[2 * tn][rl]     = lo;
            sT[2 * tn + 1][rl] = hi;
        }
        __syncthreads();
        int col = tid >> 3, r0 = (tid & 7) * 8;
        float* dst = out + ((size_t)(b * DIM + 32 * j + col)) * LSEQ + t0 + r0;
#pragma unroll
        for (int k = 0; k < 8; k++) dst[k] = sT[col][r0 + k];
    }
}

// ---------------- causal depthwise conv1d (k=4) + silu, smem-staged --------------
__global__ __launch_bounds__(256)
void conv1d_silu_T_kernel(const float* __restrict__ xrx, const float4* __restrict__ wp,
                          const float* __restrict__ bias,
                          float* __restrict__ xs, float* __restrict__ xsT)
{
    __shared__ float sin_[35][32];
    __shared__ float st[32][33];
    const int tx = threadIdx.x & 31, ty = threadIdx.x >> 5;
    const int t0 = blockIdx.x * 32, d0 = blockIdx.y * 32, b = blockIdx.z;
    const int d = d0 + tx;

    for (int r = ty; r < 35; r += 8) {
        int t = t0 - 3 + r;
        sin_[r][tx] = (t >= 0) ? xrx[((size_t)b * LSEQ + t) * DIN + d] : 0.f;
    }
    __syncthreads();

    float4 w = wp[d];
    float bv = bias[d];
#pragma unroll
    for (int k = 0; k < 4; k++) {
        int tt = ty + 8 * k;
        float acc = bv;
        acc = fmaf(w.x, sin_[tt][tx],     acc);
        acc = fmaf(w.y, sin_[tt + 1][tx], acc);
        acc = fmaf(w.z, sin_[tt + 2][tx], acc);
        acc = fmaf(w.w, sin_[tt + 3][tx], acc);
        float s = acc / (1.f + __expf(-acc));
        xs[((size_t)b * LSEQ + t0 + tt) * DIN + d] = s;
        st[tx][tt] = s;
    }
    __syncthreads();
#pragma unroll
    for (int k = 0; k < 4; k++) {
        int dd = d0 + ty + 8 * k;
        xsT[((size_t)(b * DIN + dd)) * LSEQ + t0 + tx] = st[ty + 8 * k][tx];
    }
}

// ---------------- scan pass 1 (float4 broadcast loads, NCH=32) -------------------
__global__ __launch_bounds__(256)
void scan_p1_kernel(const float* __restrict__ deltaT, const float* __restrict__ xsT,
                    const float* __restrict__ bc, const float* __restrict__ negA,
                    float* __restrict__ chA, float* __restrict__ chH)
{
    int gw = (blockIdx.x * blockDim.x + threadIdx.x) >> 5;
    int lane = threadIdx.x & 31;
    int half = lane >> 4, n = lane & 15;
    int chunk = gw >> 9;
    int wp = gw & 511;
    int pair = wp * 2 + half;
    int b = pair >> 8, d = pair & 255;
    int t0 = chunk * CHLEN;

    float A = negA[d * DSTATE + n];
    const float* dl = deltaT + (size_t)(b * DIN + d) * LSEQ + t0;
    const float* ul = xsT    + (size_t)(b * DIN + d) * LSEQ + t0;
    const float* xb = bc + ((size_t)b * LSEQ + t0) * 32;

    float h = 0.f, pA = 1.f;
    for (int tb = 0; tb < CHLEN; tb += 4) {
        float4 d4 = *(const float4*)(dl + tb);
        float4 u4 = *(const float4*)(ul + tb);
#pragma unroll
        for (int q = 0; q < 4; q++) {
            float dt = (q == 0) ? d4.x : (q == 1) ? d4.y : (q == 2) ? d4.z : d4.w;
            float ut = (q == 0) ? u4.x : (q == 1) ? u4.y : (q == 2) ? u4.z : u4.w;
            float Bn = xb[(tb + q) * 32 + n];
            float a = __expf(dt * A);
            pA *= a;
            h = fmaf(a, h, dt * ut * Bn);
        }
    }
    int idx = (chunk * NPAIR + pair) * DSTATE + n;
    chA[idx] = pA;
    chH[idx] = h;
}

// ---------------- scan pass 2 ----------------
__global__ __launch_bounds__(256)
void scan_p2_kernel(const float* __restrict__ chA, const float* __restrict__ chH,
                    float* __restrict__ hst)
{
    int i = blockIdx.x * 256 + threadIdx.x;
    float h = 0.f;
    hst[i] = 0.f;
#pragma unroll
    for (int c = 0; c < NCH - 1; c++) {
        h = fmaf(chA[c * NPAIR * DSTATE + i], h, chH[c * NPAIR * DSTATE + i]);
        hst[(c + 1) * NPAIR * DSTATE + i] = h;
    }
}

// ---------------- scan pass 3 (float4 broadcast loads, NCH=32) -------------------
__global__ __launch_bounds__(256)
void scan_p3_kernel(const float* __restrict__ deltaT, const float* __restrict__ xsT,
                    const float* __restrict__ bc, const float* __restrict__ negA,
                    const float* __restrict__ Dp, const float* __restrict__ hst,
                    const float* __restrict__ resT, float* __restrict__ gatedT)
{
    __shared__ float sy[8][2][32];
    int gw = (blockIdx.x * blockDim.x + threadIdx.x) >> 5;
    int lane = threadIdx.x & 31;
    int wslot = threadIdx.x >> 5;
    int half = lane >> 4, n = lane & 15;
    int chunk = gw >> 9;
    int wp = gw & 511;
    int pair = wp * 2 + half;
    int b = pair >> 8, d = pair & 255;
    int t0 = chunk * CHLEN;

    float A = negA[d * DSTATE + n];
    const float* dl = deltaT + (size_t)(b * DIN + d) * LSEQ + t0;
    const float* ul = xsT    + (size_t)(b * DIN + d) * LSEQ + t0;
    const float* xb = bc + ((size_t)b * LSEQ + t0) * 32;
    float h = hst[(chunk * NPAIR + pair) * DSTATE + n];

    int dp0 = (wp * 2) & 255;
    int bb  = (wp * 2) >> 8;
    float Dv0 = Dp[dp0], Dv1 = Dp[dp0 + 1];
    const float* u0p = xsT + (size_t)(bb * DIN + dp0)     * LSEQ + t0;
    const float* u1p = xsT + (size_t)(bb * DIN + dp0 + 1) * LSEQ + t0;
    const float* r0p = resT + (size_t)(bb * DIN + dp0)     * LSEQ + t0;
    const float* r1p = resT + (size_t)(bb * DIN + dp0 + 1) * LSEQ + t0;
    float* y0p = gatedT + (size_t)(bb * DIN + dp0)     * LSEQ + t0;
    float* y1p = gatedT + (size_t)(bb * DIN + dp0 + 1) * LSEQ + t0;

    for (int tb = 0; tb < CHLEN; tb += 32) {
        for (int tq = 0; tq < 32; tq += 4) {
            float4 d4 = *(const float4*)(dl + tb + tq);
            float4 u4 = *(const float4*)(ul + tb + tq);
#pragma unroll
            for (int q = 0; q < 4; q++) {
                int t = tb + tq + q;
                float dt = (q == 0) ? d4.x : (q == 1) ? d4.y : (q == 2) ? d4.z : d4.w;
                float ut = (q == 0) ? u4.x : (q == 1) ? u4.y : (q == 2) ? u4.z : u4.w;
                float Bn  = xb[t * 32 + n];
                float Cn  = xb[t * 32 + 16 + n];
                float a = __expf(dt * A);
                h = fmaf(a, h, dt * ut * Bn);
                float yv = h * Cn;
                yv += __shfl_xor_sync(0xffffffffu, yv, 8);
                yv += __shfl_xor_sync(0xffffffffu, yv, 4);
                yv += __shfl_xor_sync(0xffffffffu, yv, 2);
                yv += __shfl_xor_sync(0xffffffffu, yv, 1);
                if (n == 0) sy[wslot][half][tq + q] = yv;
            }
        }
        __syncwarp();
        float r0 = r0p[tb + lane];
        float r1 = r1p[tb + lane];
        float s0 = r0 / (1.f + __expf(-r0));
        float s1 = r1 / (1.f + __expf(-r1));
        y0p[tb + lane] = fmaf(u0p[tb + lane], Dv0, sy[wslot][0][lane]) * s0;
        y1p[tb + lane] = fmaf(u1p[tb + lane], Dv1, sy[wslot][1][lane]) * s1;
        __syncwarp();
    }
}

// ---------------- launch ----------------
extern "C" void kernel_launch(void* const* d_in, const int* in_sizes, int n_in,
                              void* d_out, int out_size)
{
    const float* x         = (const float*)d_in[0];
    const float* conv1_w   = (const float*)d_in[1];
    const float* conv1_b   = (const float*)d_in[2];
    const float* conv2_w   = (const float*)d_in[3];
    const float* conv2_b   = (const float*)d_in[4];
    const float* ln_g      = (const float*)d_in[5];
    const float* ln_b      = (const float*)d_in[6];
    const float* in_proj_w = (const float*)d_in[7];
    const float* conv1d_w  = (const float*)d_in[8];
    const float* conv1d_b  = (const float*)d_in[9];
    const float* x_proj_w  = (const float*)d_in[10];
    const float* dt_proj_w = (const float*)d_in[11];
    const float* dt_proj_b = (const float*)d_in[12];
    const float* A_log     = (const float*)d_in[13];
    const float* Dp        = (const float*)d_in[14];
    const float* out_proj_w= (const float*)d_in[15];
    float* out = (float*)d_out;

    Scratch* s = nullptr;
    cudaGetSymbolAddress((void**)&s, g_scratch);

    const size_t p1stride = (size_t)BATCH * DIN * HW;
    const size_t p2stride = (size_t)BATCH * DIM * HW;

    // 0) merged precompute (1 launch)
    const int wdup_blocks = (W1ELEMS + W2ELEMS + 255) / 256;
    precompute_kernel<<<17 + DIN + wdup_blocks, 256>>>(
        A_log, s->negA, conv1d_w, s->wpack, x_proj_w, dt_proj_w, s->weff,
        conv1_w, conv2_w, s->wd1, s->wd2);
    // 1) conv1 split-K x2
    conv3x3_v10_kernel<DIM, DIN, 2><<<dim3(2, 1, BATCH * (DIN / 8) * 2), 256>>>(
        x, s->wd1, s->h1);
    // 2) inorm (sums 2 partials + bias) + leaky
    inorm_lrelu_kernel<2><<<BATCH * DIN, 256>>>(s->h1, p1stride, conv1_b, DIN, s->h1, nullptr);
    // 3) conv2 split-K x4
    conv3x3_v10_kernel<DIN, DIM, 4><<<dim3(2, 1, BATCH * (DIM / 8) * 4), 256>>>(
        s->h1, s->wd2, s->h2);
    // 4) inorm (sums 4 partials + bias) + leaky + residual
    inorm_lrelu_kernel<4><<<BATCH * DIM, 256>>>(s->h2, p2stride, conv2_b, DIM, s->h2, x);
    // 5) layernorm (coalesced) + transpose to (b*l, c)
    layernorm_v2_kernel<<<dim3(HW / 32, BATCH), 256>>>(s->h2, ln_g, ln_b, s->t);
    // 6) in_proj GEMM (K-step 16)
    gemm_inproj_kernel<<<dim3(BATCH * LSEQ / 128, 4), 256>>>(
        s->t, in_proj_w, s->xrx, s->resT);
    // 7) depthwise conv1d + silu (smem-staged)
    conv1d_silu_T_kernel<<<dim3(LSEQ / 32, DIN / 32, BATCH), 256>>>(
        s->xrx, s->wpack, conv1d_b, s->xs, s->xsT);
    // 8) delta GEMM (K-step 16)
    gemm_delta_kernel<<<dim3(BATCH * LSEQ / 128, 2), 256>>>(
        s->xs, s->weff, dt_proj_b, s->deltaT);
    // 9) B/C GEMM (M-tile 64)
    gemm_bc_kernel<<<BATCH * LSEQ / 64, 256>>>(s->xs, x_proj_w, s->bc);
    // 10) chunked selective scan (NCH=32)
    scan_p1_kernel<<<(NCH - 1) * 64, 256>>>(
        s->deltaT, s->xsT, s->bc, s->negA, s->chA, s->chH);
    scan_p2_kernel<<<NPAIR * DSTATE / 256, 256>>>(s->chA, s->chH, s->hst);
    scan_p3_kernel<<<NCH * 64, 256>>>(
        s->deltaT, s->xsT, s->bc, s->negA, Dp, s->hst, s->resT, s->gatedT);
    // 11) out_proj GEMM (M-tile 64) + NCHW store
    gemm_out_kernel<<<BATCH * LSEQ / 64, 256>>>(s->gatedT, out_proj_w, out);
}